// round 12
// baseline (speedup 1.0000x reference)
#include <cuda_runtime.h>
#include <cuda_bf16.h>
#include <cuda_fp16.h>
#include <math.h>
#include <cstdint>

// ---------------------------------------------------------------------------
// Problem constants
// ---------------------------------------------------------------------------
#define BATCH 8
#define CIN   512
#define CI    128
#define CK    16
#define NC    19
#define NPIX  4096
#define FEAT_ELEMS (BATCH * CI * NPIX)
#define XP_H 66
#define KSPLIT 16

// ---------------------------------------------------------------------------
// Scratch (device globals)
// ---------------------------------------------------------------------------
__device__ __half g_featp1h[FEAT_ELEMS];     // conv1-p hi; later conv2-p out
__device__ __half g_featp1lo[FEAT_ELEMS];    // conv1-p lo residual
__device__ __half g_featc1h[FEAT_ELEMS];     // conv1-c hi; later conv2-c out
__device__ __half g_featc1lo[FEAT_ELEMS];    // conv1-c lo residual
__device__ __half g_qh[BATCH * NPIX * CK];
__device__ __half g_kh[BATCH * NPIX * CK];
__device__ __half g_vd[FEAT_ELEMS];
__device__ float  g_epart[KSPLIT * BATCH * CI * CI];
__device__ __half g_attn16[BATCH * CI * CI];
__device__ __half g_xpad[BATCH * XP_H * XP_H * CIN];
__device__ __half g_xp2a[BATCH * XP_H * XP_H * CI];
__device__ __half g_xp2b[BATCH * XP_H * XP_H * CI];
__device__ __half g_wf16_1[2 * 144 * 4096];
__device__ __half g_wf16_2[2 * 36 * 4096];
__device__ __half g_wqkv[10 * 8 * 32 * 8];
__device__ __half g_wfinal[4 * 16 * 32 * 8];   // [64 rows x 256 k] frag-packed

__device__ __forceinline__ float sigmoidf_(float x) {
    return 1.0f / (1.0f + __expf(-x));
}
__device__ __forceinline__ uint32_t smem_u32(const void* p) {
    uint32_t a;
    asm("{ .reg .u64 t; cvta.to.shared.u64 t, %1; cvt.u32.u64 %0, t; }" : "=r"(a) : "l"(p));
    return a;
}
__device__ __forceinline__ void mma_f16(float c[4], const uint32_t a[4], const uint32_t b0, const uint32_t b1) {
    asm volatile(
        "mma.sync.aligned.m16n8k16.row.col.f32.f16.f16.f32 "
        "{%0,%1,%2,%3}, {%4,%5,%6,%7}, {%8,%9}, {%0,%1,%2,%3};"
        : "+f"(c[0]), "+f"(c[1]), "+f"(c[2]), "+f"(c[3])
        : "r"(a[0]), "r"(a[1]), "r"(a[2]), "r"(a[3]), "r"(b0), "r"(b1));
}
__device__ __forceinline__ void ldsm4(uint32_t r[4], uint32_t addr) {
    asm volatile("ldmatrix.sync.aligned.m8n8.x4.shared.b16 {%0,%1,%2,%3}, [%4];"
                 : "=r"(r[0]), "=r"(r[1]), "=r"(r[2]), "=r"(r[3]) : "r"(addr));
}
__device__ __forceinline__ void ldsm4t(uint32_t r[4], uint32_t addr) {
    asm volatile("ldmatrix.sync.aligned.m8n8.x4.trans.shared.b16 {%0,%1,%2,%3}, [%4];"
                 : "=r"(r[0]), "=r"(r[1]), "=r"(r[2]), "=r"(r[3]) : "r"(addr));
}
#define CP_ASYNC16(dst, src) \
    asm volatile("cp.async.ca.shared.global [%0], [%1], 16;" :: "r"(dst), "l"(src))
#define CP_COMMIT() asm volatile("cp.async.commit_group;")
#define CP_WAIT(N)  asm volatile("cp.async.wait_group %0;" :: "n"(N))

__device__ __forceinline__ uint32_t ph2(float x, float y) {
    __half2 h = __floats2half2_rn(x, y);
    return *(uint32_t*)&h;
}

// ---------------------------------------------------------------------------
// Pack x: f32 NCHW -> fp16 NHWC padded
// ---------------------------------------------------------------------------
__global__ void pack_x_kernel(const float* __restrict__ x, __half* __restrict__ xp) {
    const int h = blockIdx.x, b = blockIdx.y, tid = threadIdx.x;
    __shared__ float s[32][65];
    for (int ci0 = 0; ci0 < CIN; ci0 += 32) {
        for (int idx = tid; idx < 32 * 64; idx += 256) {
            int ci_l = idx >> 6, w = idx & 63;
            s[ci_l][w] = x[(((size_t)b * CIN + ci0 + ci_l) * 64 + h) * 64 + w];
        }
        __syncthreads();
        for (int idx = tid; idx < 64 * 32; idx += 256) {
            int w = idx >> 5, ci_l = idx & 31;
            xp[(((size_t)b * XP_H + h + 1) * XP_H + w + 1) * CIN + ci0 + ci_l] =
                __float2half(s[ci_l][w]);
        }
        __syncthreads();
    }
}

// One launch zeroes the borders of all three padded buffers (z selects).
__global__ void zero_borders_all(__half* __restrict__ xpad,
                                 __half* __restrict__ xp2a,
                                 __half* __restrict__ xp2b) {
    const int hp = blockIdx.x, b = blockIdx.y, z = blockIdx.z, tid = threadIdx.x;
    __half* base = (z == 0) ? xpad : (z == 1 ? xp2a : xp2b);
    const int C = (z == 0) ? CIN : CI;
    __half* row = base + ((size_t)b * XP_H + hp) * XP_H * C;
    const __half zz = __float2half(0.0f);
    if (hp == 0 || hp == XP_H - 1) {
        for (int idx = tid; idx < XP_H * C; idx += 256) row[idx] = zz;
    } else {
        for (int idx = tid; idx < C; idx += 256) {
            row[idx] = zz;
            row[(size_t)(XP_H - 1) * C + idx] = zz;
        }
    }
}

// ---------------------------------------------------------------------------
// Pack conv weights into m16n8k16 fp16 A-fragment order.
// ---------------------------------------------------------------------------
__global__ void pack_w16(const float* __restrict__ W0, const float* __restrict__ W1,
                         __half* __restrict__ wf, int CIN_T) {
    const int cpc = CIN_T / 32;
    const int chunk = blockIdx.x;
    const int kwh = chunk / cpc, cb = chunk % cpc;
    const float* W = blockIdx.y ? W1 : W0;
    __half* dst = wf + ((size_t)blockIdx.y * gridDim.x + chunk) * 4096;
    for (int t = 0; t < 16; t++) {
        int idx = threadIdx.x + t * 256;
        int j = idx & 7, lane = (idx >> 3) & 31, ks = (idx >> 8) & 1, mt = idx >> 9;
        int reg = j >> 1, h = j & 1;
        int co = mt * 16 + (lane >> 2) + (reg & 1) * 8;
        int ci = cb * 32 + ks * 16 + (lane & 3) * 2 + (reg >> 1) * 8 + h;
        dst[idx] = __float2half(W[((size_t)co * CIN_T + ci) * 9 + kwh]);
    }
}

// One launch packs wqkv (CTA 0) and wfinal (CTA 1).
__global__ void pack_small(const float* __restrict__ Wd, const float* __restrict__ Wb,
                           const float* __restrict__ Wc, __half* __restrict__ dqkv,
                           const float* __restrict__ Wout, const float* __restrict__ Wp3,
                           const float* __restrict__ Wc3, __half* __restrict__ dfin) {
    if (blockIdx.x == 0) {
        for (int idx = threadIdx.x; idx < 20480; idx += 256) {
            int j = idx & 7, lane = (idx >> 3) & 31, ks = (idx >> 8) & 7, mt = idx >> 11;
            int reg = j >> 1, h = j & 1;
            int row = mt * 16 + (lane >> 2) + (reg & 1) * 8;
            int col = ks * 16 + (lane & 3) * 2 + (reg >> 1) * 8 + h;
            float w;
            if (row < 128)      w = Wd[row * 128 + col];
            else if (row < 144) w = Wb[(row - 128) * 128 + col];
            else                w = Wc[(row - 144) * 128 + col];
            dqkv[idx] = __float2half(w);
        }
    } else {
        for (int idx = threadIdx.x; idx < 16384; idx += 256) {
            int j = idx & 7, lane = (idx >> 3) & 31, ks = (idx >> 8) & 15, mt = idx >> 12;
            int reg = j >> 1, h = j & 1;
            int row = mt * 16 + (lane >> 2) + (reg & 1) * 8;
            int col = ks * 16 + (lane & 3) * 2 + (reg >> 1) * 8 + h;
            float w = 0.0f;
            if (col < 128) {
                if (row < 19)      w = Wout[row * 128 + col];
                else if (row < 38) w = Wp3[(row - 19) * 128 + col];
            } else {
                int c = col - 128;
                if (row < 19)      w = Wout[row * 128 + c];
                else if (row >= 38 && row < 57) w = Wc3[(row - 38) * 128 + c];
            }
            dfin[idx] = __float2half(w);
        }
    }
}

// ---------------------------------------------------------------------------
// conv3x3 implicit GEMM, fp16 m16n8k16, halo-reuse B staging, fused BN+ReLU.
// smem: B 2x21120 @0; A 2x24576 @42240.  Total 91392.  Pixel stride 80B.
// ---------------------------------------------------------------------------
#define CONV_SMEM 91392
#define BPX 80

template<int CIN_T>
__global__ void __launch_bounds__(256, 2) conv_mma_kernel(
        const __half* __restrict__ xpA, const __half* __restrict__ xpB,
        const __half* __restrict__ wfrag,
        const float* __restrict__ bn0, const float* __restrict__ bn1,
        __half* __restrict__ o16_0, __half* __restrict__ o16_1,
        __half* __restrict__ olo_0, __half* __restrict__ olo_1) {
    constexpr int CPC = CIN_T / 32;
    constexpr int NS = CPC * 3;
    extern __shared__ __align__(16) char smc[];
    const uint32_t smb = smem_u32(smc);
    const uint32_t Boff = smb;
    const uint32_t Aoff = smb + 2 * 21120;

    const int tid = threadIdx.x, lane = tid & 31, wid = tid >> 5;
    const int warp_m = wid >> 2, warp_n = wid & 3;
    const int b = blockIdx.y, z = blockIdx.z;
    const int pxbase = blockIdx.x * 128;
    const int h0 = pxbase >> 6;
    const __half* xp = z ? xpB : xpA;
    const __half* Wf = wfrag + (size_t)z * (9 * CPC) * 4096;
    const float* bn = z ? bn1 : bn0;
    __half* o16 = z ? o16_1 : o16_0;
    __half* olo = z ? olo_1 : olo_0;
    const int g = lane >> 3;

    float acc[4][4][4];
#pragma unroll
    for (int mt = 0; mt < 4; mt++)
#pragma unroll
        for (int nt = 0; nt < 4; nt++)
#pragma unroll
            for (int r = 0; r < 4; r++) acc[mt][nt][r] = 0.0f;

    auto stageA = [&](int s, int buf) {
        const int cb = s / 3, kh = s % 3;
        const uint32_t Ad = Aoff + buf * 24576;
#pragma unroll
        for (int kw = 0; kw < 3; kw++) {
            const __half* src = Wf + (size_t)((kh * 3 + kw) * CPC + cb) * 4096;
#pragma unroll
            for (int t = 0; t < 2; t++) {
                int idx = tid + t * 256;
                CP_ASYNC16(Ad + kw * 8192 + idx * 16, src + idx * 8);
            }
        }
    };
    auto stageB = [&](int cb, int buf) {
        const uint32_t Bd = Boff + buf * 21120;
        const __half* base = xp + ((size_t)(b * XP_H + h0) * XP_H) * CIN_T + cb * 32;
        for (int idx = tid; idx < 1056; idx += 256) {
            int r = idx / 264, rem = idx % 264;
            int c = rem >> 2, q = rem & 3;
            CP_ASYNC16(Bd + (r * 66 + c) * BPX + q * 16,
                       base + ((size_t)r * XP_H + c) * CIN_T + q * 8);
        }
    };

    stageB(0, 0);
    stageA(0, 0);
    CP_COMMIT();

    for (int s = 0; s < NS; s++) {
        const int cb = s / 3, kh = s % 3;
        if (s + 1 < NS) {
            stageA(s + 1, (s + 1) & 1);
            if ((s + 1) % 3 == 0) stageB((s + 1) / 3, ((s + 1) / 3) & 1);
            CP_COMMIT();
            CP_WAIT(1);
        } else {
            CP_WAIT(0);
        }
        __syncthreads();

        const uint32_t Bh = Boff + (cb & 1) * 21120;
        const char* Ap = smc + 2 * 21120 + (s & 1) * 24576;
#pragma unroll
        for (int ks = 0; ks < 2; ks++) {
#pragma unroll
            for (int kw = 0; kw < 3; kw++) {
                uint32_t afr[4][4];
#pragma unroll
                for (int mt = 0; mt < 4; mt++) {
                    uint4 v = *(const uint4*)(Ap + kw * 8192 +
                        ((((warp_m * 4 + mt) * 2 + ks) * 32 + lane) << 4));
                    afr[mt][0] = v.x; afr[mt][1] = v.y; afr[mt][2] = v.z; afr[mt][3] = v.w;
                }
                uint32_t bfr[2][4];
#pragma unroll
                for (int t16 = 0; t16 < 2; t16++) {
                    const int n_row = warp_n * 32 + t16 * 16 + (g >> 1) * 8 + (lane & 7);
                    const int r = n_row >> 6, w = n_row & 63;
                    ldsm4(bfr[t16], Bh + ((r + kh) * 66 + w + kw) * BPX
                                      + ks * 32 + (g & 1) * 16);
                }
#pragma unroll
                for (int mt = 0; mt < 4; mt++)
#pragma unroll
                    for (int t16 = 0; t16 < 2; t16++) {
                        mma_f16(acc[mt][2 * t16],     afr[mt], bfr[t16][0], bfr[t16][1]);
                        mma_f16(acc[mt][2 * t16 + 1], afr[mt], bfr[t16][2], bfr[t16][3]);
                    }
            }
        }
        __syncthreads();
    }

#pragma unroll
    for (int mt = 0; mt < 4; mt++) {
        const int co = warp_m * 64 + mt * 16 + (lane >> 2);
        const float sc0 = bn[co],     sh0 = bn[128 + co];
        const float sc8 = bn[co + 8], sh8 = bn[136 + co];
#pragma unroll
        for (int nt = 0; nt < 4; nt++) {
            const int px = pxbase + warp_n * 32 + nt * 8 + 2 * (lane & 3);
            float v0x = fmaxf(acc[mt][nt][0] * sc0 + sh0, 0.0f);
            float v0y = fmaxf(acc[mt][nt][1] * sc0 + sh0, 0.0f);
            float v1x = fmaxf(acc[mt][nt][2] * sc8 + sh8, 0.0f);
            float v1y = fmaxf(acc[mt][nt][3] * sc8 + sh8, 0.0f);
            *(uint32_t*)(o16 + ((size_t)b * 128 + co) * NPIX + px) = ph2(v0x, v0y);
            *(uint32_t*)(o16 + ((size_t)b * 128 + co + 8) * NPIX + px) = ph2(v1x, v1y);
            if (olo) {
                float r0x = v0x - __half2float(__float2half(v0x));
                float r0y = v0y - __half2float(__float2half(v0y));
                float r1x = v1x - __half2float(__float2half(v1x));
                float r1y = v1y - __half2float(__float2half(v1y));
                *(uint32_t*)(olo + ((size_t)b * 128 + co) * NPIX + px) = ph2(r0x, r0y);
                *(uint32_t*)(olo + ((size_t)b * 128 + co + 8) * NPIX + px) = ph2(r1x, r1y);
            }
        }
    }
}

// ---------------------------------------------------------------------------
// QKV GEMM: [Wd;Wb;Wc](160x128) @ y16(128x4096) + bias.
// ---------------------------------------------------------------------------
#define QKV_SMEM 59392

__global__ void __launch_bounds__(320, 1) qkv_kernel(
        const __half* __restrict__ wq, const __half* __restrict__ y16,
        const float* __restrict__ bd, const float* __restrict__ bb,
        const float* __restrict__ bc,
        __half* __restrict__ vh, __half* __restrict__ qh, __half* __restrict__ kh) {
    extern __shared__ __align__(16) char smc[];
    const uint32_t smb = smem_u32(smc);
    const int tid = threadIdx.x, lane = tid & 31, wid = tid >> 5;
    const int b = blockIdx.y;
    const int n0 = blockIdx.x * 64;
    const int g = lane >> 3;

#pragma unroll
    for (int t = 0; t < 8; t++) {
        int i = tid + t * 320;
        CP_ASYNC16(smb + i * 16, wq + i * 8);
    }
    for (int idx = tid; idx < 1024; idx += 320) {
        int ch = idx >> 3, seg = idx & 7;
        CP_ASYNC16(smb + 40960 + ch * 144 + seg * 16,
                   y16 + ((size_t)b * 128 + ch) * NPIX + n0 + seg * 8);
    }
    CP_COMMIT();
    CP_WAIT(0);
    __syncthreads();

    const int mt = wid;
    float acc[8][4];
#pragma unroll
    for (int nt = 0; nt < 8; nt++)
#pragma unroll
        for (int r = 0; r < 4; r++) acc[nt][r] = 0.0f;

    const char* Aptr = smc;
    const uint32_t Bsm = smb + 40960;
#pragma unroll
    for (int ks = 0; ks < 8; ks++) {
        uint4 v = *(const uint4*)(Aptr + (((mt * 8 + ks) * 32 + lane) << 4));
        uint32_t afr[4] = {v.x, v.y, v.z, v.w};
#pragma unroll
        for (int t16 = 0; t16 < 4; t16++) {
            uint32_t bfr[4];
            ldsm4t(bfr, Bsm + (ks * 16 + (g & 1) * 8 + (lane & 7)) * 144
                       + (t16 * 16 + (g >> 1) * 8) * 2);
            mma_f16(acc[2 * t16],     afr, bfr[0], bfr[1]);
            mma_f16(acc[2 * t16 + 1], afr, bfr[2], bfr[3]);
        }
    }

    const int r0 = mt * 16 + (lane >> 2);
    if (mt < 8) {
        const float b0 = bd[r0], b8 = bd[r0 + 8];
        __half* v0 = vh + ((size_t)b * 128 + r0) * NPIX;
        __half* v8 = vh + ((size_t)b * 128 + r0 + 8) * NPIX;
#pragma unroll
        for (int nt = 0; nt < 8; nt++) {
            const int n = n0 + nt * 8 + 2 * (lane & 3);
            *(uint32_t*)(v0 + n) = ph2(acc[nt][0] + b0, acc[nt][1] + b0);
            *(uint32_t*)(v8 + n) = ph2(acc[nt][2] + b8, acc[nt][3] + b8);
        }
    } else {
        const bool isq = (mt == 8);
        const float* bias = isq ? bb : bc;
        __half* dst = isq ? qh : kh;
        const int d = lane >> 2;
        const float b0 = bias[d], b8 = bias[d + 8];
#pragma unroll
        for (int nt = 0; nt < 8; nt++) {
            const int n = n0 + nt * 8 + 2 * (lane & 3);
            __half* p0 = dst + ((size_t)b * NPIX + n) * 16;
            p0[d]      = __float2half(acc[nt][0] + b0);
            p0[16 + d] = __float2half(acc[nt][1] + b0);
            p0[d + 8]      = __float2half(acc[nt][2] + b8);
            p0[16 + d + 8] = __float2half(acc[nt][3] + b8);
        }
    }
}

// ---------------------------------------------------------------------------
// PAM flash attention: q-tile 64, 128-thread CTA, occ 3, 3-stage K/V pipeline.
// SMEM: Q @0 (3072); K 3x3072 @3072; V 3x18432 @12288.  Total 67584.
// ---------------------------------------------------------------------------
#define ATT_SMEM 67584

__global__ void __launch_bounds__(128, 3) pam_attn_mma(
        const __half* __restrict__ qh, const __half* __restrict__ kh,
        const __half* __restrict__ vd,
        const __half* __restrict__ yhi, const __half* __restrict__ ylo,
        const float* __restrict__ alpha, __half* __restrict__ xp2) {
    extern __shared__ __align__(16) char smc[];
    const uint32_t smb = smem_u32(smc);
    const uint32_t Qb  = smb;
    const uint32_t Kb0 = smb + 3072;
    const uint32_t Vb0 = smb + 12288;

    const int tid = threadIdx.x, lane = tid & 31, wid = tid >> 5;
    const int b = blockIdx.y;
    const int n0 = blockIdx.x * 64;
    const int qbase = wid * 16;

    const int g = lane >> 3, r8 = lane & 7;
    const uint32_t qoff = (uint32_t)(((g & 1) * 8 + r8) * 48 + (g >> 1) * 16);
    const uint32_t koff = (uint32_t)(((g >> 1) * 8 + r8) * 48 + (g & 1) * 16);
    const uint32_t voff = (uint32_t)(((g >> 1) * 8 + r8) * 144 + (g & 1) * 16);

    auto stageKV = [&](int t, int buf) {
        const int k0 = t * 64;
        {
            int row = tid >> 1, h = tid & 1;
            CP_ASYNC16(Kb0 + buf * 3072 + row * 48 + h * 16,
                       kh + ((size_t)b * NPIX + k0 + row) * 16 + h * 8);
        }
#pragma unroll
        for (int t4 = 0; t4 < 8; t4++) {
            int idx = tid + t4 * 128;
            int ch = idx >> 3, c = idx & 7;
            CP_ASYNC16(Vb0 + buf * 18432 + ch * 144 + c * 16,
                       vd + ((size_t)b * 128 + ch) * NPIX + k0 + c * 8);
        }
        CP_COMMIT();
    };

    {
        int row = tid >> 1, h = tid & 1;
        CP_ASYNC16(Qb + row * 48 + h * 16,
                   qh + ((size_t)b * NPIX + n0 + row) * 16 + h * 8);
    }
    stageKV(0, 0);    // group 0 (includes Q)
    stageKV(1, 1);    // group 1

    uint32_t qfr[4];
    float O[16][4];
#pragma unroll
    for (int nc = 0; nc < 16; nc++)
#pragma unroll
        for (int r = 0; r < 4; r++) O[nc][r] = 0.0f;
    float mrun0 = -1e30f, mrun1 = -1e30f, lrun0 = 0.0f, lrun1 = 0.0f;

    for (int t = 0; t < 64; t++) {
        const int buf = t % 3;
        if (t < 63) { CP_WAIT(1); } else { CP_WAIT(0); }
        __syncthreads();
        if (t + 2 < 64) stageKV(t + 2, (t + 2) % 3);
        if (t == 0) ldsm4(qfr, Qb + qbase * 48 + qoff);

        const uint32_t Kb = Kb0 + buf * 3072;
        const uint32_t Vb = Vb0 + buf * 18432;

        float S[8][4];
#pragma unroll
        for (int ks = 0; ks < 4; ks++) {
            uint32_t kb[4];
            ldsm4(kb, Kb + ks * 768 + koff);
#pragma unroll
            for (int r = 0; r < 4; r++) { S[2 * ks][r] = 0.0f; S[2 * ks + 1][r] = 0.0f; }
            mma_f16(S[2 * ks],     qfr, kb[0], kb[1]);
            mma_f16(S[2 * ks + 1], qfr, kb[2], kb[3]);
        }

        float tm0 = -1e30f, tm1 = -1e30f;
#pragma unroll
        for (int nt = 0; nt < 8; nt++) {
            tm0 = fmaxf(tm0, fmaxf(S[nt][0], S[nt][1]));
            tm1 = fmaxf(tm1, fmaxf(S[nt][2], S[nt][3]));
        }
        tm0 = fmaxf(tm0, __shfl_xor_sync(0xffffffffu, tm0, 1));
        tm0 = fmaxf(tm0, __shfl_xor_sync(0xffffffffu, tm0, 2));
        tm1 = fmaxf(tm1, __shfl_xor_sync(0xffffffffu, tm1, 1));
        tm1 = fmaxf(tm1, __shfl_xor_sync(0xffffffffu, tm1, 2));
        const float mn0 = fmaxf(mrun0, tm0), mn1 = fmaxf(mrun1, tm1);
        const float f0 = __expf(mrun0 - mn0), f1 = __expf(mrun1 - mn1);
        mrun0 = mn0; mrun1 = mn1;

        float ts0 = 0.0f, ts1 = 0.0f;
        uint32_t afr[4][4];
#pragma unroll
        for (int j = 0; j < 4; j++) {
            float p00 = __expf(S[2 * j][0] - mn0), p01 = __expf(S[2 * j][1] - mn0);
            float p10 = __expf(S[2 * j][2] - mn1), p11 = __expf(S[2 * j][3] - mn1);
            float q00 = __expf(S[2 * j + 1][0] - mn0), q01 = __expf(S[2 * j + 1][1] - mn0);
            float q10 = __expf(S[2 * j + 1][2] - mn1), q11 = __expf(S[2 * j + 1][3] - mn1);
            ts0 += (p00 + p01) + (q00 + q01);
            ts1 += (p10 + p11) + (q10 + q11);
            afr[j][0] = ph2(p00, p01);
            afr[j][1] = ph2(p10, p11);
            afr[j][2] = ph2(q00, q01);
            afr[j][3] = ph2(q10, q11);
        }
        ts0 += __shfl_xor_sync(0xffffffffu, ts0, 1);
        ts0 += __shfl_xor_sync(0xffffffffu, ts0, 2);
        ts1 += __shfl_xor_sync(0xffffffffu, ts1, 1);
        ts1 += __shfl_xor_sync(0xffffffffu, ts1, 2);
        lrun0 = lrun0 * f0 + ts0;
        lrun1 = lrun1 * f1 + ts1;

#pragma unroll
        for (int nc = 0; nc < 16; nc++) {
            O[nc][0] *= f0; O[nc][1] *= f0;
            O[nc][2] *= f1; O[nc][3] *= f1;
        }

#pragma unroll
        for (int j = 0; j < 4; j++) {
            const uint32_t vb_j = Vb + j * 32 + voff;
#pragma unroll
            for (int p = 0; p < 8; p++) {
                uint32_t vb[4];
                ldsm4(vb, vb_j + p * 2304);
                mma_f16(O[2 * p],     afr[j], vb[0], vb[1]);
                mma_f16(O[2 * p + 1], afr[j], vb[2], vb[3]);
            }
        }
    }

    const float linv0 = 1.0f / lrun0, linv1 = 1.0f / lrun1;
    const float a = alpha[0];
    const int px0 = n0 + qbase + (lane >> 2);
    const int px1 = px0 + 8;
    __half* dst0 = xp2 + (((size_t)b * XP_H + (px0 >> 6) + 1) * XP_H + (px0 & 63) + 1) * CI;
    __half* dst1 = xp2 + (((size_t)b * XP_H + (px1 >> 6) + 1) * XP_H + (px1 & 63) + 1) * CI;
#pragma unroll
    for (int nc = 0; nc < 16; nc++) {
        const int ch = nc * 8 + 2 * (lane & 3);
        const __half* hp = yhi + ((size_t)b * 128 + ch) * NPIX;
        const __half* lp = ylo + ((size_t)b * 128 + ch) * NPIX;
        float ya0 = __half2float(hp[px0]) + __half2float(lp[px0]);
        float yb0 = __half2float(hp[NPIX + px0]) + __half2float(lp[NPIX + px0]);
        float ya1 = __half2float(hp[px1]) + __half2float(lp[px1]);
        float yb1 = __half2float(hp[NPIX + px1]) + __half2float(lp[NPIX + px1]);
        *(uint32_t*)(dst0 + ch) = ph2(fmaf(a, O[nc][0] * linv0, ya0),
                                      fmaf(a, O[nc][1] * linv0, yb0));
        *(uint32_t*)(dst1 + ch) = ph2(fmaf(a, O[nc][2] * linv1, ya1),
                                      fmaf(a, O[nc][3] * linv1, yb1));
    }
}

// ---------------------------------------------------------------------------
// CAM gram matrix via fp16 hi/lo split MMA, split-K partials.
// ---------------------------------------------------------------------------
#define CAME_SMEM 36864

__global__ void __launch_bounds__(256, 2) cam_energy_mma(
        const __half* __restrict__ yhi, const __half* __restrict__ ylo,
        float* __restrict__ epart) {
    extern __shared__ __align__(16) char smc[];
    const uint32_t smb = smem_u32(smc);
    const int tid = threadIdx.x, lane = tid & 31, wid = tid >> 5;
    const int warp_m = wid >> 2, warp_n = wid & 3;
    const int b = blockIdx.y, ksid = blockIdx.x;
    const int g = lane >> 3, r8 = lane & 7;

    float acc[4][4][4];
#pragma unroll
    for (int mt = 0; mt < 4; mt++)
#pragma unroll
        for (int nt = 0; nt < 4; nt++)
#pragma unroll
            for (int r = 0; r < 4; r++) acc[mt][nt][r] = 0.0f;

    for (int chunk = 0; chunk < 4; chunk++) {
        const int k0 = ksid * 256 + chunk * 64;
        __syncthreads();
#pragma unroll
        for (int t = 0; t < 4; t++) {
            int idx = tid + t * 256;
            int ch = idx >> 3, seg = idx & 7;
            CP_ASYNC16(smb + ch * 144 + seg * 16,
                       yhi + ((size_t)b * 128 + ch) * NPIX + k0 + seg * 8);
            CP_ASYNC16(smb + 18432 + ch * 144 + seg * 16,
                       ylo + ((size_t)b * 128 + ch) * NPIX + k0 + seg * 8);
        }
        CP_COMMIT();
        CP_WAIT(0);
        __syncthreads();

#pragma unroll
        for (int ks = 0; ks < 4; ks++) {
            uint32_t ahi[4][4], alo[4][4];
#pragma unroll
            for (int mt = 0; mt < 4; mt++) {
                const uint32_t arow = (warp_m * 64 + mt * 16 + (g & 1) * 8 + r8) * 144
                                      + ks * 32 + (g >> 1) * 16;
                ldsm4(ahi[mt], smb + arow);
                ldsm4(alo[mt], smb + 18432 + arow);
            }
            uint32_t bhi[2][4], blo[2][4];
#pragma unroll
            for (int t16 = 0; t16 < 2; t16++) {
                const uint32_t brow = (warp_n * 32 + t16 * 16 + (g >> 1) * 8 + r8) * 144
                                      + ks * 32 + (g & 1) * 16;
                ldsm4(bhi[t16], smb + brow);
                ldsm4(blo[t16], smb + 18432 + brow);
            }
#pragma unroll
            for (int mt = 0; mt < 4; mt++)
#pragma unroll
                for (int t16 = 0; t16 < 2; t16++) {
                    mma_f16(acc[mt][2 * t16],     ahi[mt], bhi[t16][0], bhi[t16][1]);
                    mma_f16(acc[mt][2 * t16 + 1], ahi[mt], bhi[t16][2], bhi[t16][3]);
                    mma_f16(acc[mt][2 * t16],     ahi[mt], blo[t16][0], blo[t16][1]);
                    mma_f16(acc[mt][2 * t16 + 1], ahi[mt], blo[t16][2], blo[t16][3]);
                    mma_f16(acc[mt][2 * t16],     alo[mt], bhi[t16][0], bhi[t16][1]);
                    mma_f16(acc[mt][2 * t16 + 1], alo[mt], bhi[t16][2], bhi[t16][3]);
                }
        }
    }

    float* ep = epart + (((size_t)ksid * BATCH + b) * 128) * 128;
#pragma unroll
    for (int mt = 0; mt < 4; mt++) {
        const int c0 = warp_m * 64 + mt * 16 + (lane >> 2);
#pragma unroll
        for (int nt = 0; nt < 4; nt++) {
            const int d = warp_n * 32 + nt * 8 + 2 * (lane & 3);
            *(float2*)(ep + (size_t)c0 * 128 + d) = make_float2(acc[mt][nt][0], acc[mt][nt][1]);
            *(float2*)(ep + (size_t)(c0 + 8) * 128 + d) = make_float2(acc[mt][nt][2], acc[mt][nt][3]);
        }
    }
}

// ---------------------------------------------------------------------------
// CAM softmax of (rowmax - E), reducing the KSPLIT partials -> fp16 attn
// ---------------------------------------------------------------------------
__global__ void cam_softmax_kernel(const float* __restrict__ epart,
                                   __half* __restrict__ attn) {
    const int row = blockIdx.x;
    const int tid = threadIdx.x;
    __shared__ float red[4];

    float e = 0.0f;
#pragma unroll
    for (int s = 0; s < KSPLIT; s++)
        e += epart[((size_t)s * 1024 + row) * 128 + tid];

    float m = e;
#pragma unroll
    for (int off = 16; off; off >>= 1) m = fmaxf(m, __shfl_xor_sync(0xffffffff, m, off));
    if ((tid & 31) == 0) red[tid >> 5] = m;
    __syncthreads();
    float mx = fmaxf(fmaxf(red[0], red[1]), fmaxf(red[2], red[3]));
    float e2 = mx - e;
    __syncthreads();

    float m2 = e2;
#pragma unroll
    for (int off = 16; off; off >>= 1) m2 = fmaxf(m2, __shfl_xor_sync(0xffffffff, m2, off));
    if ((tid & 31) == 0) red[tid >> 5] = m2;
    __syncthreads();
    m2 = fmaxf(fmaxf(red[0], red[1]), fmaxf(red[2], red[3]));
    float p = __expf(e2 - m2);
    __syncthreads();

    float s = p;
#pragma unroll
    for (int off = 16; off; off >>= 1) s += __shfl_xor_sync(0xffffffff, s, off);
    if ((tid & 31) == 0) red[tid >> 5] = s;
    __syncthreads();
    s = red[0] + red[1] + red[2] + red[3];

    attn[(size_t)row * 128 + tid] = __float2half(p / s);
}

// ---------------------------------------------------------------------------
// CAM feature via fp16 MMA -> fp16 padded NHWC; residual from hi+lo.
// ---------------------------------------------------------------------------
#define CAMF_SMEM 53248

__global__ void __launch_bounds__(256, 1) cam_feat_mma(
        const __half* __restrict__ attn16,
        const __half* __restrict__ yhi, const __half* __restrict__ ylo,
        const float* __restrict__ beta, __half* __restrict__ xp2) {
    extern __shared__ __align__(16) char smc[];
    const uint32_t smb = smem_u32(smc);
    const int tid = threadIdx.x, lane = tid & 31, wid = tid >> 5;
    const int b = blockIdx.y;
    const int n0 = blockIdx.x * 64;
    const int g = lane >> 3;

#pragma unroll
    for (int t = 0; t < 8; t++) {
        int idx = tid + t * 256;
        int c = idx >> 4, seg = idx & 15;
        CP_ASYNC16(smb + c * 272 + seg * 16,
                   attn16 + ((size_t)b * 128 + c) * 128 + seg * 8);
    }
#pragma unroll
    for (int t = 0; t < 4; t++) {
        int idx = tid + t * 256;
        int ch = idx >> 3, seg = idx & 7;
        CP_ASYNC16(smb + 34816 + ch * 144 + seg * 16,
                   yhi + ((size_t)b * 128 + ch) * NPIX + n0 + seg * 8);
    }
    CP_COMMIT();
    CP_WAIT(0);
    __syncthreads();

    const int mt = wid;
    float acc[8][4];
#pragma unroll
    for (int nt = 0; nt < 8; nt++)
#pragma unroll
        for (int r = 0; r < 4; r++) acc[nt][r] = 0.0f;

    const uint32_t Bsm = smb + 34816;
#pragma unroll
    for (int ks = 0; ks < 8; ks++) {
        uint32_t afr[4];
        ldsm4(afr, smb + (mt * 16 + (g & 1) * 8 + (lane & 7)) * 272
                  + ks * 32 + (g >> 1) * 16);
#pragma unroll
        for (int t16 = 0; t16 < 4; t16++) {
            uint32_t bfr[4];
            ldsm4t(bfr, Bsm + (ks * 16 + (g & 1) * 8 + (lane & 7)) * 144
                       + (t16 * 16 + (g >> 1) * 8) * 2);
            mma_f16(acc[2 * t16],     afr, bfr[0], bfr[1]);
            mma_f16(acc[2 * t16 + 1], afr, bfr[2], bfr[3]);
        }
    }

    const float bet = beta[0];
    const int c0 = mt * 16 + (lane >> 2);
#pragma unroll
    for (int nt = 0; nt < 8; nt++) {
        const int n = n0 + nt * 8 + 2 * (lane & 3);
        const __half* h0p = yhi + ((size_t)b * 128 + c0) * NPIX;
        const __half* l0p = ylo + ((size_t)b * 128 + c0) * NPIX;
        float y00 = __half2float(h0p[n]) + __half2float(l0p[n]);
        float y01 = __half2float(h0p[n + 1]) + __half2float(l0p[n + 1]);
        float y80 = __half2float(h0p[8 * NPIX + n]) + __half2float(l0p[8 * NPIX + n]);
        float y81 = __half2float(h0p[8 * NPIX + n + 1]) + __half2float(l0p[8 * NPIX + n + 1]);
        __half* p0 = xp2 + (((size_t)b * XP_H + (n >> 6) + 1) * XP_H + (n & 63) + 1) * CI;
        __half* p1 = p0 + CI;
        p0[c0]     = __float2half(fmaf(bet, acc[nt][0], y00));
        p1[c0]     = __float2half(fmaf(bet, acc[nt][1], y01));
        p0[c0 + 8] = __float2half(fmaf(bet, acc[nt][2], y80));
        p1[c0 + 8] = __float2half(fmaf(bet, acc[nt][3], y81));
    }
}

// ---------------------------------------------------------------------------
// Final heads via one fused fp16 MMA:  A[64x256] @ [fp;fc](256 x 64px tile).
// ---------------------------------------------------------------------------
#define FIN_SMEM 69632

__global__ void __launch_bounds__(128, 2) final_mma(
        const __half* __restrict__ wfin,
        const __half* __restrict__ fp, const __half* __restrict__ fc,
        const float* __restrict__ bout, const float* __restrict__ bp3,
        const float* __restrict__ bc3, float* __restrict__ out) {
    extern __shared__ __align__(16) char smc[];
    const uint32_t smb = smem_u32(smc);
    const int tid = threadIdx.x, lane = tid & 31, wid = tid >> 5;
    const int b = blockIdx.y;
    const int n0 = blockIdx.x * 64;
    const int g = lane >> 3;

#pragma unroll
    for (int t = 0; t < 16; t++) {
        int i = tid + t * 128;
        CP_ASYNC16(smb + i * 16, wfin + i * 8);
    }
#pragma unroll
    for (int t = 0; t < 16; t++) {
        int idx = tid + t * 128;
        int ch = idx >> 3, seg = idx & 7;
        const __half* src = (ch < 128)
            ? fp + ((size_t)b * 128 + ch) * NPIX + n0 + seg * 8
            : fc + ((size_t)b * 128 + (ch - 128)) * NPIX + n0 + seg * 8;
        CP_ASYNC16(smb + 32768 + ch * 144 + seg * 16, src);
    }
    CP_COMMIT();
    CP_WAIT(0);
    __syncthreads();

    const int mt = wid;
    float acc[8][4];
#pragma unroll
    for (int nt = 0; nt < 8; nt++)
#pragma unroll
        for (int r = 0; r < 4; r++) acc[nt][r] = 0.0f;

    const char* Aptr = smc;
    const uint32_t Bsm = smb + 32768;
#pragma unroll
    for (int ks = 0; ks < 16; ks++) {
        uint4 v = *(const uint4*)(Aptr + (((mt * 16 + ks) * 32 + lane) << 4));
        uint32_t afr[4] = {v.x, v.y, v.z, v.w};
#pragma unroll
        for (int t16 = 0; t16 < 4; t16++) {
            uint32_t bfr[4];
            ldsm4t(bfr, Bsm + (ks * 16 + (g & 1) * 8 + (lane & 7)) * 144
                       + (t16 * 16 + (g >> 1) * 8) * 2);
            mma_f16(acc[2 * t16],     afr, bfr[0], bfr[1]);
            mma_f16(acc[2 * t16 + 1], afr, bfr[2], bfr[3]);
        }
    }

    const size_t SEG = (size_t)BATCH * NC * NPIX;
    auto emit = [&](int row, int px, float v) {
        if (row >= 57) return;
        float bias;
        size_t base;
        if (row < 19)      { bias = bout[row]; base = ((size_t)b * NC + row) * NPIX; }
        else if (row < 38) { bias = bp3[row - 19]; base = SEG + ((size_t)b * NC + row - 19) * NPIX; }
        else               { bias = bc3[row - 38]; base = 2 * SEG + ((size_t)b * NC + row - 38) * NPIX; }
        out[base + px] = sigmoidf_(v + bias);
    };

    const int r0 = mt * 16 + (lane >> 2);
#pragma unroll
    for (int nt = 0; nt < 8; nt++) {
        const int px = n0 + nt * 8 + 2 * (lane & 3);
        emit(r0,     px,     acc[nt][0]);
        emit(r0,     px + 1, acc[nt][1]);
        emit(r0 + 8, px,     acc[nt][2]);
        emit(r0 + 8, px + 1, acc[nt][3]);
    }
}

// ---------------------------------------------------------------------------
// Streams / events (created once at program load)
// ---------------------------------------------------------------------------
namespace {
struct StreamInit {
    cudaStream_t s1;
    cudaEvent_t e0, e1, e2, e3, e4, e5;
    StreamInit() {
        cudaStreamCreateWithFlags(&s1, cudaStreamNonBlocking);
        cudaEventCreateWithFlags(&e0, cudaEventDisableTiming);
        cudaEventCreateWithFlags(&e1, cudaEventDisableTiming);
        cudaEventCreateWithFlags(&e2, cudaEventDisableTiming);
        cudaEventCreateWithFlags(&e3, cudaEventDisableTiming);
        cudaEventCreateWithFlags(&e4, cudaEventDisableTiming);
        cudaEventCreateWithFlags(&e5, cudaEventDisableTiming);
    }
};
StreamInit g_str;
}

// ---------------------------------------------------------------------------
// Launch
// ---------------------------------------------------------------------------
extern "C" void kernel_launch(void* const* d_in, const int* in_sizes, int n_in,
                              void* d_out, int out_size) {
    const float* x    = (const float*)d_in[0];
    const float* Wp1  = (const float*)d_in[1];
    const float* bnp1 = (const float*)d_in[2];
    const float* Wc1  = (const float*)d_in[3];
    const float* bnc1 = (const float*)d_in[4];
    const float* Wb   = (const float*)d_in[5];
    const float* bb   = (const float*)d_in[6];
    const float* Wc   = (const float*)d_in[7];
    const float* bc   = (const float*)d_in[8];
    const float* Wd   = (const float*)d_in[9];
    const float* bd   = (const float*)d_in[10];
    const float* alpha= (const float*)d_in[11];
    const float* beta = (const float*)d_in[12];
    const float* Wp2  = (const float*)d_in[13];
    const float* bnp2 = (const float*)d_in[14];
    const float* Wc2  = (const float*)d_in[15];
    const float* bnc2 = (const float*)d_in[16];
    const float* Wout = (const float*)d_in[17];
    const float* bout = (const float*)d_in[18];
    const float* Wp3  = (const float*)d_in[19];
    const float* bp3  = (const float*)d_in[20];
    const float* Wc3  = (const float*)d_in[21];
    const float* bc3  = (const float*)d_in[22];
    float* out = (float*)d_out;

    float* epart;
    __half *featp1h, *featp1lo, *featc1h, *featc1lo, *qh, *kh, *vd, *attn16;
    __half *xpad, *xp2a, *xp2b, *wf1, *wf2, *wqkv, *wfin;
    cudaGetSymbolAddress((void**)&featp1h,  g_featp1h);
    cudaGetSymbolAddress((void**)&featp1lo, g_featp1lo);
    cudaGetSymbolAddress((void**)&featc1h,  g_featc1h);
    cudaGetSymbolAddress((void**)&featc1lo, g_featc1lo);
    cudaGetSymbolAddress((void**)&qh,       g_qh);
    cudaGetSymbolAddress((void**)&kh,       g_kh);
    cudaGetSymbolAddress((void**)&vd,       g_vd);
    cudaGetSymbolAddress((void**)&epart,    g_epart);
    cudaGetSymbolAddress((void**)&attn16,   g_attn16);
    cudaGetSymbolAddress((void**)&xpad,     g_xpad);
    cudaGetSymbolAddress((void**)&xp2a,     g_xp2a);
    cudaGetSymbolAddress((void**)&xp2b,     g_xp2b);
    cudaGetSymbolAddress((void**)&wf1,      g_wf16_1);
    cudaGetSymbolAddress((void**)&wf2,      g_wf16_2);
    cudaGetSymbolAddress((void**)&wqkv,     g_wqkv);
    cudaGetSymbolAddress((void**)&wfin,     g_wfinal);

    cudaFuncSetAttribute(conv_mma_kernel<512>,
                         cudaFuncAttributeMaxDynamicSharedMemorySize, CONV_SMEM);
    cudaFuncSetAttribute(conv_mma_kernel<128>,
                         cudaFuncAttributeMaxDynamicSharedMemorySize, CONV_SMEM);
    cudaFuncSetAttribute(pam_attn_mma,
                         cudaFuncAttributeMaxDynamicSharedMemorySize, ATT_SMEM);
    cudaFuncSetAttribute(pam_attn_mma,
                         cudaFuncAttributePreferredSharedMemoryCarveout, 100);
    cudaFuncSetAttribute(qkv_kernel,
                         cudaFuncAttributeMaxDynamicSharedMemorySize, QKV_SMEM);
    cudaFuncSetAttribute(cam_energy_mma,
                         cudaFuncAttributeMaxDynamicSharedMemorySize, CAME_SMEM);
    cudaFuncSetAttribute(cam_feat_mma,
                         cudaFuncAttributeMaxDynamicSharedMemorySize, CAMF_SMEM);
    cudaFuncSetAttribute(final_mma,
                         cudaFuncAttributeMaxDynamicSharedMemorySize, FIN_SMEM);

    cudaStream_t s1 = g_str.s1;

    // Fork s1 off the main stream
    cudaEventRecord(g_str.e0, 0);
    cudaStreamWaitEvent(s1, g_str.e0, 0);

    // s0: interior packing
    pack_x_kernel<<<dim3(64, BATCH), 256>>>(x, xpad);
    cudaEventRecord(g_str.e5, 0);   // pack_x done

    // s1: consolidated borders + weight packing (parallel with pack_x)
    zero_borders_all<<<dim3(XP_H, BATCH, 3), 256, 0, s1>>>(xpad, xp2a, xp2b);
    pack_w16<<<dim3(144, 2), 256, 0, s1>>>(Wp1, Wc1, wf1, CIN);
    cudaEventRecord(g_str.e1, s1);  // borders + wf1 ready
    pack_small<<<2, 256, 0, s1>>>(Wd, Wb, Wc, wqkv, Wout, Wp3, Wc3, wfin);
    pack_w16<<<dim3(36, 2), 256, 0, s1>>>(Wp2, Wc2, wf2, CI);
    cudaEventRecord(g_str.e4, s1);  // wqkv/wfinal/wf2 ready

    // s0: conv1-PAM FIRST (alone at full chip rate)
    cudaStreamWaitEvent(0, g_str.e1, 0);
    conv_mma_kernel<512><<<dim3(32, BATCH, 1), 256, CONV_SMEM>>>(
        xpad, xpad, wf1, bnp1, bnp1, featp1h, featp1h, featp1lo, featp1lo);
    cudaEventRecord(g_str.e2, 0);   // conv1-PAM done

    // s1: conv1-CAM + entire CAM chain (concurrent with PAM chain on s0)
    cudaStreamWaitEvent(s1, g_str.e2, 0);
    cudaStreamWaitEvent(s1, g_str.e5, 0);
    conv_mma_kernel<512><<<dim3(32, BATCH, 1), 256, CONV_SMEM, s1>>>(
        xpad, xpad, wf1 + 144 * 4096, bnc1, bnc1, featc1h, featc1h, featc1lo, featc1lo);
    cam_energy_mma<<<dim3(KSPLIT, BATCH), 256, CAME_SMEM, s1>>>(featc1h, featc1lo, epart);
    cam_softmax_kernel<<<BATCH * 128, 128, 0, s1>>>(epart, attn16);
    cam_feat_mma<<<dim3(64, BATCH), 256, CAMF_SMEM, s1>>>(
        attn16, featc1h, featc1lo, beta, xp2b);
    conv_mma_kernel<128><<<dim3(32, BATCH, 1), 256, CONV_SMEM, s1>>>(
        xp2b, xp2b, wf2 + 36 * 4096, bnc2, bnc2, featc1h, featc1h, nullptr, nullptr);
    cudaEventRecord(g_str.e3, s1);  // CAM branch fully done

    // s0: PAM chain (qkv needs wqkv -> wait e4)
    cudaStreamWaitEvent(0, g_str.e4, 0);
    qkv_kernel<<<dim3(64, BATCH), 320, QKV_SMEM>>>(
        wqkv, featp1h, bd, bb, bc, vd, qh, kh);
    pam_attn_mma<<<dim3(64, BATCH), 128, ATT_SMEM>>>(
        qh, kh, vd, featp1h, featp1lo, alpha, xp2a);
    conv_mma_kernel<128><<<dim3(32, BATCH, 1), 256, CONV_SMEM>>>(
        xp2a, xp2a, wf2, bnp2, bnp2, featp1h, featp1h, nullptr, nullptr);

    // Join, then fused final heads
    cudaStreamWaitEvent(0, g_str.e3, 0);
    final_mma<<<dim3(64, BATCH), 128, FIN_SMEM>>>(
        wfin, featp1h, featc1h, bout, bp3, bc3, out);
}

// round 13
// speedup vs baseline: 1.0001x; 1.0001x over previous
#include <cuda_runtime.h>
#include <cuda_bf16.h>
#include <cuda_fp16.h>
#include <math.h>
#include <cstdint>

// ---------------------------------------------------------------------------
// Problem constants
// ---------------------------------------------------------------------------
#define BATCH 8
#define CIN   512
#define CI    128
#define CK    16
#define NC    19
#define NPIX  4096
#define FEAT_ELEMS (BATCH * CI * NPIX)
#define XP_H 66
#define KSPLIT 16

// ---------------------------------------------------------------------------
// Scratch (device globals)
// ---------------------------------------------------------------------------
__device__ __half g_featp1h[FEAT_ELEMS];     // conv1-p hi; later conv2-p out
__device__ __half g_featp1lo[FEAT_ELEMS];    // conv1-p lo residual
__device__ __half g_featc1h[FEAT_ELEMS];     // conv1-c hi; later conv2-c out
__device__ __half g_featc1lo[FEAT_ELEMS];    // conv1-c lo residual
__device__ __half g_qh[BATCH * NPIX * CK];
__device__ __half g_kh[BATCH * NPIX * CK];
__device__ __half g_vd[FEAT_ELEMS];
__device__ float  g_epart[KSPLIT * BATCH * CI * CI];
__device__ __half g_attn16[BATCH * CI * CI];
__device__ __half g_xpad[BATCH * XP_H * XP_H * CIN];
__device__ __half g_xp2a[BATCH * XP_H * XP_H * CI];
__device__ __half g_xp2b[BATCH * XP_H * XP_H * CI];
__device__ __half g_wf16_1[2 * 144 * 4096];
__device__ __half g_wf16_2[2 * 36 * 4096];
__device__ __half g_wqkv[10 * 8 * 32 * 8];
__device__ __half g_wfinal[4 * 16 * 32 * 8];   // [64 rows x 256 k] frag-packed

__device__ __forceinline__ float sigmoidf_(float x) {
    return 1.0f / (1.0f + __expf(-x));
}
__device__ __forceinline__ uint32_t smem_u32(const void* p) {
    uint32_t a;
    asm("{ .reg .u64 t; cvta.to.shared.u64 t, %1; cvt.u32.u64 %0, t; }" : "=r"(a) : "l"(p));
    return a;
}
__device__ __forceinline__ void mma_f16(float c[4], const uint32_t a[4], const uint32_t b0, const uint32_t b1) {
    asm volatile(
        "mma.sync.aligned.m16n8k16.row.col.f32.f16.f16.f32 "
        "{%0,%1,%2,%3}, {%4,%5,%6,%7}, {%8,%9}, {%0,%1,%2,%3};"
        : "+f"(c[0]), "+f"(c[1]), "+f"(c[2]), "+f"(c[3])
        : "r"(a[0]), "r"(a[1]), "r"(a[2]), "r"(a[3]), "r"(b0), "r"(b1));
}
__device__ __forceinline__ void ldsm4(uint32_t r[4], uint32_t addr) {
    asm volatile("ldmatrix.sync.aligned.m8n8.x4.shared.b16 {%0,%1,%2,%3}, [%4];"
                 : "=r"(r[0]), "=r"(r[1]), "=r"(r[2]), "=r"(r[3]) : "r"(addr));
}
__device__ __forceinline__ void ldsm4t(uint32_t r[4], uint32_t addr) {
    asm volatile("ldmatrix.sync.aligned.m8n8.x4.trans.shared.b16 {%0,%1,%2,%3}, [%4];"
                 : "=r"(r[0]), "=r"(r[1]), "=r"(r[2]), "=r"(r[3]) : "r"(addr));
}
#define CP_ASYNC16(dst, src) \
    asm volatile("cp.async.ca.shared.global [%0], [%1], 16;" :: "r"(dst), "l"(src))
#define CP_COMMIT() asm volatile("cp.async.commit_group;")
#define CP_WAIT(N)  asm volatile("cp.async.wait_group %0;" :: "n"(N))

__device__ __forceinline__ uint32_t ph2(float x, float y) {
    __half2 h = __floats2half2_rn(x, y);
    return *(uint32_t*)&h;
}

// ---------------------------------------------------------------------------
// Pack x: f32 NCHW -> fp16 NHWC padded
// ---------------------------------------------------------------------------
__global__ void pack_x_kernel(const float* __restrict__ x, __half* __restrict__ xp) {
    const int h = blockIdx.x, b = blockIdx.y, tid = threadIdx.x;
    __shared__ float s[32][65];
    for (int ci0 = 0; ci0 < CIN; ci0 += 32) {
        for (int idx = tid; idx < 32 * 64; idx += 256) {
            int ci_l = idx >> 6, w = idx & 63;
            s[ci_l][w] = x[(((size_t)b * CIN + ci0 + ci_l) * 64 + h) * 64 + w];
        }
        __syncthreads();
        for (int idx = tid; idx < 64 * 32; idx += 256) {
            int w = idx >> 5, ci_l = idx & 31;
            xp[(((size_t)b * XP_H + h + 1) * XP_H + w + 1) * CIN + ci0 + ci_l] =
                __float2half(s[ci_l][w]);
        }
        __syncthreads();
    }
}

// One launch zeroes the borders of all three padded buffers (z selects).
__global__ void zero_borders_all(__half* __restrict__ xpad,
                                 __half* __restrict__ xp2a,
                                 __half* __restrict__ xp2b) {
    const int hp = blockIdx.x, b = blockIdx.y, z = blockIdx.z, tid = threadIdx.x;
    __half* base = (z == 0) ? xpad : (z == 1 ? xp2a : xp2b);
    const int C = (z == 0) ? CIN : CI;
    __half* row = base + ((size_t)b * XP_H + hp) * XP_H * C;
    const __half zz = __float2half(0.0f);
    if (hp == 0 || hp == XP_H - 1) {
        for (int idx = tid; idx < XP_H * C; idx += 256) row[idx] = zz;
    } else {
        for (int idx = tid; idx < C; idx += 256) {
            row[idx] = zz;
            row[(size_t)(XP_H - 1) * C + idx] = zz;
        }
    }
}

// ---------------------------------------------------------------------------
// Pack conv weights into m16n8k16 fp16 A-fragment order.
// ---------------------------------------------------------------------------
__global__ void pack_w16(const float* __restrict__ W0, const float* __restrict__ W1,
                         __half* __restrict__ wf, int CIN_T) {
    const int cpc = CIN_T / 32;
    const int chunk = blockIdx.x;
    const int kwh = chunk / cpc, cb = chunk % cpc;
    const float* W = blockIdx.y ? W1 : W0;
    __half* dst = wf + ((size_t)blockIdx.y * gridDim.x + chunk) * 4096;
    for (int t = 0; t < 16; t++) {
        int idx = threadIdx.x + t * 256;
        int j = idx & 7, lane = (idx >> 3) & 31, ks = (idx >> 8) & 1, mt = idx >> 9;
        int reg = j >> 1, h = j & 1;
        int co = mt * 16 + (lane >> 2) + (reg & 1) * 8;
        int ci = cb * 32 + ks * 16 + (lane & 3) * 2 + (reg >> 1) * 8 + h;
        dst[idx] = __float2half(W[((size_t)co * CIN_T + ci) * 9 + kwh]);
    }
}

// Parallel small-table pack: 144 CTAs x 256, 1 element/thread.
// idx < 20480: wqkv;  20480 <= idx < 36864: wfinal.
__global__ void pack_small(const float* __restrict__ Wd, const float* __restrict__ Wb,
                           const float* __restrict__ Wc, __half* __restrict__ dqkv,
                           const float* __restrict__ Wout, const float* __restrict__ Wp3,
                           const float* __restrict__ Wc3, __half* __restrict__ dfin) {
    int gi = blockIdx.x * 256 + threadIdx.x;
    if (gi < 20480) {
        int idx = gi;
        int j = idx & 7, lane = (idx >> 3) & 31, ks = (idx >> 8) & 7, mt = idx >> 11;
        int reg = j >> 1, h = j & 1;
        int row = mt * 16 + (lane >> 2) + (reg & 1) * 8;
        int col = ks * 16 + (lane & 3) * 2 + (reg >> 1) * 8 + h;
        float w;
        if (row < 128)      w = Wd[row * 128 + col];
        else if (row < 144) w = Wb[(row - 128) * 128 + col];
        else                w = Wc[(row - 144) * 128 + col];
        dqkv[idx] = __float2half(w);
    } else if (gi < 36864) {
        int idx = gi - 20480;
        int j = idx & 7, lane = (idx >> 3) & 31, ks = (idx >> 8) & 15, mt = idx >> 12;
        int reg = j >> 1, h = j & 1;
        int row = mt * 16 + (lane >> 2) + (reg & 1) * 8;
        int col = ks * 16 + (lane & 3) * 2 + (reg >> 1) * 8 + h;
        float w = 0.0f;
        if (col < 128) {
            if (row < 19)      w = Wout[row * 128 + col];
            else if (row < 38) w = Wp3[(row - 19) * 128 + col];
        } else {
            int c = col - 128;
            if (row < 19)      w = Wout[row * 128 + c];
            else if (row >= 38 && row < 57) w = Wc3[(row - 38) * 128 + c];
        }
        dfin[idx] = __float2half(w);
    }
}

// ---------------------------------------------------------------------------
// conv3x3 implicit GEMM, fp16 m16n8k16, halo-reuse B staging, fused BN+ReLU.
// smem: B 2x21120 @0; A 2x24576 @42240.  Total 91392.  Pixel stride 80B.
// ---------------------------------------------------------------------------
#define CONV_SMEM 91392
#define BPX 80

template<int CIN_T>
__global__ void __launch_bounds__(256, 2) conv_mma_kernel(
        const __half* __restrict__ xpA, const __half* __restrict__ xpB,
        const __half* __restrict__ wfrag,
        const float* __restrict__ bn0, const float* __restrict__ bn1,
        __half* __restrict__ o16_0, __half* __restrict__ o16_1,
        __half* __restrict__ olo_0, __half* __restrict__ olo_1) {
    constexpr int CPC = CIN_T / 32;
    constexpr int NS = CPC * 3;
    extern __shared__ __align__(16) char smc[];
    const uint32_t smb = smem_u32(smc);
    const uint32_t Boff = smb;
    const uint32_t Aoff = smb + 2 * 21120;

    const int tid = threadIdx.x, lane = tid & 31, wid = tid >> 5;
    const int warp_m = wid >> 2, warp_n = wid & 3;
    const int b = blockIdx.y, z = blockIdx.z;
    const int pxbase = blockIdx.x * 128;
    const int h0 = pxbase >> 6;
    const __half* xp = z ? xpB : xpA;
    const __half* Wf = wfrag + (size_t)z * (9 * CPC) * 4096;
    const float* bn = z ? bn1 : bn0;
    __half* o16 = z ? o16_1 : o16_0;
    __half* olo = z ? olo_1 : olo_0;
    const int g = lane >> 3;

    float acc[4][4][4];
#pragma unroll
    for (int mt = 0; mt < 4; mt++)
#pragma unroll
        for (int nt = 0; nt < 4; nt++)
#pragma unroll
            for (int r = 0; r < 4; r++) acc[mt][nt][r] = 0.0f;

    auto stageA = [&](int s, int buf) {
        const int cb = s / 3, kh = s % 3;
        const uint32_t Ad = Aoff + buf * 24576;
#pragma unroll
        for (int kw = 0; kw < 3; kw++) {
            const __half* src = Wf + (size_t)((kh * 3 + kw) * CPC + cb) * 4096;
#pragma unroll
            for (int t = 0; t < 2; t++) {
                int idx = tid + t * 256;
                CP_ASYNC16(Ad + kw * 8192 + idx * 16, src + idx * 8);
            }
        }
    };
    auto stageB = [&](int cb, int buf) {
        const uint32_t Bd = Boff + buf * 21120;
        const __half* base = xp + ((size_t)(b * XP_H + h0) * XP_H) * CIN_T + cb * 32;
        for (int idx = tid; idx < 1056; idx += 256) {
            int r = idx / 264, rem = idx % 264;
            int c = rem >> 2, q = rem & 3;
            CP_ASYNC16(Bd + (r * 66 + c) * BPX + q * 16,
                       base + ((size_t)r * XP_H + c) * CIN_T + q * 8);
        }
    };

    stageB(0, 0);
    stageA(0, 0);
    CP_COMMIT();

    for (int s = 0; s < NS; s++) {
        const int cb = s / 3, kh = s % 3;
        if (s + 1 < NS) {
            stageA(s + 1, (s + 1) & 1);
            if ((s + 1) % 3 == 0) stageB((s + 1) / 3, ((s + 1) / 3) & 1);
            CP_COMMIT();
            CP_WAIT(1);
        } else {
            CP_WAIT(0);
        }
        __syncthreads();

        const uint32_t Bh = Boff + (cb & 1) * 21120;
        const char* Ap = smc + 2 * 21120 + (s & 1) * 24576;
#pragma unroll
        for (int ks = 0; ks < 2; ks++) {
#pragma unroll
            for (int kw = 0; kw < 3; kw++) {
                uint32_t afr[4][4];
#pragma unroll
                for (int mt = 0; mt < 4; mt++) {
                    uint4 v = *(const uint4*)(Ap + kw * 8192 +
                        ((((warp_m * 4 + mt) * 2 + ks) * 32 + lane) << 4));
                    afr[mt][0] = v.x; afr[mt][1] = v.y; afr[mt][2] = v.z; afr[mt][3] = v.w;
                }
                uint32_t bfr[2][4];
#pragma unroll
                for (int t16 = 0; t16 < 2; t16++) {
                    const int n_row = warp_n * 32 + t16 * 16 + (g >> 1) * 8 + (lane & 7);
                    const int r = n_row >> 6, w = n_row & 63;
                    ldsm4(bfr[t16], Bh + ((r + kh) * 66 + w + kw) * BPX
                                      + ks * 32 + (g & 1) * 16);
                }
#pragma unroll
                for (int mt = 0; mt < 4; mt++)
#pragma unroll
                    for (int t16 = 0; t16 < 2; t16++) {
                        mma_f16(acc[mt][2 * t16],     afr[mt], bfr[t16][0], bfr[t16][1]);
                        mma_f16(acc[mt][2 * t16 + 1], afr[mt], bfr[t16][2], bfr[t16][3]);
                    }
            }
        }
        __syncthreads();
    }

#pragma unroll
    for (int mt = 0; mt < 4; mt++) {
        const int co = warp_m * 64 + mt * 16 + (lane >> 2);
        const float sc0 = bn[co],     sh0 = bn[128 + co];
        const float sc8 = bn[co + 8], sh8 = bn[136 + co];
#pragma unroll
        for (int nt = 0; nt < 4; nt++) {
            const int px = pxbase + warp_n * 32 + nt * 8 + 2 * (lane & 3);
            float v0x = fmaxf(acc[mt][nt][0] * sc0 + sh0, 0.0f);
            float v0y = fmaxf(acc[mt][nt][1] * sc0 + sh0, 0.0f);
            float v1x = fmaxf(acc[mt][nt][2] * sc8 + sh8, 0.0f);
            float v1y = fmaxf(acc[mt][nt][3] * sc8 + sh8, 0.0f);
            *(uint32_t*)(o16 + ((size_t)b * 128 + co) * NPIX + px) = ph2(v0x, v0y);
            *(uint32_t*)(o16 + ((size_t)b * 128 + co + 8) * NPIX + px) = ph2(v1x, v1y);
            if (olo) {
                float r0x = v0x - __half2float(__float2half(v0x));
                float r0y = v0y - __half2float(__float2half(v0y));
                float r1x = v1x - __half2float(__float2half(v1x));
                float r1y = v1y - __half2float(__float2half(v1y));
                *(uint32_t*)(olo + ((size_t)b * 128 + co) * NPIX + px) = ph2(r0x, r0y);
                *(uint32_t*)(olo + ((size_t)b * 128 + co + 8) * NPIX + px) = ph2(r1x, r1y);
            }
        }
    }
}

// ---------------------------------------------------------------------------
// QKV GEMM: [Wd;Wb;Wc](160x128) @ y16(128x4096) + bias.
// ---------------------------------------------------------------------------
#define QKV_SMEM 59392

__global__ void __launch_bounds__(320, 1) qkv_kernel(
        const __half* __restrict__ wq, const __half* __restrict__ y16,
        const float* __restrict__ bd, const float* __restrict__ bb,
        const float* __restrict__ bc,
        __half* __restrict__ vh, __half* __restrict__ qh, __half* __restrict__ kh) {
    extern __shared__ __align__(16) char smc[];
    const uint32_t smb = smem_u32(smc);
    const int tid = threadIdx.x, lane = tid & 31, wid = tid >> 5;
    const int b = blockIdx.y;
    const int n0 = blockIdx.x * 64;
    const int g = lane >> 3;

#pragma unroll
    for (int t = 0; t < 8; t++) {
        int i = tid + t * 320;
        CP_ASYNC16(smb + i * 16, wq + i * 8);
    }
    for (int idx = tid; idx < 1024; idx += 320) {
        int ch = idx >> 3, seg = idx & 7;
        CP_ASYNC16(smb + 40960 + ch * 144 + seg * 16,
                   y16 + ((size_t)b * 128 + ch) * NPIX + n0 + seg * 8);
    }
    CP_COMMIT();
    CP_WAIT(0);
    __syncthreads();

    const int mt = wid;
    float acc[8][4];
#pragma unroll
    for (int nt = 0; nt < 8; nt++)
#pragma unroll
        for (int r = 0; r < 4; r++) acc[nt][r] = 0.0f;

    const char* Aptr = smc;
    const uint32_t Bsm = smb + 40960;
#pragma unroll
    for (int ks = 0; ks < 8; ks++) {
        uint4 v = *(const uint4*)(Aptr + (((mt * 8 + ks) * 32 + lane) << 4));
        uint32_t afr[4] = {v.x, v.y, v.z, v.w};
#pragma unroll
        for (int t16 = 0; t16 < 4; t16++) {
            uint32_t bfr[4];
            ldsm4t(bfr, Bsm + (ks * 16 + (g & 1) * 8 + (lane & 7)) * 144
                       + (t16 * 16 + (g >> 1) * 8) * 2);
            mma_f16(acc[2 * t16],     afr, bfr[0], bfr[1]);
            mma_f16(acc[2 * t16 + 1], afr, bfr[2], bfr[3]);
        }
    }

    const int r0 = mt * 16 + (lane >> 2);
    if (mt < 8) {
        const float b0 = bd[r0], b8 = bd[r0 + 8];
        __half* v0 = vh + ((size_t)b * 128 + r0) * NPIX;
        __half* v8 = vh + ((size_t)b * 128 + r0 + 8) * NPIX;
#pragma unroll
        for (int nt = 0; nt < 8; nt++) {
            const int n = n0 + nt * 8 + 2 * (lane & 3);
            *(uint32_t*)(v0 + n) = ph2(acc[nt][0] + b0, acc[nt][1] + b0);
            *(uint32_t*)(v8 + n) = ph2(acc[nt][2] + b8, acc[nt][3] + b8);
        }
    } else {
        const bool isq = (mt == 8);
        const float* bias = isq ? bb : bc;
        __half* dst = isq ? qh : kh;
        const int d = lane >> 2;
        const float b0 = bias[d], b8 = bias[d + 8];
#pragma unroll
        for (int nt = 0; nt < 8; nt++) {
            const int n = n0 + nt * 8 + 2 * (lane & 3);
            __half* p0 = dst + ((size_t)b * NPIX + n) * 16;
            p0[d]      = __float2half(acc[nt][0] + b0);
            p0[16 + d] = __float2half(acc[nt][1] + b0);
            p0[d + 8]      = __float2half(acc[nt][2] + b8);
            p0[16 + d + 8] = __float2half(acc[nt][3] + b8);
        }
    }
}

// ---------------------------------------------------------------------------
// PAM flash attention: q-tile 64, 128-thread CTA, occ 3, 3-stage K/V pipeline.
// SMEM: Q @0 (3072); K 3x3072 @3072; V 3x18432 @12288.  Total 67584.
// ---------------------------------------------------------------------------
#define ATT_SMEM 67584

__global__ void __launch_bounds__(128, 3) pam_attn_mma(
        const __half* __restrict__ qh, const __half* __restrict__ kh,
        const __half* __restrict__ vd,
        const __half* __restrict__ yhi, const __half* __restrict__ ylo,
        const float* __restrict__ alpha, __half* __restrict__ xp2) {
    extern __shared__ __align__(16) char smc[];
    const uint32_t smb = smem_u32(smc);
    const uint32_t Qb  = smb;
    const uint32_t Kb0 = smb + 3072;
    const uint32_t Vb0 = smb + 12288;

    const int tid = threadIdx.x, lane = tid & 31, wid = tid >> 5;
    const int b = blockIdx.y;
    const int n0 = blockIdx.x * 64;
    const int qbase = wid * 16;

    const int g = lane >> 3, r8 = lane & 7;
    const uint32_t qoff = (uint32_t)(((g & 1) * 8 + r8) * 48 + (g >> 1) * 16);
    const uint32_t koff = (uint32_t)(((g >> 1) * 8 + r8) * 48 + (g & 1) * 16);
    const uint32_t voff = (uint32_t)(((g >> 1) * 8 + r8) * 144 + (g & 1) * 16);

    auto stageKV = [&](int t, int buf) {
        const int k0 = t * 64;
        {
            int row = tid >> 1, h = tid & 1;
            CP_ASYNC16(Kb0 + buf * 3072 + row * 48 + h * 16,
                       kh + ((size_t)b * NPIX + k0 + row) * 16 + h * 8);
        }
#pragma unroll
        for (int t4 = 0; t4 < 8; t4++) {
            int idx = tid + t4 * 128;
            int ch = idx >> 3, c = idx & 7;
            CP_ASYNC16(Vb0 + buf * 18432 + ch * 144 + c * 16,
                       vd + ((size_t)b * 128 + ch) * NPIX + k0 + c * 8);
        }
        CP_COMMIT();
    };

    {
        int row = tid >> 1, h = tid & 1;
        CP_ASYNC16(Qb + row * 48 + h * 16,
                   qh + ((size_t)b * NPIX + n0 + row) * 16 + h * 8);
    }
    stageKV(0, 0);    // group 0 (includes Q)
    stageKV(1, 1);    // group 1

    uint32_t qfr[4];
    float O[16][4];
#pragma unroll
    for (int nc = 0; nc < 16; nc++)
#pragma unroll
        for (int r = 0; r < 4; r++) O[nc][r] = 0.0f;
    float mrun0 = -1e30f, mrun1 = -1e30f, lrun0 = 0.0f, lrun1 = 0.0f;

    for (int t = 0; t < 64; t++) {
        const int buf = t % 3;
        if (t < 63) { CP_WAIT(1); } else { CP_WAIT(0); }
        __syncthreads();
        if (t + 2 < 64) stageKV(t + 2, (t + 2) % 3);
        if (t == 0) ldsm4(qfr, Qb + qbase * 48 + qoff);

        const uint32_t Kb = Kb0 + buf * 3072;
        const uint32_t Vb = Vb0 + buf * 18432;

        float S[8][4];
#pragma unroll
        for (int ks = 0; ks < 4; ks++) {
            uint32_t kb[4];
            ldsm4(kb, Kb + ks * 768 + koff);
#pragma unroll
            for (int r = 0; r < 4; r++) { S[2 * ks][r] = 0.0f; S[2 * ks + 1][r] = 0.0f; }
            mma_f16(S[2 * ks],     qfr, kb[0], kb[1]);
            mma_f16(S[2 * ks + 1], qfr, kb[2], kb[3]);
        }

        float tm0 = -1e30f, tm1 = -1e30f;
#pragma unroll
        for (int nt = 0; nt < 8; nt++) {
            tm0 = fmaxf(tm0, fmaxf(S[nt][0], S[nt][1]));
            tm1 = fmaxf(tm1, fmaxf(S[nt][2], S[nt][3]));
        }
        tm0 = fmaxf(tm0, __shfl_xor_sync(0xffffffffu, tm0, 1));
        tm0 = fmaxf(tm0, __shfl_xor_sync(0xffffffffu, tm0, 2));
        tm1 = fmaxf(tm1, __shfl_xor_sync(0xffffffffu, tm1, 1));
        tm1 = fmaxf(tm1, __shfl_xor_sync(0xffffffffu, tm1, 2));
        const float mn0 = fmaxf(mrun0, tm0), mn1 = fmaxf(mrun1, tm1);
        const float f0 = __expf(mrun0 - mn0), f1 = __expf(mrun1 - mn1);
        mrun0 = mn0; mrun1 = mn1;

        float ts0 = 0.0f, ts1 = 0.0f;
        uint32_t afr[4][4];
#pragma unroll
        for (int j = 0; j < 4; j++) {
            float p00 = __expf(S[2 * j][0] - mn0), p01 = __expf(S[2 * j][1] - mn0);
            float p10 = __expf(S[2 * j][2] - mn1), p11 = __expf(S[2 * j][3] - mn1);
            float q00 = __expf(S[2 * j + 1][0] - mn0), q01 = __expf(S[2 * j + 1][1] - mn0);
            float q10 = __expf(S[2 * j + 1][2] - mn1), q11 = __expf(S[2 * j + 1][3] - mn1);
            ts0 += (p00 + p01) + (q00 + q01);
            ts1 += (p10 + p11) + (q10 + q11);
            afr[j][0] = ph2(p00, p01);
            afr[j][1] = ph2(p10, p11);
            afr[j][2] = ph2(q00, q01);
            afr[j][3] = ph2(q10, q11);
        }
        ts0 += __shfl_xor_sync(0xffffffffu, ts0, 1);
        ts0 += __shfl_xor_sync(0xffffffffu, ts0, 2);
        ts1 += __shfl_xor_sync(0xffffffffu, ts1, 1);
        ts1 += __shfl_xor_sync(0xffffffffu, ts1, 2);
        lrun0 = lrun0 * f0 + ts0;
        lrun1 = lrun1 * f1 + ts1;

#pragma unroll
        for (int nc = 0; nc < 16; nc++) {
            O[nc][0] *= f0; O[nc][1] *= f0;
            O[nc][2] *= f1; O[nc][3] *= f1;
        }

#pragma unroll
        for (int j = 0; j < 4; j++) {
            const uint32_t vb_j = Vb + j * 32 + voff;
#pragma unroll
            for (int p = 0; p < 8; p++) {
                uint32_t vb[4];
                ldsm4(vb, vb_j + p * 2304);
                mma_f16(O[2 * p],     afr[j], vb[0], vb[1]);
                mma_f16(O[2 * p + 1], afr[j], vb[2], vb[3]);
            }
        }
    }

    const float linv0 = 1.0f / lrun0, linv1 = 1.0f / lrun1;
    const float a = alpha[0];
    const int px0 = n0 + qbase + (lane >> 2);
    const int px1 = px0 + 8;
    __half* dst0 = xp2 + (((size_t)b * XP_H + (px0 >> 6) + 1) * XP_H + (px0 & 63) + 1) * CI;
    __half* dst1 = xp2 + (((size_t)b * XP_H + (px1 >> 6) + 1) * XP_H + (px1 & 63) + 1) * CI;
#pragma unroll
    for (int nc = 0; nc < 16; nc++) {
        const int ch = nc * 8 + 2 * (lane & 3);
        const __half* hp = yhi + ((size_t)b * 128 + ch) * NPIX;
        const __half* lp = ylo + ((size_t)b * 128 + ch) * NPIX;
        float ya0 = __half2float(hp[px0]) + __half2float(lp[px0]);
        float yb0 = __half2float(hp[NPIX + px0]) + __half2float(lp[NPIX + px0]);
        float ya1 = __half2float(hp[px1]) + __half2float(lp[px1]);
        float yb1 = __half2float(hp[NPIX + px1]) + __half2float(lp[NPIX + px1]);
        *(uint32_t*)(dst0 + ch) = ph2(fmaf(a, O[nc][0] * linv0, ya0),
                                      fmaf(a, O[nc][1] * linv0, yb0));
        *(uint32_t*)(dst1 + ch) = ph2(fmaf(a, O[nc][2] * linv1, ya1),
                                      fmaf(a, O[nc][3] * linv1, yb1));
    }
}

// ---------------------------------------------------------------------------
// CAM gram matrix via fp16 hi/lo split MMA, split-K partials.
// ---------------------------------------------------------------------------
#define CAME_SMEM 36864

__global__ void __launch_bounds__(256, 2) cam_energy_mma(
        const __half* __restrict__ yhi, const __half* __restrict__ ylo,
        float* __restrict__ epart) {
    extern __shared__ __align__(16) char smc[];
    const uint32_t smb = smem_u32(smc);
    const int tid = threadIdx.x, lane = tid & 31, wid = tid >> 5;
    const int warp_m = wid >> 2, warp_n = wid & 3;
    const int b = blockIdx.y, ksid = blockIdx.x;
    const int g = lane >> 3, r8 = lane & 7;

    float acc[4][4][4];
#pragma unroll
    for (int mt = 0; mt < 4; mt++)
#pragma unroll
        for (int nt = 0; nt < 4; nt++)
#pragma unroll
            for (int r = 0; r < 4; r++) acc[mt][nt][r] = 0.0f;

    for (int chunk = 0; chunk < 4; chunk++) {
        const int k0 = ksid * 256 + chunk * 64;
        __syncthreads();
#pragma unroll
        for (int t = 0; t < 4; t++) {
            int idx = tid + t * 256;
            int ch = idx >> 3, seg = idx & 7;
            CP_ASYNC16(smb + ch * 144 + seg * 16,
                       yhi + ((size_t)b * 128 + ch) * NPIX + k0 + seg * 8);
            CP_ASYNC16(smb + 18432 + ch * 144 + seg * 16,
                       ylo + ((size_t)b * 128 + ch) * NPIX + k0 + seg * 8);
        }
        CP_COMMIT();
        CP_WAIT(0);
        __syncthreads();

#pragma unroll
        for (int ks = 0; ks < 4; ks++) {
            uint32_t ahi[4][4], alo[4][4];
#pragma unroll
            for (int mt = 0; mt < 4; mt++) {
                const uint32_t arow = (warp_m * 64 + mt * 16 + (g & 1) * 8 + r8) * 144
                                      + ks * 32 + (g >> 1) * 16;
                ldsm4(ahi[mt], smb + arow);
                ldsm4(alo[mt], smb + 18432 + arow);
            }
            uint32_t bhi[2][4], blo[2][4];
#pragma unroll
            for (int t16 = 0; t16 < 2; t16++) {
                const uint32_t brow = (warp_n * 32 + t16 * 16 + (g >> 1) * 8 + r8) * 144
                                      + ks * 32 + (g & 1) * 16;
                ldsm4(bhi[t16], smb + brow);
                ldsm4(blo[t16], smb + 18432 + brow);
            }
#pragma unroll
            for (int mt = 0; mt < 4; mt++)
#pragma unroll
                for (int t16 = 0; t16 < 2; t16++) {
                    mma_f16(acc[mt][2 * t16],     ahi[mt], bhi[t16][0], bhi[t16][1]);
                    mma_f16(acc[mt][2 * t16 + 1], ahi[mt], bhi[t16][2], bhi[t16][3]);
                    mma_f16(acc[mt][2 * t16],     ahi[mt], blo[t16][0], blo[t16][1]);
                    mma_f16(acc[mt][2 * t16 + 1], ahi[mt], blo[t16][2], blo[t16][3]);
                    mma_f16(acc[mt][2 * t16],     alo[mt], bhi[t16][0], bhi[t16][1]);
                    mma_f16(acc[mt][2 * t16 + 1], alo[mt], bhi[t16][2], bhi[t16][3]);
                }
        }
    }

    float* ep = epart + (((size_t)ksid * BATCH + b) * 128) * 128;
#pragma unroll
    for (int mt = 0; mt < 4; mt++) {
        const int c0 = warp_m * 64 + mt * 16 + (lane >> 2);
#pragma unroll
        for (int nt = 0; nt < 4; nt++) {
            const int d = warp_n * 32 + nt * 8 + 2 * (lane & 3);
            *(float2*)(ep + (size_t)c0 * 128 + d) = make_float2(acc[mt][nt][0], acc[mt][nt][1]);
            *(float2*)(ep + (size_t)(c0 + 8) * 128 + d) = make_float2(acc[mt][nt][2], acc[mt][nt][3]);
        }
    }
}

// ---------------------------------------------------------------------------
// CAM softmax of (rowmax - E), reducing the KSPLIT partials -> fp16 attn
// ---------------------------------------------------------------------------
__global__ void cam_softmax_kernel(const float* __restrict__ epart,
                                   __half* __restrict__ attn) {
    const int row = blockIdx.x;
    const int tid = threadIdx.x;
    __shared__ float red[4];

    float e = 0.0f;
#pragma unroll
    for (int s = 0; s < KSPLIT; s++)
        e += epart[((size_t)s * 1024 + row) * 128 + tid];

    float m = e;
#pragma unroll
    for (int off = 16; off; off >>= 1) m = fmaxf(m, __shfl_xor_sync(0xffffffff, m, off));
    if ((tid & 31) == 0) red[tid >> 5] = m;
    __syncthreads();
    float mx = fmaxf(fmaxf(red[0], red[1]), fmaxf(red[2], red[3]));
    float e2 = mx - e;
    __syncthreads();

    float m2 = e2;
#pragma unroll
    for (int off = 16; off; off >>= 1) m2 = fmaxf(m2, __shfl_xor_sync(0xffffffff, m2, off));
    if ((tid & 31) == 0) red[tid >> 5] = m2;
    __syncthreads();
    m2 = fmaxf(fmaxf(red[0], red[1]), fmaxf(red[2], red[3]));
    float p = __expf(e2 - m2);
    __syncthreads();

    float s = p;
#pragma unroll
    for (int off = 16; off; off >>= 1) s += __shfl_xor_sync(0xffffffff, s, off);
    if ((tid & 31) == 0) red[tid >> 5] = s;
    __syncthreads();
    s = red[0] + red[1] + red[2] + red[3];

    attn[(size_t)row * 128 + tid] = __float2half(p / s);
}

// ---------------------------------------------------------------------------
// CAM feature via fp16 MMA -> fp16 padded NHWC; residual from hi+lo.
// ---------------------------------------------------------------------------
#define CAMF_SMEM 53248

__global__ void __launch_bounds__(256, 1) cam_feat_mma(
        const __half* __restrict__ attn16,
        const __half* __restrict__ yhi, const __half* __restrict__ ylo,
        const float* __restrict__ beta, __half* __restrict__ xp2) {
    extern __shared__ __align__(16) char smc[];
    const uint32_t smb = smem_u32(smc);
    const int tid = threadIdx.x, lane = tid & 31, wid = tid >> 5;
    const int b = blockIdx.y;
    const int n0 = blockIdx.x * 64;
    const int g = lane >> 3;

#pragma unroll
    for (int t = 0; t < 8; t++) {
        int idx = tid + t * 256;
        int c = idx >> 4, seg = idx & 15;
        CP_ASYNC16(smb + c * 272 + seg * 16,
                   attn16 + ((size_t)b * 128 + c) * 128 + seg * 8);
    }
#pragma unroll
    for (int t = 0; t < 4; t++) {
        int idx = tid + t * 256;
        int ch = idx >> 3, seg = idx & 7;
        CP_ASYNC16(smb + 34816 + ch * 144 + seg * 16,
                   yhi + ((size_t)b * 128 + ch) * NPIX + n0 + seg * 8);
    }
    CP_COMMIT();
    CP_WAIT(0);
    __syncthreads();

    const int mt = wid;
    float acc[8][4];
#pragma unroll
    for (int nt = 0; nt < 8; nt++)
#pragma unroll
        for (int r = 0; r < 4; r++) acc[nt][r] = 0.0f;

    const uint32_t Bsm = smb + 34816;
#pragma unroll
    for (int ks = 0; ks < 8; ks++) {
        uint32_t afr[4];
        ldsm4(afr, smb + (mt * 16 + (g & 1) * 8 + (lane & 7)) * 272
                  + ks * 32 + (g >> 1) * 16);
#pragma unroll
        for (int t16 = 0; t16 < 4; t16++) {
            uint32_t bfr[4];
            ldsm4t(bfr, Bsm + (ks * 16 + (g & 1) * 8 + (lane & 7)) * 144
                       + (t16 * 16 + (g >> 1) * 8) * 2);
            mma_f16(acc[2 * t16],     afr, bfr[0], bfr[1]);
            mma_f16(acc[2 * t16 + 1], afr, bfr[2], bfr[3]);
        }
    }

    const float bet = beta[0];
    const int c0 = mt * 16 + (lane >> 2);
#pragma unroll
    for (int nt = 0; nt < 8; nt++) {
        const int n = n0 + nt * 8 + 2 * (lane & 3);
        const __half* h0p = yhi + ((size_t)b * 128 + c0) * NPIX;
        const __half* l0p = ylo + ((size_t)b * 128 + c0) * NPIX;
        float y00 = __half2float(h0p[n]) + __half2float(l0p[n]);
        float y01 = __half2float(h0p[n + 1]) + __half2float(l0p[n + 1]);
        float y80 = __half2float(h0p[8 * NPIX + n]) + __half2float(l0p[8 * NPIX + n]);
        float y81 = __half2float(h0p[8 * NPIX + n + 1]) + __half2float(l0p[8 * NPIX + n + 1]);
        __half* p0 = xp2 + (((size_t)b * XP_H + (n >> 6) + 1) * XP_H + (n & 63) + 1) * CI;
        __half* p1 = p0 + CI;
        p0[c0]     = __float2half(fmaf(bet, acc[nt][0], y00));
        p1[c0]     = __float2half(fmaf(bet, acc[nt][1], y01));
        p0[c0 + 8] = __float2half(fmaf(bet, acc[nt][2], y80));
        p1[c0 + 8] = __float2half(fmaf(bet, acc[nt][3], y81));
    }
}

// ---------------------------------------------------------------------------
// Final heads via one fused fp16 MMA:  A[64x256] @ [fp;fc](256 x 64px tile).
// ---------------------------------------------------------------------------
#define FIN_SMEM 69632

__global__ void __launch_bounds__(128, 2) final_mma(
        const __half* __restrict__ wfin,
        const __half* __restrict__ fp, const __half* __restrict__ fc,
        const float* __restrict__ bout, const float* __restrict__ bp3,
        const float* __restrict__ bc3, float* __restrict__ out) {
    extern __shared__ __align__(16) char smc[];
    const uint32_t smb = smem_u32(smc);
    const int tid = threadIdx.x, lane = tid & 31, wid = tid >> 5;
    const int b = blockIdx.y;
    const int n0 = blockIdx.x * 64;
    const int g = lane >> 3;

#pragma unroll
    for (int t = 0; t < 16; t++) {
        int i = tid + t * 128;
        CP_ASYNC16(smb + i * 16, wfin + i * 8);
    }
#pragma unroll
    for (int t = 0; t < 16; t++) {
        int idx = tid + t * 128;
        int ch = idx >> 3, seg = idx & 7;
        const __half* src = (ch < 128)
            ? fp + ((size_t)b * 128 + ch) * NPIX + n0 + seg * 8
            : fc + ((size_t)b * 128 + (ch - 128)) * NPIX + n0 + seg * 8;
        CP_ASYNC16(smb + 32768 + ch * 144 + seg * 16, src);
    }
    CP_COMMIT();
    CP_WAIT(0);
    __syncthreads();

    const int mt = wid;
    float acc[8][4];
#pragma unroll
    for (int nt = 0; nt < 8; nt++)
#pragma unroll
        for (int r = 0; r < 4; r++) acc[nt][r] = 0.0f;

    const char* Aptr = smc;
    const uint32_t Bsm = smb + 32768;
#pragma unroll
    for (int ks = 0; ks < 16; ks++) {
        uint4 v = *(const uint4*)(Aptr + (((mt * 16 + ks) * 32 + lane) << 4));
        uint32_t afr[4] = {v.x, v.y, v.z, v.w};
#pragma unroll
        for (int t16 = 0; t16 < 4; t16++) {
            uint32_t bfr[4];
            ldsm4t(bfr, Bsm + (ks * 16 + (g & 1) * 8 + (lane & 7)) * 144
                       + (t16 * 16 + (g >> 1) * 8) * 2);
            mma_f16(acc[2 * t16],     afr, bfr[0], bfr[1]);
            mma_f16(acc[2 * t16 + 1], afr, bfr[2], bfr[3]);
        }
    }

    const size_t SEG = (size_t)BATCH * NC * NPIX;
    auto emit = [&](int row, int px, float v) {
        if (row >= 57) return;
        float bias;
        size_t base;
        if (row < 19)      { bias = bout[row]; base = ((size_t)b * NC + row) * NPIX; }
        else if (row < 38) { bias = bp3[row - 19]; base = SEG + ((size_t)b * NC + row - 19) * NPIX; }
        else               { bias = bc3[row - 38]; base = 2 * SEG + ((size_t)b * NC + row - 38) * NPIX; }
        out[base + px] = sigmoidf_(v + bias);
    };

    const int r0 = mt * 16 + (lane >> 2);
#pragma unroll
    for (int nt = 0; nt < 8; nt++) {
        const int px = n0 + nt * 8 + 2 * (lane & 3);
        emit(r0,     px,     acc[nt][0]);
        emit(r0,     px + 1, acc[nt][1]);
        emit(r0 + 8, px,     acc[nt][2]);
        emit(r0 + 8, px + 1, acc[nt][3]);
    }
}

// ---------------------------------------------------------------------------
// Streams / events (created once at program load)
// ---------------------------------------------------------------------------
namespace {
struct StreamInit {
    cudaStream_t s1;
    cudaEvent_t e0, e1, e2, e3, e4, e5;
    StreamInit() {
        cudaStreamCreateWithFlags(&s1, cudaStreamNonBlocking);
        cudaEventCreateWithFlags(&e0, cudaEventDisableTiming);
        cudaEventCreateWithFlags(&e1, cudaEventDisableTiming);
        cudaEventCreateWithFlags(&e2, cudaEventDisableTiming);
        cudaEventCreateWithFlags(&e3, cudaEventDisableTiming);
        cudaEventCreateWithFlags(&e4, cudaEventDisableTiming);
        cudaEventCreateWithFlags(&e5, cudaEventDisableTiming);
    }
};
StreamInit g_str;
}

// ---------------------------------------------------------------------------
// Launch
// ---------------------------------------------------------------------------
extern "C" void kernel_launch(void* const* d_in, const int* in_sizes, int n_in,
                              void* d_out, int out_size) {
    const float* x    = (const float*)d_in[0];
    const float* Wp1  = (const float*)d_in[1];
    const float* bnp1 = (const float*)d_in[2];
    const float* Wc1  = (const float*)d_in[3];
    const float* bnc1 = (const float*)d_in[4];
    const float* Wb   = (const float*)d_in[5];
    const float* bb   = (const float*)d_in[6];
    const float* Wc   = (const float*)d_in[7];
    const float* bc   = (const float*)d_in[8];
    const float* Wd   = (const float*)d_in[9];
    const float* bd   = (const float*)d_in[10];
    const float* alpha= (const float*)d_in[11];
    const float* beta = (const float*)d_in[12];
    const float* Wp2  = (const float*)d_in[13];
    const float* bnp2 = (const float*)d_in[14];
    const float* Wc2  = (const float*)d_in[15];
    const float* bnc2 = (const float*)d_in[16];
    const float* Wout = (const float*)d_in[17];
    const float* bout = (const float*)d_in[18];
    const float* Wp3  = (const float*)d_in[19];
    const float* bp3  = (const float*)d_in[20];
    const float* Wc3  = (const float*)d_in[21];
    const float* bc3  = (const float*)d_in[22];
    float* out = (float*)d_out;

    float* epart;
    __half *featp1h, *featp1lo, *featc1h, *featc1lo, *qh, *kh, *vd, *attn16;
    __half *xpad, *xp2a, *xp2b, *wf1, *wf2, *wqkv, *wfin;
    cudaGetSymbolAddress((void**)&featp1h,  g_featp1h);
    cudaGetSymbolAddress((void**)&featp1lo, g_featp1lo);
    cudaGetSymbolAddress((void**)&featc1h,  g_featc1h);
    cudaGetSymbolAddress((void**)&featc1lo, g_featc1lo);
    cudaGetSymbolAddress((void**)&qh,       g_qh);
    cudaGetSymbolAddress((void**)&kh,       g_kh);
    cudaGetSymbolAddress((void**)&vd,       g_vd);
    cudaGetSymbolAddress((void**)&epart,    g_epart);
    cudaGetSymbolAddress((void**)&attn16,   g_attn16);
    cudaGetSymbolAddress((void**)&xpad,     g_xpad);
    cudaGetSymbolAddress((void**)&xp2a,     g_xp2a);
    cudaGetSymbolAddress((void**)&xp2b,     g_xp2b);
    cudaGetSymbolAddress((void**)&wf1,      g_wf16_1);
    cudaGetSymbolAddress((void**)&wf2,      g_wf16_2);
    cudaGetSymbolAddress((void**)&wqkv,     g_wqkv);
    cudaGetSymbolAddress((void**)&wfin,     g_wfinal);

    cudaFuncSetAttribute(conv_mma_kernel<512>,
                         cudaFuncAttributeMaxDynamicSharedMemorySize, CONV_SMEM);
    cudaFuncSetAttribute(conv_mma_kernel<128>,
                         cudaFuncAttributeMaxDynamicSharedMemorySize, CONV_SMEM);
    cudaFuncSetAttribute(pam_attn_mma,
                         cudaFuncAttributeMaxDynamicSharedMemorySize, ATT_SMEM);
    cudaFuncSetAttribute(pam_attn_mma,
                         cudaFuncAttributePreferredSharedMemoryCarveout, 100);
    cudaFuncSetAttribute(qkv_kernel,
                         cudaFuncAttributeMaxDynamicSharedMemorySize, QKV_SMEM);
    cudaFuncSetAttribute(cam_energy_mma,
                         cudaFuncAttributeMaxDynamicSharedMemorySize, CAME_SMEM);
    cudaFuncSetAttribute(cam_feat_mma,
                         cudaFuncAttributeMaxDynamicSharedMemorySize, CAMF_SMEM);
    cudaFuncSetAttribute(final_mma,
                         cudaFuncAttributeMaxDynamicSharedMemorySize, FIN_SMEM);

    cudaStream_t s1 = g_str.s1;

    // Fork s1 off the main stream
    cudaEventRecord(g_str.e0, 0);
    cudaStreamWaitEvent(s1, g_str.e0, 0);

    // s0: interior packing
    pack_x_kernel<<<dim3(64, BATCH), 256>>>(x, xpad);
    cudaEventRecord(g_str.e5, 0);   // pack_x done

    // s1: consolidated borders + weight packing (parallel with pack_x)
    zero_borders_all<<<dim3(XP_H, BATCH, 3), 256, 0, s1>>>(xpad, xp2a, xp2b);
    pack_w16<<<dim3(144, 2), 256, 0, s1>>>(Wp1, Wc1, wf1, CIN);
    cudaEventRecord(g_str.e1, s1);  // borders + wf1 ready
    pack_small<<<144, 256, 0, s1>>>(Wd, Wb, Wc, wqkv, Wout, Wp3, Wc3, wfin);
    pack_w16<<<dim3(36, 2), 256, 0, s1>>>(Wp2, Wc2, wf2, CI);
    cudaEventRecord(g_str.e4, s1);  // wqkv/wfinal/wf2 ready

    // s0: conv1-PAM FIRST (alone at full chip rate)
    cudaStreamWaitEvent(0, g_str.e1, 0);
    conv_mma_kernel<512><<<dim3(32, BATCH, 1), 256, CONV_SMEM>>>(
        xpad, xpad, wf1, bnp1, bnp1, featp1h, featp1h, featp1lo, featp1lo);
    cudaEventRecord(g_str.e2, 0);   // conv1-PAM done

    // s1: conv1-CAM + entire CAM chain (concurrent with PAM chain on s0)
    cudaStreamWaitEvent(s1, g_str.e2, 0);
    cudaStreamWaitEvent(s1, g_str.e5, 0);
    conv_mma_kernel<512><<<dim3(32, BATCH, 1), 256, CONV_SMEM, s1>>>(
        xpad, xpad, wf1 + 144 * 4096, bnc1, bnc1, featc1h, featc1h, featc1lo, featc1lo);
    cam_energy_mma<<<dim3(KSPLIT, BATCH), 256, CAME_SMEM, s1>>>(featc1h, featc1lo, epart);
    cam_softmax_kernel<<<BATCH * 128, 128, 0, s1>>>(epart, attn16);
    cam_feat_mma<<<dim3(64, BATCH), 256, CAMF_SMEM, s1>>>(
        attn16, featc1h, featc1lo, beta, xp2b);
    conv_mma_kernel<128><<<dim3(32, BATCH, 1), 256, CONV_SMEM, s1>>>(
        xp2b, xp2b, wf2 + 36 * 4096, bnc2, bnc2, featc1h, featc1h, nullptr, nullptr);
    cudaEventRecord(g_str.e3, s1);  // CAM branch fully done

    // s0: PAM chain (qkv needs wqkv -> wait e4)
    cudaStreamWaitEvent(0, g_str.e4, 0);
    qkv_kernel<<<dim3(64, BATCH), 320, QKV_SMEM>>>(
        wqkv, featp1h, bd, bb, bc, vd, qh, kh);
    pam_attn_mma<<<dim3(64, BATCH), 128, ATT_SMEM>>>(
        qh, kh, vd, featp1h, featp1lo, alpha, xp2a);
    conv_mma_kernel<128><<<dim3(32, BATCH, 1), 256, CONV_SMEM>>>(
        xp2a, xp2a, wf2, bnp2, bnp2, featp1h, featp1h, nullptr, nullptr);

    // Join, then fused final heads
    cudaStreamWaitEvent(0, g_str.e3, 0);
    final_mma<<<dim3(64, BATCH), 128, FIN_SMEM>>>(
        wfin, featp1h, featc1h, bout, bp3, bc3, out);
}

// round 14
// speedup vs baseline: 1.0127x; 1.0127x over previous
#include <cuda_runtime.h>
#include <cuda_bf16.h>
#include <cuda_fp16.h>
#include <math.h>
#include <cstdint>

// ---------------------------------------------------------------------------
// Problem constants
// ---------------------------------------------------------------------------
#define BATCH 8
#define CIN   512
#define CI    128
#define CK    16
#define NC    19
#define NPIX  4096
#define FEAT_ELEMS (BATCH * CI * NPIX)
#define XP_H 66
#define KSPLIT 16

// ---------------------------------------------------------------------------
// Scratch (device globals)
// ---------------------------------------------------------------------------
__device__ __half g_featp1h[FEAT_ELEMS];
__device__ __half g_featp1lo[FEAT_ELEMS];
__device__ __half g_featc1h[FEAT_ELEMS];
__device__ __half g_featc1lo[FEAT_ELEMS];
__device__ __half g_qh[BATCH * NPIX * CK];
__device__ __half g_kh[BATCH * NPIX * CK];
__device__ __half g_vd[FEAT_ELEMS];
__device__ float  g_epart[KSPLIT * BATCH * CI * CI];
__device__ __half g_attn16[BATCH * CI * CI];
__device__ __half g_xpad[BATCH * XP_H * XP_H * CIN];
__device__ __half g_xp2a[BATCH * XP_H * XP_H * CI];
__device__ __half g_xp2b[BATCH * XP_H * XP_H * CI];
__device__ __half g_wf16_1[2 * 144 * 4096];
__device__ __half g_wf16_2[2 * 36 * 4096];
__device__ __half g_wqkv[10 * 8 * 32 * 8];
__device__ __half g_wfinal[4 * 16 * 32 * 8];

__device__ __forceinline__ float sigmoidf_(float x) {
    return 1.0f / (1.0f + __expf(-x));
}
__device__ __forceinline__ uint32_t smem_u32(const void* p) {
    uint32_t a;
    asm("{ .reg .u64 t; cvta.to.shared.u64 t, %1; cvt.u32.u64 %0, t; }" : "=r"(a) : "l"(p));
    return a;
}
__device__ __forceinline__ void mma_f16(float c[4], const uint32_t a[4], const uint32_t b0, const uint32_t b1) {
    asm volatile(
        "mma.sync.aligned.m16n8k16.row.col.f32.f16.f16.f32 "
        "{%0,%1,%2,%3}, {%4,%5,%6,%7}, {%8,%9}, {%0,%1,%2,%3};"
        : "+f"(c[0]), "+f"(c[1]), "+f"(c[2]), "+f"(c[3])
        : "r"(a[0]), "r"(a[1]), "r"(a[2]), "r"(a[3]), "r"(b0), "r"(b1));
}
__device__ __forceinline__ void ldsm4(uint32_t r[4], uint32_t addr) {
    asm volatile("ldmatrix.sync.aligned.m8n8.x4.shared.b16 {%0,%1,%2,%3}, [%4];"
                 : "=r"(r[0]), "=r"(r[1]), "=r"(r[2]), "=r"(r[3]) : "r"(addr));
}
__device__ __forceinline__ void ldsm4t(uint32_t r[4], uint32_t addr) {
    asm volatile("ldmatrix.sync.aligned.m8n8.x4.trans.shared.b16 {%0,%1,%2,%3}, [%4];"
                 : "=r"(r[0]), "=r"(r[1]), "=r"(r[2]), "=r"(r[3]) : "r"(addr));
}
#define CP_ASYNC16(dst, src) \
    asm volatile("cp.async.ca.shared.global [%0], [%1], 16;" :: "r"(dst), "l"(src))
#define CP_COMMIT() asm volatile("cp.async.commit_group;")
#define CP_WAIT(N)  asm volatile("cp.async.wait_group %0;" :: "n"(N))

__device__ __forceinline__ uint32_t ph2(float x, float y) {
    __half2 h = __floats2half2_rn(x, y);
    return *(uint32_t*)&h;
}

// ---------------------------------------------------------------------------
// Pack x: f32 NCHW -> fp16 NHWC padded
// ---------------------------------------------------------------------------
__global__ void pack_x_kernel(const float* __restrict__ x, __half* __restrict__ xp) {
    const int h = blockIdx.x, b = blockIdx.y, tid = threadIdx.x;
    __shared__ float s[32][65];
    for (int ci0 = 0; ci0 < CIN; ci0 += 32) {
        for (int idx = tid; idx < 32 * 64; idx += 256) {
            int ci_l = idx >> 6, w = idx & 63;
            s[ci_l][w] = x[(((size_t)b * CIN + ci0 + ci_l) * 64 + h) * 64 + w];
        }
        __syncthreads();
        for (int idx = tid; idx < 64 * 32; idx += 256) {
            int w = idx >> 5, ci_l = idx & 31;
            xp[(((size_t)b * XP_H + h + 1) * XP_H + w + 1) * CIN + ci0 + ci_l] =
                __float2half(s[ci_l][w]);
        }
        __syncthreads();
    }
}

// One launch zeroes the borders of all three padded buffers (z selects).
__global__ void zero_borders_all(__half* __restrict__ xpad,
                                 __half* __restrict__ xp2a,
                                 __half* __restrict__ xp2b) {
    const int hp = blockIdx.x, b = blockIdx.y, z = blockIdx.z, tid = threadIdx.x;
    __half* base = (z == 0) ? xpad : (z == 1 ? xp2a : xp2b);
    const int C = (z == 0) ? CIN : CI;
    __half* row = base + ((size_t)b * XP_H + hp) * XP_H * C;
    const __half zz = __float2half(0.0f);
    if (hp == 0 || hp == XP_H - 1) {
        for (int idx = tid; idx < XP_H * C; idx += 256) row[idx] = zz;
    } else {
        for (int idx = tid; idx < C; idx += 256) {
            row[idx] = zz;
            row[(size_t)(XP_H - 1) * C + idx] = zz;
        }
    }
}

// ---------------------------------------------------------------------------
// Pack conv weights into m16n8k16 fp16 A-fragment order.
// ---------------------------------------------------------------------------
__global__ void pack_w16(const float* __restrict__ W0, const float* __restrict__ W1,
                         __half* __restrict__ wf, int CIN_T) {
    const int cpc = CIN_T / 32;
    const int chunk = blockIdx.x;
    const int kwh = chunk / cpc, cb = chunk % cpc;
    const float* W = blockIdx.y ? W1 : W0;
    __half* dst = wf + ((size_t)blockIdx.y * gridDim.x + chunk) * 4096;
    for (int t = 0; t < 16; t++) {
        int idx = threadIdx.x + t * 256;
        int j = idx & 7, lane = (idx >> 3) & 31, ks = (idx >> 8) & 1, mt = idx >> 9;
        int reg = j >> 1, h = j & 1;
        int co = mt * 16 + (lane >> 2) + (reg & 1) * 8;
        int ci = cb * 32 + ks * 16 + (lane & 3) * 2 + (reg >> 1) * 8 + h;
        dst[idx] = __float2half(W[((size_t)co * CIN_T + ci) * 9 + kwh]);
    }
}

// Parallel small-table pack: 144 CTAs x 256, 1 element/thread.
__global__ void pack_small(const float* __restrict__ Wd, const float* __restrict__ Wb,
                           const float* __restrict__ Wc, __half* __restrict__ dqkv,
                           const float* __restrict__ Wout, const float* __restrict__ Wp3,
                           const float* __restrict__ Wc3, __half* __restrict__ dfin) {
    int gi = blockIdx.x * 256 + threadIdx.x;
    if (gi < 20480) {
        int idx = gi;
        int j = idx & 7, lane = (idx >> 3) & 31, ks = (idx >> 8) & 7, mt = idx >> 11;
        int reg = j >> 1, h = j & 1;
        int row = mt * 16 + (lane >> 2) + (reg & 1) * 8;
        int col = ks * 16 + (lane & 3) * 2 + (reg >> 1) * 8 + h;
        float w;
        if (row < 128)      w = Wd[row * 128 + col];
        else if (row < 144) w = Wb[(row - 128) * 128 + col];
        else                w = Wc[(row - 144) * 128 + col];
        dqkv[idx] = __float2half(w);
    } else if (gi < 36864) {
        int idx = gi - 20480;
        int j = idx & 7, lane = (idx >> 3) & 31, ks = (idx >> 8) & 15, mt = idx >> 12;
        int reg = j >> 1, h = j & 1;
        int row = mt * 16 + (lane >> 2) + (reg & 1) * 8;
        int col = ks * 16 + (lane & 3) * 2 + (reg >> 1) * 8 + h;
        float w = 0.0f;
        if (col < 128) {
            if (row < 19)      w = Wout[row * 128 + col];
            else if (row < 38) w = Wp3[(row - 19) * 128 + col];
        } else {
            int c = col - 128;
            if (row < 19)      w = Wout[row * 128 + c];
            else if (row >= 38 && row < 57) w = Wc3[(row - 38) * 128 + c];
        }
        dfin[idx] = __float2half(w);
    }
}

// ---------------------------------------------------------------------------
// conv3x3 implicit GEMM, fp16 m16n8k16, halo-reuse B staging, fused BN+ReLU.
// ---------------------------------------------------------------------------
#define CONV_SMEM 91392
#define BPX 80

template<int CIN_T>
__global__ void __launch_bounds__(256, 2) conv_mma_kernel(
        const __half* __restrict__ xpA, const __half* __restrict__ xpB,
        const __half* __restrict__ wfrag,
        const float* __restrict__ bn0, const float* __restrict__ bn1,
        __half* __restrict__ o16_0, __half* __restrict__ o16_1,
        __half* __restrict__ olo_0, __half* __restrict__ olo_1) {
    constexpr int CPC = CIN_T / 32;
    constexpr int NS = CPC * 3;
    extern __shared__ __align__(16) char smc[];
    const uint32_t smb = smem_u32(smc);
    const uint32_t Boff = smb;
    const uint32_t Aoff = smb + 2 * 21120;

    const int tid = threadIdx.x, lane = tid & 31, wid = tid >> 5;
    const int warp_m = wid >> 2, warp_n = wid & 3;
    const int b = blockIdx.y, z = blockIdx.z;
    const int pxbase = blockIdx.x * 128;
    const int h0 = pxbase >> 6;
    const __half* xp = z ? xpB : xpA;
    const __half* Wf = wfrag + (size_t)z * (9 * CPC) * 4096;
    const float* bn = z ? bn1 : bn0;
    __half* o16 = z ? o16_1 : o16_0;
    __half* olo = z ? olo_1 : olo_0;
    const int g = lane >> 3;

    float acc[4][4][4];
#pragma unroll
    for (int mt = 0; mt < 4; mt++)
#pragma unroll
        for (int nt = 0; nt < 4; nt++)
#pragma unroll
            for (int r = 0; r < 4; r++) acc[mt][nt][r] = 0.0f;

    auto stageA = [&](int s, int buf) {
        const int cb = s / 3, kh = s % 3;
        const uint32_t Ad = Aoff + buf * 24576;
#pragma unroll
        for (int kw = 0; kw < 3; kw++) {
            const __half* src = Wf + (size_t)((kh * 3 + kw) * CPC + cb) * 4096;
#pragma unroll
            for (int t = 0; t < 2; t++) {
                int idx = tid + t * 256;
                CP_ASYNC16(Ad + kw * 8192 + idx * 16, src + idx * 8);
            }
        }
    };
    auto stageB = [&](int cb, int buf) {
        const uint32_t Bd = Boff + buf * 21120;
        const __half* base = xp + ((size_t)(b * XP_H + h0) * XP_H) * CIN_T + cb * 32;
        for (int idx = tid; idx < 1056; idx += 256) {
            int r = idx / 264, rem = idx % 264;
            int c = rem >> 2, q = rem & 3;
            CP_ASYNC16(Bd + (r * 66 + c) * BPX + q * 16,
                       base + ((size_t)r * XP_H + c) * CIN_T + q * 8);
        }
    };

    stageB(0, 0);
    stageA(0, 0);
    CP_COMMIT();

    for (int s = 0; s < NS; s++) {
        const int cb = s / 3, kh = s % 3;
        if (s + 1 < NS) {
            stageA(s + 1, (s + 1) & 1);
            if ((s + 1) % 3 == 0) stageB((s + 1) / 3, ((s + 1) / 3) & 1);
            CP_COMMIT();
            CP_WAIT(1);
        } else {
            CP_WAIT(0);
        }
        __syncthreads();

        const uint32_t Bh = Boff + (cb & 1) * 21120;
        const char* Ap = smc + 2 * 21120 + (s & 1) * 24576;
#pragma unroll
        for (int ks = 0; ks < 2; ks++) {
#pragma unroll
            for (int kw = 0; kw < 3; kw++) {
                uint32_t afr[4][4];
#pragma unroll
                for (int mt = 0; mt < 4; mt++) {
                    uint4 v = *(const uint4*)(Ap + kw * 8192 +
                        ((((warp_m * 4 + mt) * 2 + ks) * 32 + lane) << 4));
                    afr[mt][0] = v.x; afr[mt][1] = v.y; afr[mt][2] = v.z; afr[mt][3] = v.w;
                }
                uint32_t bfr[2][4];
#pragma unroll
                for (int t16 = 0; t16 < 2; t16++) {
                    const int n_row = warp_n * 32 + t16 * 16 + (g >> 1) * 8 + (lane & 7);
                    const int r = n_row >> 6, w = n_row & 63;
                    ldsm4(bfr[t16], Bh + ((r + kh) * 66 + w + kw) * BPX
                                      + ks * 32 + (g & 1) * 16);
                }
#pragma unroll
                for (int mt = 0; mt < 4; mt++)
#pragma unroll
                    for (int t16 = 0; t16 < 2; t16++) {
                        mma_f16(acc[mt][2 * t16],     afr[mt], bfr[t16][0], bfr[t16][1]);
                        mma_f16(acc[mt][2 * t16 + 1], afr[mt], bfr[t16][2], bfr[t16][3]);
                    }
            }
        }
        __syncthreads();
    }

#pragma unroll
    for (int mt = 0; mt < 4; mt++) {
        const int co = warp_m * 64 + mt * 16 + (lane >> 2);
        const float sc0 = bn[co],     sh0 = bn[128 + co];
        const float sc8 = bn[co + 8], sh8 = bn[136 + co];
#pragma unroll
        for (int nt = 0; nt < 4; nt++) {
            const int px = pxbase + warp_n * 32 + nt * 8 + 2 * (lane & 3);
            float v0x = fmaxf(acc[mt][nt][0] * sc0 + sh0, 0.0f);
            float v0y = fmaxf(acc[mt][nt][1] * sc0 + sh0, 0.0f);
            float v1x = fmaxf(acc[mt][nt][2] * sc8 + sh8, 0.0f);
            float v1y = fmaxf(acc[mt][nt][3] * sc8 + sh8, 0.0f);
            *(uint32_t*)(o16 + ((size_t)b * 128 + co) * NPIX + px) = ph2(v0x, v0y);
            *(uint32_t*)(o16 + ((size_t)b * 128 + co + 8) * NPIX + px) = ph2(v1x, v1y);
            if (olo) {
                float r0x = v0x - __half2float(__float2half(v0x));
                float r0y = v0y - __half2float(__float2half(v0y));
                float r1x = v1x - __half2float(__float2half(v1x));
                float r1y = v1y - __half2float(__float2half(v1y));
                *(uint32_t*)(olo + ((size_t)b * 128 + co) * NPIX + px) = ph2(r0x, r0y);
                *(uint32_t*)(olo + ((size_t)b * 128 + co + 8) * NPIX + px) = ph2(r1x, r1y);
            }
        }
    }
}

// ---------------------------------------------------------------------------
// QKV GEMM: [Wd;Wb;Wc](160x128) @ y16(128x4096) + bias.
// ---------------------------------------------------------------------------
#define QKV_SMEM 59392

__global__ void __launch_bounds__(320, 1) qkv_kernel(
        const __half* __restrict__ wq, const __half* __restrict__ y16,
        const float* __restrict__ bd, const float* __restrict__ bb,
        const float* __restrict__ bc,
        __half* __restrict__ vh, __half* __restrict__ qh, __half* __restrict__ kh) {
    extern __shared__ __align__(16) char smc[];
    const uint32_t smb = smem_u32(smc);
    const int tid = threadIdx.x, lane = tid & 31, wid = tid >> 5;
    const int b = blockIdx.y;
    const int n0 = blockIdx.x * 64;
    const int g = lane >> 3;

#pragma unroll
    for (int t = 0; t < 8; t++) {
        int i = tid + t * 320;
        CP_ASYNC16(smb + i * 16, wq + i * 8);
    }
    for (int idx = tid; idx < 1024; idx += 320) {
        int ch = idx >> 3, seg = idx & 7;
        CP_ASYNC16(smb + 40960 + ch * 144 + seg * 16,
                   y16 + ((size_t)b * 128 + ch) * NPIX + n0 + seg * 8);
    }
    CP_COMMIT();
    CP_WAIT(0);
    __syncthreads();

    const int mt = wid;
    float acc[8][4];
#pragma unroll
    for (int nt = 0; nt < 8; nt++)
#pragma unroll
        for (int r = 0; r < 4; r++) acc[nt][r] = 0.0f;

    const char* Aptr = smc;
    const uint32_t Bsm = smb + 40960;
#pragma unroll
    for (int ks = 0; ks < 8; ks++) {
        uint4 v = *(const uint4*)(Aptr + (((mt * 8 + ks) * 32 + lane) << 4));
        uint32_t afr[4] = {v.x, v.y, v.z, v.w};
#pragma unroll
        for (int t16 = 0; t16 < 4; t16++) {
            uint32_t bfr[4];
            ldsm4t(bfr, Bsm + (ks * 16 + (g & 1) * 8 + (lane & 7)) * 144
                       + (t16 * 16 + (g >> 1) * 8) * 2);
            mma_f16(acc[2 * t16],     afr, bfr[0], bfr[1]);
            mma_f16(acc[2 * t16 + 1], afr, bfr[2], bfr[3]);
        }
    }

    const int r0 = mt * 16 + (lane >> 2);
    if (mt < 8) {
        const float b0 = bd[r0], b8 = bd[r0 + 8];
        __half* v0 = vh + ((size_t)b * 128 + r0) * NPIX;
        __half* v8 = vh + ((size_t)b * 128 + r0 + 8) * NPIX;
#pragma unroll
        for (int nt = 0; nt < 8; nt++) {
            const int n = n0 + nt * 8 + 2 * (lane & 3);
            *(uint32_t*)(v0 + n) = ph2(acc[nt][0] + b0, acc[nt][1] + b0);
            *(uint32_t*)(v8 + n) = ph2(acc[nt][2] + b8, acc[nt][3] + b8);
        }
    } else {
        const bool isq = (mt == 8);
        const float* bias = isq ? bb : bc;
        __half* dst = isq ? qh : kh;
        const int d = lane >> 2;
        const float b0 = bias[d], b8 = bias[d + 8];
#pragma unroll
        for (int nt = 0; nt < 8; nt++) {
            const int n = n0 + nt * 8 + 2 * (lane & 3);
            __half* p0 = dst + ((size_t)b * NPIX + n) * 16;
            p0[d]      = __float2half(acc[nt][0] + b0);
            p0[16 + d] = __float2half(acc[nt][1] + b0);
            p0[d + 8]      = __float2half(acc[nt][2] + b8);
            p0[16 + d + 8] = __float2half(acc[nt][3] + b8);
        }
    }
}

// ---------------------------------------------------------------------------
// PAM flash attention: q-tile 64, 128-thread CTA, occ 3, double-buffered K/V
// (reverted to the verified R11 structure).  SMEM total 46080.
// ---------------------------------------------------------------------------
#define ATT_SMEM 46080

__global__ void __launch_bounds__(128, 3) pam_attn_mma(
        const __half* __restrict__ qh, const __half* __restrict__ kh,
        const __half* __restrict__ vd,
        const __half* __restrict__ yhi, const __half* __restrict__ ylo,
        const float* __restrict__ alpha, __half* __restrict__ xp2) {
    extern __shared__ __align__(16) char smc[];
    const uint32_t smb = smem_u32(smc);
    const uint32_t Qb  = smb;
    const uint32_t Kb0 = smb + 3072;
    const uint32_t Vb0 = smb + 9216;

    const int tid = threadIdx.x, lane = tid & 31, wid = tid >> 5;
    const int b = blockIdx.y;
    const int n0 = blockIdx.x * 64;
    const int qbase = wid * 16;

    const int g = lane >> 3, r8 = lane & 7;
    const uint32_t qoff = (uint32_t)(((g & 1) * 8 + r8) * 48 + (g >> 1) * 16);
    const uint32_t koff = (uint32_t)(((g >> 1) * 8 + r8) * 48 + (g & 1) * 16);
    const uint32_t voff = (uint32_t)(((g >> 1) * 8 + r8) * 144 + (g & 1) * 16);

    auto stageKV = [&](int t, int buf) {
        const int k0 = t * 64;
        {
            int row = tid >> 1, h = tid & 1;
            CP_ASYNC16(Kb0 + buf * 3072 + row * 48 + h * 16,
                       kh + ((size_t)b * NPIX + k0 + row) * 16 + h * 8);
        }
#pragma unroll
        for (int t4 = 0; t4 < 8; t4++) {
            int idx = tid + t4 * 128;
            int ch = idx >> 3, c = idx & 7;
            CP_ASYNC16(Vb0 + buf * 18432 + ch * 144 + c * 16,
                       vd + ((size_t)b * 128 + ch) * NPIX + k0 + c * 8);
        }
        CP_COMMIT();
    };

    {
        int row = tid >> 1, h = tid & 1;
        CP_ASYNC16(Qb + row * 48 + h * 16,
                   qh + ((size_t)b * NPIX + n0 + row) * 16 + h * 8);
    }
    stageKV(0, 0);

    uint32_t qfr[4];
    float O[16][4];
#pragma unroll
    for (int nc = 0; nc < 16; nc++)
#pragma unroll
        for (int r = 0; r < 4; r++) O[nc][r] = 0.0f;
    float mrun0 = -1e30f, mrun1 = -1e30f, lrun0 = 0.0f, lrun1 = 0.0f;

    for (int t = 0; t < 64; t++) {
        const int buf = t & 1;
        CP_WAIT(0);
        __syncthreads();
        if (t + 1 < 64) stageKV(t + 1, buf ^ 1);
        if (t == 0) ldsm4(qfr, Qb + qbase * 48 + qoff);

        const uint32_t Kb = Kb0 + buf * 3072;
        const uint32_t Vb = Vb0 + buf * 18432;

        float S[8][4];
#pragma unroll
        for (int ks = 0; ks < 4; ks++) {
            uint32_t kb[4];
            ldsm4(kb, Kb + ks * 768 + koff);
#pragma unroll
            for (int r = 0; r < 4; r++) { S[2 * ks][r] = 0.0f; S[2 * ks + 1][r] = 0.0f; }
            mma_f16(S[2 * ks],     qfr, kb[0], kb[1]);
            mma_f16(S[2 * ks + 1], qfr, kb[2], kb[3]);
        }

        float tm0 = -1e30f, tm1 = -1e30f;
#pragma unroll
        for (int nt = 0; nt < 8; nt++) {
            tm0 = fmaxf(tm0, fmaxf(S[nt][0], S[nt][1]));
            tm1 = fmaxf(tm1, fmaxf(S[nt][2], S[nt][3]));
        }
        tm0 = fmaxf(tm0, __shfl_xor_sync(0xffffffffu, tm0, 1));
        tm0 = fmaxf(tm0, __shfl_xor_sync(0xffffffffu, tm0, 2));
        tm1 = fmaxf(tm1, __shfl_xor_sync(0xffffffffu, tm1, 1));
        tm1 = fmaxf(tm1, __shfl_xor_sync(0xffffffffu, tm1, 2));
        const float mn0 = fmaxf(mrun0, tm0), mn1 = fmaxf(mrun1, tm1);
        const float f0 = __expf(mrun0 - mn0), f1 = __expf(mrun1 - mn1);
        mrun0 = mn0; mrun1 = mn1;

        float ts0 = 0.0f, ts1 = 0.0f;
        uint32_t afr[4][4];
#pragma unroll
        for (int j = 0; j < 4; j++) {
            float p00 = __expf(S[2 * j][0] - mn0), p01 = __expf(S[2 * j][1] - mn0);
            float p10 = __expf(S[2 * j][2] - mn1), p11 = __expf(S[2 * j][3] - mn1);
            float q00 = __expf(S[2 * j + 1][0] - mn0), q01 = __expf(S[2 * j + 1][1] - mn0);
            float q10 = __expf(S[2 * j + 1][2] - mn1), q11 = __expf(S[2 * j + 1][3] - mn1);
            ts0 += (p00 + p01) + (q00 + q01);
            ts1 += (p10 + p11) + (q10 + q11);
            afr[j][0] = ph2(p00, p01);
            afr[j][1] = ph2(p10, p11);
            afr[j][2] = ph2(q00, q01);
            afr[j][3] = ph2(q10, q11);
        }
        ts0 += __shfl_xor_sync(0xffffffffu, ts0, 1);
        ts0 += __shfl_xor_sync(0xffffffffu, ts0, 2);
        ts1 += __shfl_xor_sync(0xffffffffu, ts1, 1);
        ts1 += __shfl_xor_sync(0xffffffffu, ts1, 2);
        lrun0 = lrun0 * f0 + ts0;
        lrun1 = lrun1 * f1 + ts1;

#pragma unroll
        for (int nc = 0; nc < 16; nc++) {
            O[nc][0] *= f0; O[nc][1] *= f0;
            O[nc][2] *= f1; O[nc][3] *= f1;
        }

#pragma unroll
        for (int j = 0; j < 4; j++) {
            const uint32_t vb_j = Vb + j * 32 + voff;
#pragma unroll
            for (int p = 0; p < 8; p++) {
                uint32_t vb[4];
                ldsm4(vb, vb_j + p * 2304);
                mma_f16(O[2 * p],     afr[j], vb[0], vb[1]);
                mma_f16(O[2 * p + 1], afr[j], vb[2], vb[3]);
            }
        }
    }

    const float linv0 = 1.0f / lrun0, linv1 = 1.0f / lrun1;
    const float a = alpha[0];
    const int px0 = n0 + qbase + (lane >> 2);
    const int px1 = px0 + 8;
    __half* dst0 = xp2 + (((size_t)b * XP_H + (px0 >> 6) + 1) * XP_H + (px0 & 63) + 1) * CI;
    __half* dst1 = xp2 + (((size_t)b * XP_H + (px1 >> 6) + 1) * XP_H + (px1 & 63) + 1) * CI;
#pragma unroll
    for (int nc = 0; nc < 16; nc++) {
        const int ch = nc * 8 + 2 * (lane & 3);
        const __half* hp = yhi + ((size_t)b * 128 + ch) * NPIX;
        const __half* lp = ylo + ((size_t)b * 128 + ch) * NPIX;
        float ya0 = __half2float(hp[px0]) + __half2float(lp[px0]);
        float yb0 = __half2float(hp[NPIX + px0]) + __half2float(lp[NPIX + px0]);
        float ya1 = __half2float(hp[px1]) + __half2float(lp[px1]);
        float yb1 = __half2float(hp[NPIX + px1]) + __half2float(lp[NPIX + px1]);
        *(uint32_t*)(dst0 + ch) = ph2(fmaf(a, O[nc][0] * linv0, ya0),
                                      fmaf(a, O[nc][1] * linv0, yb0));
        *(uint32_t*)(dst1 + ch) = ph2(fmaf(a, O[nc][2] * linv1, ya1),
                                      fmaf(a, O[nc][3] * linv1, yb1));
    }
}

// ---------------------------------------------------------------------------
// CAM gram matrix via fp16 hi/lo split MMA, split-K partials.
// ---------------------------------------------------------------------------
#define CAME_SMEM 36864

__global__ void __launch_bounds__(256, 2) cam_energy_mma(
        const __half* __restrict__ yhi, const __half* __restrict__ ylo,
        float* __restrict__ epart) {
    extern __shared__ __align__(16) char smc[];
    const uint32_t smb = smem_u32(smc);
    const int tid = threadIdx.x, lane = tid & 31, wid = tid >> 5;
    const int warp_m = wid >> 2, warp_n = wid & 3;
    const int b = blockIdx.y, ksid = blockIdx.x;
    const int g = lane >> 3, r8 = lane & 7;

    float acc[4][4][4];
#pragma unroll
    for (int mt = 0; mt < 4; mt++)
#pragma unroll
        for (int nt = 0; nt < 4; nt++)
#pragma unroll
            for (int r = 0; r < 4; r++) acc[mt][nt][r] = 0.0f;

    for (int chunk = 0; chunk < 4; chunk++) {
        const int k0 = ksid * 256 + chunk * 64;
        __syncthreads();
#pragma unroll
        for (int t = 0; t < 4; t++) {
            int idx = tid + t * 256;
            int ch = idx >> 3, seg = idx & 7;
            CP_ASYNC16(smb + ch * 144 + seg * 16,
                       yhi + ((size_t)b * 128 + ch) * NPIX + k0 + seg * 8);
            CP_ASYNC16(smb + 18432 + ch * 144 + seg * 16,
                       ylo + ((size_t)b * 128 + ch) * NPIX + k0 + seg * 8);
        }
        CP_COMMIT();
        CP_WAIT(0);
        __syncthreads();

#pragma unroll
        for (int ks = 0; ks < 4; ks++) {
            uint32_t ahi[4][4], alo[4][4];
#pragma unroll
            for (int mt = 0; mt < 4; mt++) {
                const uint32_t arow = (warp_m * 64 + mt * 16 + (g & 1) * 8 + r8) * 144
                                      + ks * 32 + (g >> 1) * 16;
                ldsm4(ahi[mt], smb + arow);
                ldsm4(alo[mt], smb + 18432 + arow);
            }
            uint32_t bhi[2][4], blo[2][4];
#pragma unroll
            for (int t16 = 0; t16 < 2; t16++) {
                const uint32_t brow = (warp_n * 32 + t16 * 16 + (g >> 1) * 8 + r8) * 144
                                      + ks * 32 + (g & 1) * 16;
                ldsm4(bhi[t16], smb + brow);
                ldsm4(blo[t16], smb + 18432 + brow);
            }
#pragma unroll
            for (int mt = 0; mt < 4; mt++)
#pragma unroll
                for (int t16 = 0; t16 < 2; t16++) {
                    mma_f16(acc[mt][2 * t16],     ahi[mt], bhi[t16][0], bhi[t16][1]);
                    mma_f16(acc[mt][2 * t16 + 1], ahi[mt], bhi[t16][2], bhi[t16][3]);
                    mma_f16(acc[mt][2 * t16],     ahi[mt], blo[t16][0], blo[t16][1]);
                    mma_f16(acc[mt][2 * t16 + 1], ahi[mt], blo[t16][2], blo[t16][3]);
                    mma_f16(acc[mt][2 * t16],     alo[mt], bhi[t16][0], bhi[t16][1]);
                    mma_f16(acc[mt][2 * t16 + 1], alo[mt], bhi[t16][2], bhi[t16][3]);
                }
        }
    }

    float* ep = epart + (((size_t)ksid * BATCH + b) * 128) * 128;
#pragma unroll
    for (int mt = 0; mt < 4; mt++) {
        const int c0 = warp_m * 64 + mt * 16 + (lane >> 2);
#pragma unroll
        for (int nt = 0; nt < 4; nt++) {
            const int d = warp_n * 32 + nt * 8 + 2 * (lane & 3);
            *(float2*)(ep + (size_t)c0 * 128 + d) = make_float2(acc[mt][nt][0], acc[mt][nt][1]);
            *(float2*)(ep + (size_t)(c0 + 8) * 128 + d) = make_float2(acc[mt][nt][2], acc[mt][nt][3]);
        }
    }
}

// ---------------------------------------------------------------------------
// CAM softmax of (rowmax - E), reducing the KSPLIT partials -> fp16 attn
// ---------------------------------------------------------------------------
__global__ void cam_softmax_kernel(const float* __restrict__ epart,
                                   __half* __restrict__ attn) {
    const int row = blockIdx.x;
    const int tid = threadIdx.x;
    __shared__ float red[4];

    float e = 0.0f;
#pragma unroll
    for (int s = 0; s < KSPLIT; s++)
        e += epart[((size_t)s * 1024 + row) * 128 + tid];

    float m = e;
#pragma unroll
    for (int off = 16; off; off >>= 1) m = fmaxf(m, __shfl_xor_sync(0xffffffff, m, off));
    if ((tid & 31) == 0) red[tid >> 5] = m;
    __syncthreads();
    float mx = fmaxf(fmaxf(red[0], red[1]), fmaxf(red[2], red[3]));
    float e2 = mx - e;
    __syncthreads();

    float m2 = e2;
#pragma unroll
    for (int off = 16; off; off >>= 1) m2 = fmaxf(m2, __shfl_xor_sync(0xffffffff, m2, off));
    if ((tid & 31) == 0) red[tid >> 5] = m2;
    __syncthreads();
    m2 = fmaxf(fmaxf(red[0], red[1]), fmaxf(red[2], red[3]));
    float p = __expf(e2 - m2);
    __syncthreads();

    float s = p;
#pragma unroll
    for (int off = 16; off; off >>= 1) s += __shfl_xor_sync(0xffffffff, s, off);
    if ((tid & 31) == 0) red[tid >> 5] = s;
    __syncthreads();
    s = red[0] + red[1] + red[2] + red[3];

    attn[(size_t)row * 128 + tid] = __float2half(p / s);
}

// ---------------------------------------------------------------------------
// CAM feature via fp16 MMA -> fp16 padded NHWC; residual from hi+lo.
// ---------------------------------------------------------------------------
#define CAMF_SMEM 53248

__global__ void __launch_bounds__(256, 1) cam_feat_mma(
        const __half* __restrict__ attn16,
        const __half* __restrict__ yhi, const __half* __restrict__ ylo,
        const float* __restrict__ beta, __half* __restrict__ xp2) {
    extern __shared__ __align__(16) char smc[];
    const uint32_t smb = smem_u32(smc);
    const int tid = threadIdx.x, lane = tid & 31, wid = tid >> 5;
    const int b = blockIdx.y;
    const int n0 = blockIdx.x * 64;
    const int g = lane >> 3;

#pragma unroll
    for (int t = 0; t < 8; t++) {
        int idx = tid + t * 256;
        int c = idx >> 4, seg = idx & 15;
        CP_ASYNC16(smb + c * 272 + seg * 16,
                   attn16 + ((size_t)b * 128 + c) * 128 + seg * 8);
    }
#pragma unroll
    for (int t = 0; t < 4; t++) {
        int idx = tid + t * 256;
        int ch = idx >> 3, seg = idx & 7;
        CP_ASYNC16(smb + 34816 + ch * 144 + seg * 16,
                   yhi + ((size_t)b * 128 + ch) * NPIX + n0 + seg * 8);
    }
    CP_COMMIT();
    CP_WAIT(0);
    __syncthreads();

    const int mt = wid;
    float acc[8][4];
#pragma unroll
    for (int nt = 0; nt < 8; nt++)
#pragma unroll
        for (int r = 0; r < 4; r++) acc[nt][r] = 0.0f;

    const uint32_t Bsm = smb + 34816;
#pragma unroll
    for (int ks = 0; ks < 8; ks++) {
        uint32_t afr[4];
        ldsm4(afr, smb + (mt * 16 + (g & 1) * 8 + (lane & 7)) * 272
                  + ks * 32 + (g >> 1) * 16);
#pragma unroll
        for (int t16 = 0; t16 < 4; t16++) {
            uint32_t bfr[4];
            ldsm4t(bfr, Bsm + (ks * 16 + (g & 1) * 8 + (lane & 7)) * 144
                       + (t16 * 16 + (g >> 1) * 8) * 2);
            mma_f16(acc[2 * t16],     afr, bfr[0], bfr[1]);
            mma_f16(acc[2 * t16 + 1], afr, bfr[2], bfr[3]);
        }
    }

    const float bet = beta[0];
    const int c0 = mt * 16 + (lane >> 2);
#pragma unroll
    for (int nt = 0; nt < 8; nt++) {
        const int n = n0 + nt * 8 + 2 * (lane & 3);
        const __half* h0p = yhi + ((size_t)b * 128 + c0) * NPIX;
        const __half* l0p = ylo + ((size_t)b * 128 + c0) * NPIX;
        float y00 = __half2float(h0p[n]) + __half2float(l0p[n]);
        float y01 = __half2float(h0p[n + 1]) + __half2float(l0p[n + 1]);
        float y80 = __half2float(h0p[8 * NPIX + n]) + __half2float(l0p[8 * NPIX + n]);
        float y81 = __half2float(h0p[8 * NPIX + n + 1]) + __half2float(l0p[8 * NPIX + n + 1]);
        __half* p0 = xp2 + (((size_t)b * XP_H + (n >> 6) + 1) * XP_H + (n & 63) + 1) * CI;
        __half* p1 = p0 + CI;
        p0[c0]     = __float2half(fmaf(bet, acc[nt][0], y00));
        p1[c0]     = __float2half(fmaf(bet, acc[nt][1], y01));
        p0[c0 + 8] = __float2half(fmaf(bet, acc[nt][2], y80));
        p1[c0 + 8] = __float2half(fmaf(bet, acc[nt][3], y81));
    }
}

// ---------------------------------------------------------------------------
// Final heads via one fused fp16 MMA:  A[64x256] @ [fp;fc](256 x 64px tile).
// ---------------------------------------------------------------------------
#define FIN_SMEM 69632

__global__ void __launch_bounds__(128, 2) final_mma(
        const __half* __restrict__ wfin,
        const __half* __restrict__ fp, const __half* __restrict__ fc,
        const float* __restrict__ bout, const float* __restrict__ bp3,
        const float* __restrict__ bc3, float* __restrict__ out) {
    extern __shared__ __align__(16) char smc[];
    const uint32_t smb = smem_u32(smc);
    const int tid = threadIdx.x, lane = tid & 31, wid = tid >> 5;
    const int b = blockIdx.y;
    const int n0 = blockIdx.x * 64;
    const int g = lane >> 3;

#pragma unroll
    for (int t = 0; t < 16; t++) {
        int i = tid + t * 128;
        CP_ASYNC16(smb + i * 16, wfin + i * 8);
    }
#pragma unroll
    for (int t = 0; t < 16; t++) {
        int idx = tid + t * 128;
        int ch = idx >> 3, seg = idx & 7;
        const __half* src = (ch < 128)
            ? fp + ((size_t)b * 128 + ch) * NPIX + n0 + seg * 8
            : fc + ((size_t)b * 128 + (ch - 128)) * NPIX + n0 + seg * 8;
        CP_ASYNC16(smb + 32768 + ch * 144 + seg * 16, src);
    }
    CP_COMMIT();
    CP_WAIT(0);
    __syncthreads();

    const int mt = wid;
    float acc[8][4];
#pragma unroll
    for (int nt = 0; nt < 8; nt++)
#pragma unroll
        for (int r = 0; r < 4; r++) acc[nt][r] = 0.0f;

    const char* Aptr = smc;
    const uint32_t Bsm = smb + 32768;
#pragma unroll
    for (int ks = 0; ks < 16; ks++) {
        uint4 v = *(const uint4*)(Aptr + (((mt * 16 + ks) * 32 + lane) << 4));
        uint32_t afr[4] = {v.x, v.y, v.z, v.w};
#pragma unroll
        for (int t16 = 0; t16 < 4; t16++) {
            uint32_t bfr[4];
            ldsm4t(bfr, Bsm + (ks * 16 + (g & 1) * 8 + (lane & 7)) * 144
                       + (t16 * 16 + (g >> 1) * 8) * 2);
            mma_f16(acc[2 * t16],     afr, bfr[0], bfr[1]);
            mma_f16(acc[2 * t16 + 1], afr, bfr[2], bfr[3]);
        }
    }

    const size_t SEG = (size_t)BATCH * NC * NPIX;
    auto emit = [&](int row, int px, float v) {
        if (row >= 57) return;
        float bias;
        size_t base;
        if (row < 19)      { bias = bout[row]; base = ((size_t)b * NC + row) * NPIX; }
        else if (row < 38) { bias = bp3[row - 19]; base = SEG + ((size_t)b * NC + row - 19) * NPIX; }
        else               { bias = bc3[row - 38]; base = 2 * SEG + ((size_t)b * NC + row - 38) * NPIX; }
        out[base + px] = sigmoidf_(v + bias);
    };

    const int r0 = mt * 16 + (lane >> 2);
#pragma unroll
    for (int nt = 0; nt < 8; nt++) {
        const int px = n0 + nt * 8 + 2 * (lane & 3);
        emit(r0,     px,     acc[nt][0]);
        emit(r0,     px + 1, acc[nt][1]);
        emit(r0 + 8, px,     acc[nt][2]);
        emit(r0 + 8, px + 1, acc[nt][3]);
    }
}

// ---------------------------------------------------------------------------
// Streams / events (created once at program load)
// ---------------------------------------------------------------------------
namespace {
struct StreamInit {
    cudaStream_t s1;
    cudaEvent_t e0, e1, e2, e3, e4, e5, e6;
    StreamInit() {
        cudaStreamCreateWithFlags(&s1, cudaStreamNonBlocking);
        cudaEventCreateWithFlags(&e0, cudaEventDisableTiming);
        cudaEventCreateWithFlags(&e1, cudaEventDisableTiming);
        cudaEventCreateWithFlags(&e2, cudaEventDisableTiming);
        cudaEventCreateWithFlags(&e3, cudaEventDisableTiming);
        cudaEventCreateWithFlags(&e4, cudaEventDisableTiming);
        cudaEventCreateWithFlags(&e5, cudaEventDisableTiming);
        cudaEventCreateWithFlags(&e6, cudaEventDisableTiming);
    }
};
StreamInit g_str;
}

// ---------------------------------------------------------------------------
// Launch
// ---------------------------------------------------------------------------
extern "C" void kernel_launch(void* const* d_in, const int* in_sizes, int n_in,
                              void* d_out, int out_size) {
    const float* x    = (const float*)d_in[0];
    const float* Wp1  = (const float*)d_in[1];
    const float* bnp1 = (const float*)d_in[2];
    const float* Wc1  = (const float*)d_in[3];
    const float* bnc1 = (const float*)d_in[4];
    const float* Wb   = (const float*)d_in[5];
    const float* bb   = (const float*)d_in[6];
    const float* Wc   = (const float*)d_in[7];
    const float* bc   = (const float*)d_in[8];
    const float* Wd   = (const float*)d_in[9];
    const float* bd   = (const float*)d_in[10];
    const float* alpha= (const float*)d_in[11];
    const float* beta = (const float*)d_in[12];
    const float* Wp2  = (const float*)d_in[13];
    const float* bnp2 = (const float*)d_in[14];
    const float* Wc2  = (const float*)d_in[15];
    const float* bnc2 = (const float*)d_in[16];
    const float* Wout = (const float*)d_in[17];
    const float* bout = (const float*)d_in[18];
    const float* Wp3  = (const float*)d_in[19];
    const float* bp3  = (const float*)d_in[20];
    const float* Wc3  = (const float*)d_in[21];
    const float* bc3  = (const float*)d_in[22];
    float* out = (float*)d_out;

    float* epart;
    __half *featp1h, *featp1lo, *featc1h, *featc1lo, *qh, *kh, *vd, *attn16;
    __half *xpad, *xp2a, *xp2b, *wf1, *wf2, *wqkv, *wfin;
    cudaGetSymbolAddress((void**)&featp1h,  g_featp1h);
    cudaGetSymbolAddress((void**)&featp1lo, g_featp1lo);
    cudaGetSymbolAddress((void**)&featc1h,  g_featc1h);
    cudaGetSymbolAddress((void**)&featc1lo, g_featc1lo);
    cudaGetSymbolAddress((void**)&qh,       g_qh);
    cudaGetSymbolAddress((void**)&kh,       g_kh);
    cudaGetSymbolAddress((void**)&vd,       g_vd);
    cudaGetSymbolAddress((void**)&epart,    g_epart);
    cudaGetSymbolAddress((void**)&attn16,   g_attn16);
    cudaGetSymbolAddress((void**)&xpad,     g_xpad);
    cudaGetSymbolAddress((void**)&xp2a,     g_xp2a);
    cudaGetSymbolAddress((void**)&xp2b,     g_xp2b);
    cudaGetSymbolAddress((void**)&wf1,      g_wf16_1);
    cudaGetSymbolAddress((void**)&wf2,      g_wf16_2);
    cudaGetSymbolAddress((void**)&wqkv,     g_wqkv);
    cudaGetSymbolAddress((void**)&wfin,     g_wfinal);

    cudaFuncSetAttribute(conv_mma_kernel<512>,
                         cudaFuncAttributeMaxDynamicSharedMemorySize, CONV_SMEM);
    cudaFuncSetAttribute(conv_mma_kernel<128>,
                         cudaFuncAttributeMaxDynamicSharedMemorySize, CONV_SMEM);
    cudaFuncSetAttribute(pam_attn_mma,
                         cudaFuncAttributeMaxDynamicSharedMemorySize, ATT_SMEM);
    cudaFuncSetAttribute(pam_attn_mma,
                         cudaFuncAttributePreferredSharedMemoryCarveout, 100);
    cudaFuncSetAttribute(qkv_kernel,
                         cudaFuncAttributeMaxDynamicSharedMemorySize, QKV_SMEM);
    cudaFuncSetAttribute(cam_energy_mma,
                         cudaFuncAttributeMaxDynamicSharedMemorySize, CAME_SMEM);
    cudaFuncSetAttribute(cam_feat_mma,
                         cudaFuncAttributeMaxDynamicSharedMemorySize, CAMF_SMEM);
    cudaFuncSetAttribute(final_mma,
                         cudaFuncAttributeMaxDynamicSharedMemorySize, FIN_SMEM);

    cudaStream_t s1 = g_str.s1;

    // Fork s1 off the main stream
    cudaEventRecord(g_str.e0, 0);
    cudaStreamWaitEvent(s1, g_str.e0, 0);

    // s0: interior packing
    pack_x_kernel<<<dim3(64, BATCH), 256>>>(x, xpad);
    cudaEventRecord(g_str.e5, 0);   // pack_x done

    // s1: consolidated borders + weight packing (parallel with pack_x)
    zero_borders_all<<<dim3(XP_H, BATCH, 3), 256, 0, s1>>>(xpad, xp2a, xp2b);
    pack_w16<<<dim3(144, 2), 256, 0, s1>>>(Wp1, Wc1, wf1, CIN);
    cudaEventRecord(g_str.e1, s1);  // borders + wf1 ready
    pack_small<<<144, 256, 0, s1>>>(Wd, Wb, Wc, wqkv, Wout, Wp3, Wc3, wfin);
    cudaEventRecord(g_str.e4, s1);  // wqkv + wfinal ready (for qkv)
    pack_w16<<<dim3(36, 2), 256, 0, s1>>>(Wp2, Wc2, wf2, CI);
    cudaEventRecord(g_str.e6, s1);  // wf2 ready (for conv2)

    // s0: conv1-PAM FIRST (alone at full chip rate)
    cudaStreamWaitEvent(0, g_str.e1, 0);
    conv_mma_kernel<512><<<dim3(32, BATCH, 1), 256, CONV_SMEM>>>(
        xpad, xpad, wf1, bnp1, bnp1, featp1h, featp1h, featp1lo, featp1lo);
    cudaEventRecord(g_str.e2, 0);   // conv1-PAM done

    // s1: conv1-CAM + entire CAM chain (concurrent with PAM chain on s0)
    cudaStreamWaitEvent(s1, g_str.e2, 0);
    cudaStreamWaitEvent(s1, g_str.e5, 0);
    conv_mma_kernel<512><<<dim3(32, BATCH, 1), 256, CONV_SMEM, s1>>>(
        xpad, xpad, wf1 + 144 * 4096, bnc1, bnc1, featc1h, featc1h, featc1lo, featc1lo);
    cam_energy_mma<<<dim3(KSPLIT, BATCH), 256, CAME_SMEM, s1>>>(featc1h, featc1lo, epart);
    cam_softmax_kernel<<<BATCH * 128, 128, 0, s1>>>(epart, attn16);
    cam_feat_mma<<<dim3(64, BATCH), 256, CAMF_SMEM, s1>>>(
        attn16, featc1h, featc1lo, beta, xp2b);
    conv_mma_kernel<128><<<dim3(32, BATCH, 1), 256, CONV_SMEM, s1>>>(
        xp2b, xp2b, wf2 + 36 * 4096, bnc2, bnc2, featc1h, featc1h, nullptr, nullptr);
    cudaEventRecord(g_str.e3, s1);  // CAM branch fully done

    // s0: PAM chain (qkv waits only on pack_small)
    cudaStreamWaitEvent(0, g_str.e4, 0);
    qkv_kernel<<<dim3(64, BATCH), 320, QKV_SMEM>>>(
        wqkv, featp1h, bd, bb, bc, vd, qh, kh);
    pam_attn_mma<<<dim3(64, BATCH), 128, ATT_SMEM>>>(
        qh, kh, vd, featp1h, featp1lo, alpha, xp2a);
    cudaStreamWaitEvent(0, g_str.e6, 0);
    conv_mma_kernel<128><<<dim3(32, BATCH, 1), 256, CONV_SMEM>>>(
        xp2a, xp2a, wf2, bnp2, bnp2, featp1h, featp1h, nullptr, nullptr);

    // Join, then fused final heads
    cudaStreamWaitEvent(0, g_str.e3, 0);
    final_mma<<<dim3(64, BATCH), 128, FIN_SMEM>>>(
        wfin, featp1h, featc1h, bout, bp3, bc3, out);
}

// round 15
// speedup vs baseline: 1.0260x; 1.0131x over previous
#include <cuda_runtime.h>
#include <cuda_bf16.h>
#include <cuda_fp16.h>
#include <math.h>
#include <cstdint>

// ---------------------------------------------------------------------------
// Problem constants
// ---------------------------------------------------------------------------
#define BATCH 8
#define CIN   512
#define CI    128
#define CK    16
#define NC    19
#define NPIX  4096
#define FEAT_ELEMS (BATCH * CI * NPIX)
#define XP_H 66
#define KSPLIT 16

// ---------------------------------------------------------------------------
// Scratch (device globals)
// ---------------------------------------------------------------------------
__device__ __half g_featp1h[FEAT_ELEMS];
__device__ __half g_featp1lo[FEAT_ELEMS];
__device__ __half g_featc1h[FEAT_ELEMS];
__device__ __half g_featc1lo[FEAT_ELEMS];
__device__ __half g_qh[BATCH * NPIX * CK];
__device__ __half g_kh[BATCH * NPIX * CK];
__device__ __half g_vd[FEAT_ELEMS];
__device__ float  g_epart[KSPLIT * BATCH * CI * CI];
__device__ __half g_attn16[BATCH * CI * CI];
__device__ __half g_xpad[BATCH * XP_H * XP_H * CIN];
__device__ __half g_xp2a[BATCH * XP_H * XP_H * CI];
__device__ __half g_xp2b[BATCH * XP_H * XP_H * CI];
__device__ __half g_wf16_1[2 * 144 * 4096];
__device__ __half g_wf16_2[2 * 36 * 4096];
__device__ __half g_wqkv[10 * 8 * 32 * 8];
__device__ __half g_wfinal[4 * 16 * 32 * 8];

__device__ __forceinline__ float sigmoidf_(float x) {
    return 1.0f / (1.0f + __expf(-x));
}
__device__ __forceinline__ uint32_t smem_u32(const void* p) {
    uint32_t a;
    asm("{ .reg .u64 t; cvta.to.shared.u64 t, %1; cvt.u32.u64 %0, t; }" : "=r"(a) : "l"(p));
    return a;
}
__device__ __forceinline__ void mma_f16(float c[4], const uint32_t a[4], const uint32_t b0, const uint32_t b1) {
    asm volatile(
        "mma.sync.aligned.m16n8k16.row.col.f32.f16.f16.f32 "
        "{%0,%1,%2,%3}, {%4,%5,%6,%7}, {%8,%9}, {%0,%1,%2,%3};"
        : "+f"(c[0]), "+f"(c[1]), "+f"(c[2]), "+f"(c[3])
        : "r"(a[0]), "r"(a[1]), "r"(a[2]), "r"(a[3]), "r"(b0), "r"(b1));
}
__device__ __forceinline__ void ldsm4(uint32_t r[4], uint32_t addr) {
    asm volatile("ldmatrix.sync.aligned.m8n8.x4.shared.b16 {%0,%1,%2,%3}, [%4];"
                 : "=r"(r[0]), "=r"(r[1]), "=r"(r[2]), "=r"(r[3]) : "r"(addr));
}
__device__ __forceinline__ void ldsm4t(uint32_t r[4], uint32_t addr) {
    asm volatile("ldmatrix.sync.aligned.m8n8.x4.trans.shared.b16 {%0,%1,%2,%3}, [%4];"
                 : "=r"(r[0]), "=r"(r[1]), "=r"(r[2]), "=r"(r[3]) : "r"(addr));
}
#define CP_ASYNC16(dst, src) \
    asm volatile("cp.async.ca.shared.global [%0], [%1], 16;" :: "r"(dst), "l"(src))
#define CP_COMMIT() asm volatile("cp.async.commit_group;")
#define CP_WAIT(N)  asm volatile("cp.async.wait_group %0;" :: "n"(N))

__device__ __forceinline__ uint32_t ph2(float x, float y) {
    __half2 h = __floats2half2_rn(x, y);
    return *(uint32_t*)&h;
}

// ---------------------------------------------------------------------------
// Pack x: f32 NCHW -> fp16 NHWC padded
// ---------------------------------------------------------------------------
__global__ void pack_x_kernel(const float* __restrict__ x, __half* __restrict__ xp) {
    const int h = blockIdx.x, b = blockIdx.y, tid = threadIdx.x;
    __shared__ float s[32][65];
    for (int ci0 = 0; ci0 < CIN; ci0 += 32) {
        for (int idx = tid; idx < 32 * 64; idx += 256) {
            int ci_l = idx >> 6, w = idx & 63;
            s[ci_l][w] = x[(((size_t)b * CIN + ci0 + ci_l) * 64 + h) * 64 + w];
        }
        __syncthreads();
        for (int idx = tid; idx < 64 * 32; idx += 256) {
            int w = idx >> 5, ci_l = idx & 31;
            xp[(((size_t)b * XP_H + h + 1) * XP_H + w + 1) * CIN + ci0 + ci_l] =
                __float2half(s[ci_l][w]);
        }
        __syncthreads();
    }
}

// One launch zeroes the borders of all three padded buffers (z selects).
__global__ void zero_borders_all(__half* __restrict__ xpad,
                                 __half* __restrict__ xp2a,
                                 __half* __restrict__ xp2b) {
    const int hp = blockIdx.x, b = blockIdx.y, z = blockIdx.z, tid = threadIdx.x;
    __half* base = (z == 0) ? xpad : (z == 1 ? xp2a : xp2b);
    const int C = (z == 0) ? CIN : CI;
    __half* row = base + ((size_t)b * XP_H + hp) * XP_H * C;
    const __half zz = __float2half(0.0f);
    if (hp == 0 || hp == XP_H - 1) {
        for (int idx = tid; idx < XP_H * C; idx += 256) row[idx] = zz;
    } else {
        for (int idx = tid; idx < C; idx += 256) {
            row[idx] = zz;
            row[(size_t)(XP_H - 1) * C + idx] = zz;
        }
    }
}

// ---------------------------------------------------------------------------
// Pack conv weights into m16n8k16 fp16 A-fragment order.
// ---------------------------------------------------------------------------
__global__ void pack_w16(const float* __restrict__ W0, const float* __restrict__ W1,
                         __half* __restrict__ wf, int CIN_T) {
    const int cpc = CIN_T / 32;
    const int chunk = blockIdx.x;
    const int kwh = chunk / cpc, cb = chunk % cpc;
    const float* W = blockIdx.y ? W1 : W0;
    __half* dst = wf + ((size_t)blockIdx.y * gridDim.x + chunk) * 4096;
    for (int t = 0; t < 16; t++) {
        int idx = threadIdx.x + t * 256;
        int j = idx & 7, lane = (idx >> 3) & 31, ks = (idx >> 8) & 1, mt = idx >> 9;
        int reg = j >> 1, h = j & 1;
        int co = mt * 16 + (lane >> 2) + (reg & 1) * 8;
        int ci = cb * 32 + ks * 16 + (lane & 3) * 2 + (reg >> 1) * 8 + h;
        dst[idx] = __float2half(W[((size_t)co * CIN_T + ci) * 9 + kwh]);
    }
}

// Parallel small-table pack: 144 CTAs x 256, 1 element/thread.
__global__ void pack_small(const float* __restrict__ Wd, const float* __restrict__ Wb,
                           const float* __restrict__ Wc, __half* __restrict__ dqkv,
                           const float* __restrict__ Wout, const float* __restrict__ Wp3,
                           const float* __restrict__ Wc3, __half* __restrict__ dfin) {
    int gi = blockIdx.x * 256 + threadIdx.x;
    if (gi < 20480) {
        int idx = gi;
        int j = idx & 7, lane = (idx >> 3) & 31, ks = (idx >> 8) & 7, mt = idx >> 11;
        int reg = j >> 1, h = j & 1;
        int row = mt * 16 + (lane >> 2) + (reg & 1) * 8;
        int col = ks * 16 + (lane & 3) * 2 + (reg >> 1) * 8 + h;
        float w;
        if (row < 128)      w = Wd[row * 128 + col];
        else if (row < 144) w = Wb[(row - 128) * 128 + col];
        else                w = Wc[(row - 144) * 128 + col];
        dqkv[idx] = __float2half(w);
    } else if (gi < 36864) {
        int idx = gi - 20480;
        int j = idx & 7, lane = (idx >> 3) & 31, ks = (idx >> 8) & 15, mt = idx >> 12;
        int reg = j >> 1, h = j & 1;
        int row = mt * 16 + (lane >> 2) + (reg & 1) * 8;
        int col = ks * 16 + (lane & 3) * 2 + (reg >> 1) * 8 + h;
        float w = 0.0f;
        if (col < 128) {
            if (row < 19)      w = Wout[row * 128 + col];
            else if (row < 38) w = Wp3[(row - 19) * 128 + col];
        } else {
            int c = col - 128;
            if (row < 19)      w = Wout[row * 128 + c];
            else if (row >= 38 && row < 57) w = Wc3[(row - 38) * 128 + c];
        }
        dfin[idx] = __float2half(w);
    }
}

// ---------------------------------------------------------------------------
// conv3x3 implicit GEMM, fp16 m16n8k16, halo-reuse B staging, fused BN+ReLU.
// ---------------------------------------------------------------------------
#define CONV_SMEM 91392
#define BPX 80

template<int CIN_T>
__global__ void __launch_bounds__(256, 2) conv_mma_kernel(
        const __half* __restrict__ xpA, const __half* __restrict__ xpB,
        const __half* __restrict__ wfrag,
        const float* __restrict__ bn0, const float* __restrict__ bn1,
        __half* __restrict__ o16_0, __half* __restrict__ o16_1,
        __half* __restrict__ olo_0, __half* __restrict__ olo_1) {
    constexpr int CPC = CIN_T / 32;
    constexpr int NS = CPC * 3;
    extern __shared__ __align__(16) char smc[];
    const uint32_t smb = smem_u32(smc);
    const uint32_t Boff = smb;
    const uint32_t Aoff = smb + 2 * 21120;

    const int tid = threadIdx.x, lane = tid & 31, wid = tid >> 5;
    const int warp_m = wid >> 2, warp_n = wid & 3;
    const int b = blockIdx.y, z = blockIdx.z;
    const int pxbase = blockIdx.x * 128;
    const int h0 = pxbase >> 6;
    const __half* xp = z ? xpB : xpA;
    const __half* Wf = wfrag + (size_t)z * (9 * CPC) * 4096;
    const float* bn = z ? bn1 : bn0;
    __half* o16 = z ? o16_1 : o16_0;
    __half* olo = z ? olo_1 : olo_0;
    const int g = lane >> 3;

    float acc[4][4][4];
#pragma unroll
    for (int mt = 0; mt < 4; mt++)
#pragma unroll
        for (int nt = 0; nt < 4; nt++)
#pragma unroll
            for (int r = 0; r < 4; r++) acc[mt][nt][r] = 0.0f;

    auto stageA = [&](int s, int buf) {
        const int cb = s / 3, kh = s % 3;
        const uint32_t Ad = Aoff + buf * 24576;
#pragma unroll
        for (int kw = 0; kw < 3; kw++) {
            const __half* src = Wf + (size_t)((kh * 3 + kw) * CPC + cb) * 4096;
#pragma unroll
            for (int t = 0; t < 2; t++) {
                int idx = tid + t * 256;
                CP_ASYNC16(Ad + kw * 8192 + idx * 16, src + idx * 8);
            }
        }
    };
    auto stageB = [&](int cb, int buf) {
        const uint32_t Bd = Boff + buf * 21120;
        const __half* base = xp + ((size_t)(b * XP_H + h0) * XP_H) * CIN_T + cb * 32;
        for (int idx = tid; idx < 1056; idx += 256) {
            int r = idx / 264, rem = idx % 264;
            int c = rem >> 2, q = rem & 3;
            CP_ASYNC16(Bd + (r * 66 + c) * BPX + q * 16,
                       base + ((size_t)r * XP_H + c) * CIN_T + q * 8);
        }
    };

    stageB(0, 0);
    stageA(0, 0);
    CP_COMMIT();

    for (int s = 0; s < NS; s++) {
        const int cb = s / 3, kh = s % 3;
        if (s + 1 < NS) {
            stageA(s + 1, (s + 1) & 1);
            if ((s + 1) % 3 == 0) stageB((s + 1) / 3, ((s + 1) / 3) & 1);
            CP_COMMIT();
            CP_WAIT(1);
        } else {
            CP_WAIT(0);
        }
        __syncthreads();

        const uint32_t Bh = Boff + (cb & 1) * 21120;
        const char* Ap = smc + 2 * 21120 + (s & 1) * 24576;
#pragma unroll
        for (int ks = 0; ks < 2; ks++) {
#pragma unroll
            for (int kw = 0; kw < 3; kw++) {
                uint32_t afr[4][4];
#pragma unroll
                for (int mt = 0; mt < 4; mt++) {
                    uint4 v = *(const uint4*)(Ap + kw * 8192 +
                        ((((warp_m * 4 + mt) * 2 + ks) * 32 + lane) << 4));
                    afr[mt][0] = v.x; afr[mt][1] = v.y; afr[mt][2] = v.z; afr[mt][3] = v.w;
                }
                uint32_t bfr[2][4];
#pragma unroll
                for (int t16 = 0; t16 < 2; t16++) {
                    const int n_row = warp_n * 32 + t16 * 16 + (g >> 1) * 8 + (lane & 7);
                    const int r = n_row >> 6, w = n_row & 63;
                    ldsm4(bfr[t16], Bh + ((r + kh) * 66 + w + kw) * BPX
                                      + ks * 32 + (g & 1) * 16);
                }
#pragma unroll
                for (int mt = 0; mt < 4; mt++)
#pragma unroll
                    for (int t16 = 0; t16 < 2; t16++) {
                        mma_f16(acc[mt][2 * t16],     afr[mt], bfr[t16][0], bfr[t16][1]);
                        mma_f16(acc[mt][2 * t16 + 1], afr[mt], bfr[t16][2], bfr[t16][3]);
                    }
            }
        }
        __syncthreads();
    }

#pragma unroll
    for (int mt = 0; mt < 4; mt++) {
        const int co = warp_m * 64 + mt * 16 + (lane >> 2);
        const float sc0 = bn[co],     sh0 = bn[128 + co];
        const float sc8 = bn[co + 8], sh8 = bn[136 + co];
#pragma unroll
        for (int nt = 0; nt < 4; nt++) {
            const int px = pxbase + warp_n * 32 + nt * 8 + 2 * (lane & 3);
            float v0x = fmaxf(acc[mt][nt][0] * sc0 + sh0, 0.0f);
            float v0y = fmaxf(acc[mt][nt][1] * sc0 + sh0, 0.0f);
            float v1x = fmaxf(acc[mt][nt][2] * sc8 + sh8, 0.0f);
            float v1y = fmaxf(acc[mt][nt][3] * sc8 + sh8, 0.0f);
            *(uint32_t*)(o16 + ((size_t)b * 128 + co) * NPIX + px) = ph2(v0x, v0y);
            *(uint32_t*)(o16 + ((size_t)b * 128 + co + 8) * NPIX + px) = ph2(v1x, v1y);
            if (olo) {
                float r0x = v0x - __half2float(__float2half(v0x));
                float r0y = v0y - __half2float(__float2half(v0y));
                float r1x = v1x - __half2float(__float2half(v1x));
                float r1y = v1y - __half2float(__float2half(v1y));
                *(uint32_t*)(olo + ((size_t)b * 128 + co) * NPIX + px) = ph2(r0x, r0y);
                *(uint32_t*)(olo + ((size_t)b * 128 + co + 8) * NPIX + px) = ph2(r1x, r1y);
            }
        }
    }
}

// ---------------------------------------------------------------------------
// QKV GEMM: [Wd;Wb;Wc](160x128) @ y16(128x4096) + bias.
// A fragments loaded DIRECTLY from frag-packed gmem (no smem staging):
// smem = B tile only (18432 B) -> high occupancy, no per-CTA weight reload.
// ---------------------------------------------------------------------------
#define QKV_SMEM 18432

__global__ void __launch_bounds__(320, 2) qkv_kernel(
        const __half* __restrict__ wq, const __half* __restrict__ y16,
        const float* __restrict__ bd, const float* __restrict__ bb,
        const float* __restrict__ bc,
        __half* __restrict__ vh, __half* __restrict__ qh, __half* __restrict__ kh) {
    extern __shared__ __align__(16) char smc[];
    const uint32_t smb = smem_u32(smc);
    const int tid = threadIdx.x, lane = tid & 31, wid = tid >> 5;
    const int b = blockIdx.y;
    const int n0 = blockIdx.x * 64;
    const int g = lane >> 3;

    for (int idx = tid; idx < 1024; idx += 320) {
        int ch = idx >> 3, seg = idx & 7;
        CP_ASYNC16(smb + ch * 144 + seg * 16,
                   y16 + ((size_t)b * 128 + ch) * NPIX + n0 + seg * 8);
    }
    CP_COMMIT();

    const int mt = wid;
    // Load A fragments from gmem while B stages (coalesced 16B per lane).
    uint32_t afr[8][4];
    const uint4* wq4 = (const uint4*)wq;
#pragma unroll
    for (int ks = 0; ks < 8; ks++) {
        uint4 v = __ldg(&wq4[(mt * 8 + ks) * 32 + lane]);
        afr[ks][0] = v.x; afr[ks][1] = v.y; afr[ks][2] = v.z; afr[ks][3] = v.w;
    }

    float acc[8][4];
#pragma unroll
    for (int nt = 0; nt < 8; nt++)
#pragma unroll
        for (int r = 0; r < 4; r++) acc[nt][r] = 0.0f;

    CP_WAIT(0);
    __syncthreads();

    const uint32_t Bsm = smb;
#pragma unroll
    for (int ks = 0; ks < 8; ks++) {
#pragma unroll
        for (int t16 = 0; t16 < 4; t16++) {
            uint32_t bfr[4];
            ldsm4t(bfr, Bsm + (ks * 16 + (g & 1) * 8 + (lane & 7)) * 144
                       + (t16 * 16 + (g >> 1) * 8) * 2);
            mma_f16(acc[2 * t16],     afr[ks], bfr[0], bfr[1]);
            mma_f16(acc[2 * t16 + 1], afr[ks], bfr[2], bfr[3]);
        }
    }

    const int r0 = mt * 16 + (lane >> 2);
    if (mt < 8) {
        const float b0 = bd[r0], b8 = bd[r0 + 8];
        __half* v0 = vh + ((size_t)b * 128 + r0) * NPIX;
        __half* v8 = vh + ((size_t)b * 128 + r0 + 8) * NPIX;
#pragma unroll
        for (int nt = 0; nt < 8; nt++) {
            const int n = n0 + nt * 8 + 2 * (lane & 3);
            *(uint32_t*)(v0 + n) = ph2(acc[nt][0] + b0, acc[nt][1] + b0);
            *(uint32_t*)(v8 + n) = ph2(acc[nt][2] + b8, acc[nt][3] + b8);
        }
    } else {
        const bool isq = (mt == 8);
        const float* bias = isq ? bb : bc;
        __half* dst = isq ? qh : kh;
        const int d = lane >> 2;
        const float b0 = bias[d], b8 = bias[d + 8];
#pragma unroll
        for (int nt = 0; nt < 8; nt++) {
            const int n = n0 + nt * 8 + 2 * (lane & 3);
            __half* p0 = dst + ((size_t)b * NPIX + n) * 16;
            p0[d]      = __float2half(acc[nt][0] + b0);
            p0[16 + d] = __float2half(acc[nt][1] + b0);
            p0[d + 8]      = __float2half(acc[nt][2] + b8);
            p0[16 + d + 8] = __float2half(acc[nt][3] + b8);
        }
    }
}

// ---------------------------------------------------------------------------
// PAM flash attention: q-tile 64, 128-thread CTA, occ 3, double-buffered K/V.
// ---------------------------------------------------------------------------
#define ATT_SMEM 46080

__global__ void __launch_bounds__(128, 3) pam_attn_mma(
        const __half* __restrict__ qh, const __half* __restrict__ kh,
        const __half* __restrict__ vd,
        const __half* __restrict__ yhi, const __half* __restrict__ ylo,
        const float* __restrict__ alpha, __half* __restrict__ xp2) {
    extern __shared__ __align__(16) char smc[];
    const uint32_t smb = smem_u32(smc);
    const uint32_t Qb  = smb;
    const uint32_t Kb0 = smb + 3072;
    const uint32_t Vb0 = smb + 9216;

    const int tid = threadIdx.x, lane = tid & 31, wid = tid >> 5;
    const int b = blockIdx.y;
    const int n0 = blockIdx.x * 64;
    const int qbase = wid * 16;

    const int g = lane >> 3, r8 = lane & 7;
    const uint32_t qoff = (uint32_t)(((g & 1) * 8 + r8) * 48 + (g >> 1) * 16);
    const uint32_t koff = (uint32_t)(((g >> 1) * 8 + r8) * 48 + (g & 1) * 16);
    const uint32_t voff = (uint32_t)(((g >> 1) * 8 + r8) * 144 + (g & 1) * 16);

    auto stageKV = [&](int t, int buf) {
        const int k0 = t * 64;
        {
            int row = tid >> 1, h = tid & 1;
            CP_ASYNC16(Kb0 + buf * 3072 + row * 48 + h * 16,
                       kh + ((size_t)b * NPIX + k0 + row) * 16 + h * 8);
        }
#pragma unroll
        for (int t4 = 0; t4 < 8; t4++) {
            int idx = tid + t4 * 128;
            int ch = idx >> 3, c = idx & 7;
            CP_ASYNC16(Vb0 + buf * 18432 + ch * 144 + c * 16,
                       vd + ((size_t)b * 128 + ch) * NPIX + k0 + c * 8);
        }
        CP_COMMIT();
    };

    {
        int row = tid >> 1, h = tid & 1;
        CP_ASYNC16(Qb + row * 48 + h * 16,
                   qh + ((size_t)b * NPIX + n0 + row) * 16 + h * 8);
    }
    stageKV(0, 0);

    uint32_t qfr[4];
    float O[16][4];
#pragma unroll
    for (int nc = 0; nc < 16; nc++)
#pragma unroll
        for (int r = 0; r < 4; r++) O[nc][r] = 0.0f;
    float mrun0 = -1e30f, mrun1 = -1e30f, lrun0 = 0.0f, lrun1 = 0.0f;

    for (int t = 0; t < 64; t++) {
        const int buf = t & 1;
        CP_WAIT(0);
        __syncthreads();
        if (t + 1 < 64) stageKV(t + 1, buf ^ 1);
        if (t == 0) ldsm4(qfr, Qb + qbase * 48 + qoff);

        const uint32_t Kb = Kb0 + buf * 3072;
        const uint32_t Vb = Vb0 + buf * 18432;

        float S[8][4];
#pragma unroll
        for (int ks = 0; ks < 4; ks++) {
            uint32_t kb[4];
            ldsm4(kb, Kb + ks * 768 + koff);
#pragma unroll
            for (int r = 0; r < 4; r++) { S[2 * ks][r] = 0.0f; S[2 * ks + 1][r] = 0.0f; }
            mma_f16(S[2 * ks],     qfr, kb[0], kb[1]);
            mma_f16(S[2 * ks + 1], qfr, kb[2], kb[3]);
        }

        float tm0 = -1e30f, tm1 = -1e30f;
#pragma unroll
        for (int nt = 0; nt < 8; nt++) {
            tm0 = fmaxf(tm0, fmaxf(S[nt][0], S[nt][1]));
            tm1 = fmaxf(tm1, fmaxf(S[nt][2], S[nt][3]));
        }
        tm0 = fmaxf(tm0, __shfl_xor_sync(0xffffffffu, tm0, 1));
        tm0 = fmaxf(tm0, __shfl_xor_sync(0xffffffffu, tm0, 2));
        tm1 = fmaxf(tm1, __shfl_xor_sync(0xffffffffu, tm1, 1));
        tm1 = fmaxf(tm1, __shfl_xor_sync(0xffffffffu, tm1, 2));
        const float mn0 = fmaxf(mrun0, tm0), mn1 = fmaxf(mrun1, tm1);
        const float f0 = __expf(mrun0 - mn0), f1 = __expf(mrun1 - mn1);
        mrun0 = mn0; mrun1 = mn1;

        float ts0 = 0.0f, ts1 = 0.0f;
        uint32_t afr[4][4];
#pragma unroll
        for (int j = 0; j < 4; j++) {
            float p00 = __expf(S[2 * j][0] - mn0), p01 = __expf(S[2 * j][1] - mn0);
            float p10 = __expf(S[2 * j][2] - mn1), p11 = __expf(S[2 * j][3] - mn1);
            float q00 = __expf(S[2 * j + 1][0] - mn0), q01 = __expf(S[2 * j + 1][1] - mn0);
            float q10 = __expf(S[2 * j + 1][2] - mn1), q11 = __expf(S[2 * j + 1][3] - mn1);
            ts0 += (p00 + p01) + (q00 + q01);
            ts1 += (p10 + p11) + (q10 + q11);
            afr[j][0] = ph2(p00, p01);
            afr[j][1] = ph2(p10, p11);
            afr[j][2] = ph2(q00, q01);
            afr[j][3] = ph2(q10, q11);
        }
        ts0 += __shfl_xor_sync(0xffffffffu, ts0, 1);
        ts0 += __shfl_xor_sync(0xffffffffu, ts0, 2);
        ts1 += __shfl_xor_sync(0xffffffffu, ts1, 1);
        ts1 += __shfl_xor_sync(0xffffffffu, ts1, 2);
        lrun0 = lrun0 * f0 + ts0;
        lrun1 = lrun1 * f1 + ts1;

#pragma unroll
        for (int nc = 0; nc < 16; nc++) {
            O[nc][0] *= f0; O[nc][1] *= f0;
            O[nc][2] *= f1; O[nc][3] *= f1;
        }

#pragma unroll
        for (int j = 0; j < 4; j++) {
            const uint32_t vb_j = Vb + j * 32 + voff;
#pragma unroll
            for (int p = 0; p < 8; p++) {
                uint32_t vb[4];
                ldsm4(vb, vb_j + p * 2304);
                mma_f16(O[2 * p],     afr[j], vb[0], vb[1]);
                mma_f16(O[2 * p + 1], afr[j], vb[2], vb[3]);
            }
        }
    }

    const float linv0 = 1.0f / lrun0, linv1 = 1.0f / lrun1;
    const float a = alpha[0];
    const int px0 = n0 + qbase + (lane >> 2);
    const int px1 = px0 + 8;
    __half* dst0 = xp2 + (((size_t)b * XP_H + (px0 >> 6) + 1) * XP_H + (px0 & 63) + 1) * CI;
    __half* dst1 = xp2 + (((size_t)b * XP_H + (px1 >> 6) + 1) * XP_H + (px1 & 63) + 1) * CI;
#pragma unroll
    for (int nc = 0; nc < 16; nc++) {
        const int ch = nc * 8 + 2 * (lane & 3);
        const __half* hp = yhi + ((size_t)b * 128 + ch) * NPIX;
        const __half* lp = ylo + ((size_t)b * 128 + ch) * NPIX;
        float ya0 = __half2float(hp[px0]) + __half2float(lp[px0]);
        float yb0 = __half2float(hp[NPIX + px0]) + __half2float(lp[NPIX + px0]);
        float ya1 = __half2float(hp[px1]) + __half2float(lp[px1]);
        float yb1 = __half2float(hp[NPIX + px1]) + __half2float(lp[NPIX + px1]);
        *(uint32_t*)(dst0 + ch) = ph2(fmaf(a, O[nc][0] * linv0, ya0),
                                      fmaf(a, O[nc][1] * linv0, yb0));
        *(uint32_t*)(dst1 + ch) = ph2(fmaf(a, O[nc][2] * linv1, ya1),
                                      fmaf(a, O[nc][3] * linv1, yb1));
    }
}

// ---------------------------------------------------------------------------
// CAM gram matrix via fp16 hi/lo split MMA, split-K partials.
// ---------------------------------------------------------------------------
#define CAME_SMEM 36864

__global__ void __launch_bounds__(256, 2) cam_energy_mma(
        const __half* __restrict__ yhi, const __half* __restrict__ ylo,
        float* __restrict__ epart) {
    extern __shared__ __align__(16) char smc[];
    const uint32_t smb = smem_u32(smc);
    const int tid = threadIdx.x, lane = tid & 31, wid = tid >> 5;
    const int warp_m = wid >> 2, warp_n = wid & 3;
    const int b = blockIdx.y, ksid = blockIdx.x;
    const int g = lane >> 3, r8 = lane & 7;

    float acc[4][4][4];
#pragma unroll
    for (int mt = 0; mt < 4; mt++)
#pragma unroll
        for (int nt = 0; nt < 4; nt++)
#pragma unroll
            for (int r = 0; r < 4; r++) acc[mt][nt][r] = 0.0f;

    for (int chunk = 0; chunk < 4; chunk++) {
        const int k0 = ksid * 256 + chunk * 64;
        __syncthreads();
#pragma unroll
        for (int t = 0; t < 4; t++) {
            int idx = tid + t * 256;
            int ch = idx >> 3, seg = idx & 7;
            CP_ASYNC16(smb + ch * 144 + seg * 16,
                       yhi + ((size_t)b * 128 + ch) * NPIX + k0 + seg * 8);
            CP_ASYNC16(smb + 18432 + ch * 144 + seg * 16,
                       ylo + ((size_t)b * 128 + ch) * NPIX + k0 + seg * 8);
        }
        CP_COMMIT();
        CP_WAIT(0);
        __syncthreads();

#pragma unroll
        for (int ks = 0; ks < 4; ks++) {
            uint32_t ahi[4][4], alo[4][4];
#pragma unroll
            for (int mt = 0; mt < 4; mt++) {
                const uint32_t arow = (warp_m * 64 + mt * 16 + (g & 1) * 8 + r8) * 144
                                      + ks * 32 + (g >> 1) * 16;
                ldsm4(ahi[mt], smb + arow);
                ldsm4(alo[mt], smb + 18432 + arow);
            }
            uint32_t bhi[2][4], blo[2][4];
#pragma unroll
            for (int t16 = 0; t16 < 2; t16++) {
                const uint32_t brow = (warp_n * 32 + t16 * 16 + (g >> 1) * 8 + r8) * 144
                                      + ks * 32 + (g & 1) * 16;
                ldsm4(bhi[t16], smb + brow);
                ldsm4(blo[t16], smb + 18432 + brow);
            }
#pragma unroll
            for (int mt = 0; mt < 4; mt++)
#pragma unroll
                for (int t16 = 0; t16 < 2; t16++) {
                    mma_f16(acc[mt][2 * t16],     ahi[mt], bhi[t16][0], bhi[t16][1]);
                    mma_f16(acc[mt][2 * t16 + 1], ahi[mt], bhi[t16][2], bhi[t16][3]);
                    mma_f16(acc[mt][2 * t16],     ahi[mt], blo[t16][0], blo[t16][1]);
                    mma_f16(acc[mt][2 * t16 + 1], ahi[mt], blo[t16][2], blo[t16][3]);
                    mma_f16(acc[mt][2 * t16],     alo[mt], bhi[t16][0], bhi[t16][1]);
                    mma_f16(acc[mt][2 * t16 + 1], alo[mt], bhi[t16][2], bhi[t16][3]);
                }
        }
    }

    float* ep = epart + (((size_t)ksid * BATCH + b) * 128) * 128;
#pragma unroll
    for (int mt = 0; mt < 4; mt++) {
        const int c0 = warp_m * 64 + mt * 16 + (lane >> 2);
#pragma unroll
        for (int nt = 0; nt < 4; nt++) {
            const int d = warp_n * 32 + nt * 8 + 2 * (lane & 3);
            *(float2*)(ep + (size_t)c0 * 128 + d) = make_float2(acc[mt][nt][0], acc[mt][nt][1]);
            *(float2*)(ep + (size_t)(c0 + 8) * 128 + d) = make_float2(acc[mt][nt][2], acc[mt][nt][3]);
        }
    }
}

// ---------------------------------------------------------------------------
// CAM softmax of (rowmax - E), reducing the KSPLIT partials -> fp16 attn
// ---------------------------------------------------------------------------
__global__ void cam_softmax_kernel(const float* __restrict__ epart,
                                   __half* __restrict__ attn) {
    const int row = blockIdx.x;
    const int tid = threadIdx.x;
    __shared__ float red[4];

    float e = 0.0f;
#pragma unroll
    for (int s = 0; s < KSPLIT; s++)
        e += epart[((size_t)s * 1024 + row) * 128 + tid];

    float m = e;
#pragma unroll
    for (int off = 16; off; off >>= 1) m = fmaxf(m, __shfl_xor_sync(0xffffffff, m, off));
    if ((tid & 31) == 0) red[tid >> 5] = m;
    __syncthreads();
    float mx = fmaxf(fmaxf(red[0], red[1]), fmaxf(red[2], red[3]));
    float e2 = mx - e;
    __syncthreads();

    float m2 = e2;
#pragma unroll
    for (int off = 16; off; off >>= 1) m2 = fmaxf(m2, __shfl_xor_sync(0xffffffff, m2, off));
    if ((tid & 31) == 0) red[tid >> 5] = m2;
    __syncthreads();
    m2 = fmaxf(fmaxf(red[0], red[1]), fmaxf(red[2], red[3]));
    float p = __expf(e2 - m2);
    __syncthreads();

    float s = p;
#pragma unroll
    for (int off = 16; off; off >>= 1) s += __shfl_xor_sync(0xffffffff, s, off);
    if ((tid & 31) == 0) red[tid >> 5] = s;
    __syncthreads();
    s = red[0] + red[1] + red[2] + red[3];

    attn[(size_t)row * 128 + tid] = __float2half(p / s);
}

// ---------------------------------------------------------------------------
// CAM feature via fp16 MMA -> fp16 padded NHWC; residual from hi+lo.
// ---------------------------------------------------------------------------
#define CAMF_SMEM 53248

__global__ void __launch_bounds__(256, 1) cam_feat_mma(
        const __half* __restrict__ attn16,
        const __half* __restrict__ yhi, const __half* __restrict__ ylo,
        const float* __restrict__ beta, __half* __restrict__ xp2) {
    extern __shared__ __align__(16) char smc[];
    const uint32_t smb = smem_u32(smc);
    const int tid = threadIdx.x, lane = tid & 31, wid = tid >> 5;
    const int b = blockIdx.y;
    const int n0 = blockIdx.x * 64;
    const int g = lane >> 3;

#pragma unroll
    for (int t = 0; t < 8; t++) {
        int idx = tid + t * 256;
        int c = idx >> 4, seg = idx & 15;
        CP_ASYNC16(smb + c * 272 + seg * 16,
                   attn16 + ((size_t)b * 128 + c) * 128 + seg * 8);
    }
#pragma unroll
    for (int t = 0; t < 4; t++) {
        int idx = tid + t * 256;
        int ch = idx >> 3, seg = idx & 7;
        CP_ASYNC16(smb + 34816 + ch * 144 + seg * 16,
                   yhi + ((size_t)b * 128 + ch) * NPIX + n0 + seg * 8);
    }
    CP_COMMIT();
    CP_WAIT(0);
    __syncthreads();

    const int mt = wid;
    float acc[8][4];
#pragma unroll
    for (int nt = 0; nt < 8; nt++)
#pragma unroll
        for (int r = 0; r < 4; r++) acc[nt][r] = 0.0f;

    const uint32_t Bsm = smb + 34816;
#pragma unroll
    for (int ks = 0; ks < 8; ks++) {
        uint32_t afr[4];
        ldsm4(afr, smb + (mt * 16 + (g & 1) * 8 + (lane & 7)) * 272
                  + ks * 32 + (g >> 1) * 16);
#pragma unroll
        for (int t16 = 0; t16 < 4; t16++) {
            uint32_t bfr[4];
            ldsm4t(bfr, Bsm + (ks * 16 + (g & 1) * 8 + (lane & 7)) * 144
                       + (t16 * 16 + (g >> 1) * 8) * 2);
            mma_f16(acc[2 * t16],     afr, bfr[0], bfr[1]);
            mma_f16(acc[2 * t16 + 1], afr, bfr[2], bfr[3]);
        }
    }

    const float bet = beta[0];
    const int c0 = mt * 16 + (lane >> 2);
#pragma unroll
    for (int nt = 0; nt < 8; nt++) {
        const int n = n0 + nt * 8 + 2 * (lane & 3);
        const __half* h0p = yhi + ((size_t)b * 128 + c0) * NPIX;
        const __half* l0p = ylo + ((size_t)b * 128 + c0) * NPIX;
        float y00 = __half2float(h0p[n]) + __half2float(l0p[n]);
        float y01 = __half2float(h0p[n + 1]) + __half2float(l0p[n + 1]);
        float y80 = __half2float(h0p[8 * NPIX + n]) + __half2float(l0p[8 * NPIX + n]);
        float y81 = __half2float(h0p[8 * NPIX + n + 1]) + __half2float(l0p[8 * NPIX + n + 1]);
        __half* p0 = xp2 + (((size_t)b * XP_H + (n >> 6) + 1) * XP_H + (n & 63) + 1) * CI;
        __half* p1 = p0 + CI;
        p0[c0]     = __float2half(fmaf(bet, acc[nt][0], y00));
        p1[c0]     = __float2half(fmaf(bet, acc[nt][1], y01));
        p0[c0 + 8] = __float2half(fmaf(bet, acc[nt][2], y80));
        p1[c0 + 8] = __float2half(fmaf(bet, acc[nt][3], y81));
    }
}

// ---------------------------------------------------------------------------
// Final heads via one fused fp16 MMA:  A[64x256] @ [fp;fc](256 x 64px tile).
// A fragments loaded directly from frag-packed gmem; smem = B only (36864 B).
// ---------------------------------------------------------------------------
#define FIN_SMEM 36864

__global__ void __launch_bounds__(128, 3) final_mma(
        const __half* __restrict__ wfin,
        const __half* __restrict__ fp, const __half* __restrict__ fc,
        const float* __restrict__ bout, const float* __restrict__ bp3,
        const float* __restrict__ bc3, float* __restrict__ out) {
    extern __shared__ __align__(16) char smc[];
    const uint32_t smb = smem_u32(smc);
    const int tid = threadIdx.x, lane = tid & 31, wid = tid >> 5;
    const int b = blockIdx.y;
    const int n0 = blockIdx.x * 64;
    const int g = lane >> 3;

#pragma unroll
    for (int t = 0; t < 16; t++) {
        int idx = tid + t * 128;
        int ch = idx >> 3, seg = idx & 7;
        const __half* src = (ch < 128)
            ? fp + ((size_t)b * 128 + ch) * NPIX + n0 + seg * 8
            : fc + ((size_t)b * 128 + (ch - 128)) * NPIX + n0 + seg * 8;
        CP_ASYNC16(smb + ch * 144 + seg * 16, src);
    }
    CP_COMMIT();

    const int mt = wid;
    uint32_t afr[16][4];
    const uint4* wf4 = (const uint4*)wfin;
#pragma unroll
    for (int ks = 0; ks < 16; ks++) {
        uint4 v = __ldg(&wf4[(mt * 16 + ks) * 32 + lane]);
        afr[ks][0] = v.x; afr[ks][1] = v.y; afr[ks][2] = v.z; afr[ks][3] = v.w;
    }

    float acc[8][4];
#pragma unroll
    for (int nt = 0; nt < 8; nt++)
#pragma unroll
        for (int r = 0; r < 4; r++) acc[nt][r] = 0.0f;

    CP_WAIT(0);
    __syncthreads();

    const uint32_t Bsm = smb;
#pragma unroll
    for (int ks = 0; ks < 16; ks++) {
#pragma unroll
        for (int t16 = 0; t16 < 4; t16++) {
            uint32_t bfr[4];
            ldsm4t(bfr, Bsm + (ks * 16 + (g & 1) * 8 + (lane & 7)) * 144
                       + (t16 * 16 + (g >> 1) * 8) * 2);
            mma_f16(acc[2 * t16],     afr[ks], bfr[0], bfr[1]);
            mma_f16(acc[2 * t16 + 1], afr[ks], bfr[2], bfr[3]);
        }
    }

    const size_t SEG = (size_t)BATCH * NC * NPIX;
    auto emit = [&](int row, int px, float v) {
        if (row >= 57) return;
        float bias;
        size_t base;
        if (row < 19)      { bias = bout[row]; base = ((size_t)b * NC + row) * NPIX; }
        else if (row < 38) { bias = bp3[row - 19]; base = SEG + ((size_t)b * NC + row - 19) * NPIX; }
        else               { bias = bc3[row - 38]; base = 2 * SEG + ((size_t)b * NC + row - 38) * NPIX; }
        out[base + px] = sigmoidf_(v + bias);
    };

    const int r0 = mt * 16 + (lane >> 2);
#pragma unroll
    for (int nt = 0; nt < 8; nt++) {
        const int px = n0 + nt * 8 + 2 * (lane & 3);
        emit(r0,     px,     acc[nt][0]);
        emit(r0,     px + 1, acc[nt][1]);
        emit(r0 + 8, px,     acc[nt][2]);
        emit(r0 + 8, px + 1, acc[nt][3]);
    }
}

// ---------------------------------------------------------------------------
// Streams / events (created once at program load)
// ---------------------------------------------------------------------------
namespace {
struct StreamInit {
    cudaStream_t s1;
    cudaEvent_t e0, e1, e2, e3, e4, e5, e6;
    StreamInit() {
        cudaStreamCreateWithFlags(&s1, cudaStreamNonBlocking);
        cudaEventCreateWithFlags(&e0, cudaEventDisableTiming);
        cudaEventCreateWithFlags(&e1, cudaEventDisableTiming);
        cudaEventCreateWithFlags(&e2, cudaEventDisableTiming);
        cudaEventCreateWithFlags(&e3, cudaEventDisableTiming);
        cudaEventCreateWithFlags(&e4, cudaEventDisableTiming);
        cudaEventCreateWithFlags(&e5, cudaEventDisableTiming);
        cudaEventCreateWithFlags(&e6, cudaEventDisableTiming);
    }
};
StreamInit g_str;
}

// ---------------------------------------------------------------------------
// Launch
// ---------------------------------------------------------------------------
extern "C" void kernel_launch(void* const* d_in, const int* in_sizes, int n_in,
                              void* d_out, int out_size) {
    const float* x    = (const float*)d_in[0];
    const float* Wp1  = (const float*)d_in[1];
    const float* bnp1 = (const float*)d_in[2];
    const float* Wc1  = (const float*)d_in[3];
    const float* bnc1 = (const float*)d_in[4];
    const float* Wb   = (const float*)d_in[5];
    const float* bb   = (const float*)d_in[6];
    const float* Wc   = (const float*)d_in[7];
    const float* bc   = (const float*)d_in[8];
    const float* Wd   = (const float*)d_in[9];
    const float* bd   = (const float*)d_in[10];
    const float* alpha= (const float*)d_in[11];
    const float* beta = (const float*)d_in[12];
    const float* Wp2  = (const float*)d_in[13];
    const float* bnp2 = (const float*)d_in[14];
    const float* Wc2  = (const float*)d_in[15];
    const float* bnc2 = (const float*)d_in[16];
    const float* Wout = (const float*)d_in[17];
    const float* bout = (const float*)d_in[18];
    const float* Wp3  = (const float*)d_in[19];
    const float* bp3  = (const float*)d_in[20];
    const float* Wc3  = (const float*)d_in[21];
    const float* bc3  = (const float*)d_in[22];
    float* out = (float*)d_out;

    float* epart;
    __half *featp1h, *featp1lo, *featc1h, *featc1lo, *qh, *kh, *vd, *attn16;
    __half *xpad, *xp2a, *xp2b, *wf1, *wf2, *wqkv, *wfin;
    cudaGetSymbolAddress((void**)&featp1h,  g_featp1h);
    cudaGetSymbolAddress((void**)&featp1lo, g_featp1lo);
    cudaGetSymbolAddress((void**)&featc1h,  g_featc1h);
    cudaGetSymbolAddress((void**)&featc1lo, g_featc1lo);
    cudaGetSymbolAddress((void**)&qh,       g_qh);
    cudaGetSymbolAddress((void**)&kh,       g_kh);
    cudaGetSymbolAddress((void**)&vd,       g_vd);
    cudaGetSymbolAddress((void**)&epart,    g_epart);
    cudaGetSymbolAddress((void**)&attn16,   g_attn16);
    cudaGetSymbolAddress((void**)&xpad,     g_xpad);
    cudaGetSymbolAddress((void**)&xp2a,     g_xp2a);
    cudaGetSymbolAddress((void**)&xp2b,     g_xp2b);
    cudaGetSymbolAddress((void**)&wf1,      g_wf16_1);
    cudaGetSymbolAddress((void**)&wf2,      g_wf16_2);
    cudaGetSymbolAddress((void**)&wqkv,     g_wqkv);
    cudaGetSymbolAddress((void**)&wfin,     g_wfinal);

    cudaFuncSetAttribute(conv_mma_kernel<512>,
                         cudaFuncAttributeMaxDynamicSharedMemorySize, CONV_SMEM);
    cudaFuncSetAttribute(conv_mma_kernel<128>,
                         cudaFuncAttributeMaxDynamicSharedMemorySize, CONV_SMEM);
    cudaFuncSetAttribute(pam_attn_mma,
                         cudaFuncAttributeMaxDynamicSharedMemorySize, ATT_SMEM);
    cudaFuncSetAttribute(pam_attn_mma,
                         cudaFuncAttributePreferredSharedMemoryCarveout, 100);
    cudaFuncSetAttribute(qkv_kernel,
                         cudaFuncAttributeMaxDynamicSharedMemorySize, QKV_SMEM);
    cudaFuncSetAttribute(cam_energy_mma,
                         cudaFuncAttributeMaxDynamicSharedMemorySize, CAME_SMEM);
    cudaFuncSetAttribute(cam_feat_mma,
                         cudaFuncAttributeMaxDynamicSharedMemorySize, CAMF_SMEM);
    cudaFuncSetAttribute(final_mma,
                         cudaFuncAttributeMaxDynamicSharedMemorySize, FIN_SMEM);

    cudaStream_t s1 = g_str.s1;

    // Fork s1 off the main stream
    cudaEventRecord(g_str.e0, 0);
    cudaStreamWaitEvent(s1, g_str.e0, 0);

    // s0: interior packing
    pack_x_kernel<<<dim3(64, BATCH), 256>>>(x, xpad);
    cudaEventRecord(g_str.e5, 0);   // pack_x done

    // s1: consolidated borders + weight packing (parallel with pack_x)
    zero_borders_all<<<dim3(XP_H, BATCH, 3), 256, 0, s1>>>(xpad, xp2a, xp2b);
    pack_w16<<<dim3(144, 2), 256, 0, s1>>>(Wp1, Wc1, wf1, CIN);
    cudaEventRecord(g_str.e1, s1);  // borders + wf1 ready
    pack_small<<<144, 256, 0, s1>>>(Wd, Wb, Wc, wqkv, Wout, Wp3, Wc3, wfin);
    cudaEventRecord(g_str.e4, s1);  // wqkv + wfinal ready (for qkv)
    pack_w16<<<dim3(36, 2), 256, 0, s1>>>(Wp2, Wc2, wf2, CI);
    cudaEventRecord(g_str.e6, s1);  // wf2 ready (for conv2)

    // s0: conv1-PAM FIRST (alone at full chip rate)
    cudaStreamWaitEvent(0, g_str.e1, 0);
    conv_mma_kernel<512><<<dim3(32, BATCH, 1), 256, CONV_SMEM>>>(
        xpad, xpad, wf1, bnp1, bnp1, featp1h, featp1h, featp1lo, featp1lo);
    cudaEventRecord(g_str.e2, 0);   // conv1-PAM done

    // s1: conv1-CAM + entire CAM chain (concurrent with PAM chain on s0)
    cudaStreamWaitEvent(s1, g_str.e2, 0);
    cudaStreamWaitEvent(s1, g_str.e5, 0);
    conv_mma_kernel<512><<<dim3(32, BATCH, 1), 256, CONV_SMEM, s1>>>(
        xpad, xpad, wf1 + 144 * 4096, bnc1, bnc1, featc1h, featc1h, featc1lo, featc1lo);
    cam_energy_mma<<<dim3(KSPLIT, BATCH), 256, CAME_SMEM, s1>>>(featc1h, featc1lo, epart);
    cam_softmax_kernel<<<BATCH * 128, 128, 0, s1>>>(epart, attn16);
    cam_feat_mma<<<dim3(64, BATCH), 256, CAMF_SMEM, s1>>>(
        attn16, featc1h, featc1lo, beta, xp2b);
    conv_mma_kernel<128><<<dim3(32, BATCH, 1), 256, CONV_SMEM, s1>>>(
        xp2b, xp2b, wf2 + 36 * 4096, bnc2, bnc2, featc1h, featc1h, nullptr, nullptr);
    cudaEventRecord(g_str.e3, s1);  // CAM branch fully done

    // s0: PAM chain (qkv waits only on pack_small)
    cudaStreamWaitEvent(0, g_str.e4, 0);
    qkv_kernel<<<dim3(64, BATCH), 320, QKV_SMEM>>>(
        wqkv, featp1h, bd, bb, bc, vd, qh, kh);
    pam_attn_mma<<<dim3(64, BATCH), 128, ATT_SMEM>>>(
        qh, kh, vd, featp1h, featp1lo, alpha, xp2a);
    cudaStreamWaitEvent(0, g_str.e6, 0);
    conv_mma_kernel<128><<<dim3(32, BATCH, 1), 256, CONV_SMEM>>>(
        xp2a, xp2a, wf2, bnp2, bnp2, featp1h, featp1h, nullptr, nullptr);

    // Join, then fused final heads
    cudaStreamWaitEvent(0, g_str.e3, 0);
    final_mma<<<dim3(64, BATCH), 128, FIN_SMEM>>>(
        wfin, featp1h, featc1h, bout, bp3, bc3, out);
}

// round 16
// speedup vs baseline: 1.0345x; 1.0082x over previous
#include <cuda_runtime.h>
#include <cuda_bf16.h>
#include <cuda_fp16.h>
#include <math.h>
#include <cstdint>

// ---------------------------------------------------------------------------
// Problem constants
// ---------------------------------------------------------------------------
#define BATCH 8
#define CIN   512
#define CI    128
#define CK    16
#define NC    19
#define NPIX  4096
#define FEAT_ELEMS (BATCH * CI * NPIX)
#define XP_H 66
#define KSPLIT 16
#define LOG2E 1.4426950408889634f

// ---------------------------------------------------------------------------
// Scratch (device globals)
// ---------------------------------------------------------------------------
__device__ __half g_featp1h[FEAT_ELEMS];
__device__ __half g_featp1lo[FEAT_ELEMS];
__device__ __half g_featc1h[FEAT_ELEMS];
__device__ __half g_featc1lo[FEAT_ELEMS];
__device__ __half g_qh[BATCH * NPIX * CK];
__device__ __half g_kh[BATCH * NPIX * CK];
__device__ __half g_vd[FEAT_ELEMS];
__device__ float  g_epart[KSPLIT * BATCH * CI * CI];
__device__ __half g_attn16[BATCH * CI * CI];
__device__ __half g_xpad[BATCH * XP_H * XP_H * CIN];
__device__ __half g_xp2a[BATCH * XP_H * XP_H * CI];
__device__ __half g_xp2b[BATCH * XP_H * XP_H * CI];
__device__ __half g_wf16_1[2 * 144 * 4096];
__device__ __half g_wf16_2[2 * 36 * 4096];
__device__ __half g_wqkv[10 * 8 * 32 * 8];
__device__ __half g_wfinal[4 * 16 * 32 * 8];

__device__ __forceinline__ float sigmoidf_(float x) {
    return 1.0f / (1.0f + __expf(-x));
}
__device__ __forceinline__ uint32_t smem_u32(const void* p) {
    uint32_t a;
    asm("{ .reg .u64 t; cvta.to.shared.u64 t, %1; cvt.u32.u64 %0, t; }" : "=r"(a) : "l"(p));
    return a;
}
__device__ __forceinline__ void mma_f16(float c[4], const uint32_t a[4], const uint32_t b0, const uint32_t b1) {
    asm volatile(
        "mma.sync.aligned.m16n8k16.row.col.f32.f16.f16.f32 "
        "{%0,%1,%2,%3}, {%4,%5,%6,%7}, {%8,%9}, {%0,%1,%2,%3};"
        : "+f"(c[0]), "+f"(c[1]), "+f"(c[2]), "+f"(c[3])
        : "r"(a[0]), "r"(a[1]), "r"(a[2]), "r"(a[3]), "r"(b0), "r"(b1));
}
__device__ __forceinline__ void ldsm4(uint32_t r[4], uint32_t addr) {
    asm volatile("ldmatrix.sync.aligned.m8n8.x4.shared.b16 {%0,%1,%2,%3}, [%4];"
                 : "=r"(r[0]), "=r"(r[1]), "=r"(r[2]), "=r"(r[3]) : "r"(addr));
}
__device__ __forceinline__ void ldsm4t(uint32_t r[4], uint32_t addr) {
    asm volatile("ldmatrix.sync.aligned.m8n8.x4.trans.shared.b16 {%0,%1,%2,%3}, [%4];"
                 : "=r"(r[0]), "=r"(r[1]), "=r"(r[2]), "=r"(r[3]) : "r"(addr));
}
#define CP_ASYNC16(dst, src) \
    asm volatile("cp.async.ca.shared.global [%0], [%1], 16;" :: "r"(dst), "l"(src))
#define CP_COMMIT() asm volatile("cp.async.commit_group;")
#define CP_WAIT(N)  asm volatile("cp.async.wait_group %0;" :: "n"(N))

__device__ __forceinline__ uint32_t ph2(float x, float y) {
    __half2 h = __floats2half2_rn(x, y);
    return *(uint32_t*)&h;
}
// Pack (lo, hi) floats to f16x2 and take 2^x on both halves (one MUFU op).
__device__ __forceinline__ uint32_t h2e2(float lo, float hi) {
    uint32_t h, r;
    asm("cvt.rn.f16x2.f32 %0, %1, %2;" : "=r"(h) : "f"(hi), "f"(lo));
    asm("ex2.approx.f16x2 %0, %1;" : "=r"(r) : "r"(h));
    return r;
}
__device__ __forceinline__ __half2 u2h2(uint32_t u) { return *(__half2*)&u; }

// ---------------------------------------------------------------------------
// Pack x: f32 NCHW -> fp16 NHWC padded
// ---------------------------------------------------------------------------
__global__ void pack_x_kernel(const float* __restrict__ x, __half* __restrict__ xp) {
    const int h = blockIdx.x, b = blockIdx.y, tid = threadIdx.x;
    __shared__ float s[32][65];
    for (int ci0 = 0; ci0 < CIN; ci0 += 32) {
        for (int idx = tid; idx < 32 * 64; idx += 256) {
            int ci_l = idx >> 6, w = idx & 63;
            s[ci_l][w] = x[(((size_t)b * CIN + ci0 + ci_l) * 64 + h) * 64 + w];
        }
        __syncthreads();
        for (int idx = tid; idx < 64 * 32; idx += 256) {
            int w = idx >> 5, ci_l = idx & 31;
            xp[(((size_t)b * XP_H + h + 1) * XP_H + w + 1) * CIN + ci0 + ci_l] =
                __float2half(s[ci_l][w]);
        }
        __syncthreads();
    }
}

// One launch zeroes the borders of all three padded buffers (z selects).
__global__ void zero_borders_all(__half* __restrict__ xpad,
                                 __half* __restrict__ xp2a,
                                 __half* __restrict__ xp2b) {
    const int hp = blockIdx.x, b = blockIdx.y, z = blockIdx.z, tid = threadIdx.x;
    __half* base = (z == 0) ? xpad : (z == 1 ? xp2a : xp2b);
    const int C = (z == 0) ? CIN : CI;
    __half* row = base + ((size_t)b * XP_H + hp) * XP_H * C;
    const __half zz = __float2half(0.0f);
    if (hp == 0 || hp == XP_H - 1) {
        for (int idx = tid; idx < XP_H * C; idx += 256) row[idx] = zz;
    } else {
        for (int idx = tid; idx < C; idx += 256) {
            row[idx] = zz;
            row[(size_t)(XP_H - 1) * C + idx] = zz;
        }
    }
}

// ---------------------------------------------------------------------------
// Pack conv weights into m16n8k16 fp16 A-fragment order.
// ---------------------------------------------------------------------------
__global__ void pack_w16(const float* __restrict__ W0, const float* __restrict__ W1,
                         __half* __restrict__ wf, int CIN_T) {
    const int cpc = CIN_T / 32;
    const int chunk = blockIdx.x;
    const int kwh = chunk / cpc, cb = chunk % cpc;
    const float* W = blockIdx.y ? W1 : W0;
    __half* dst = wf + ((size_t)blockIdx.y * gridDim.x + chunk) * 4096;
    for (int t = 0; t < 16; t++) {
        int idx = threadIdx.x + t * 256;
        int j = idx & 7, lane = (idx >> 3) & 31, ks = (idx >> 8) & 1, mt = idx >> 9;
        int reg = j >> 1, h = j & 1;
        int co = mt * 16 + (lane >> 2) + (reg & 1) * 8;
        int ci = cb * 32 + ks * 16 + (lane & 3) * 2 + (reg >> 1) * 8 + h;
        dst[idx] = __float2half(W[((size_t)co * CIN_T + ci) * 9 + kwh]);
    }
}

// Parallel small-table pack: 144 CTAs x 256, 1 element/thread.
__global__ void pack_small(const float* __restrict__ Wd, const float* __restrict__ Wb,
                           const float* __restrict__ Wc, __half* __restrict__ dqkv,
                           const float* __restrict__ Wout, const float* __restrict__ Wp3,
                           const float* __restrict__ Wc3, __half* __restrict__ dfin) {
    int gi = blockIdx.x * 256 + threadIdx.x;
    if (gi < 20480) {
        int idx = gi;
        int j = idx & 7, lane = (idx >> 3) & 31, ks = (idx >> 8) & 7, mt = idx >> 11;
        int reg = j >> 1, h = j & 1;
        int row = mt * 16 + (lane >> 2) + (reg & 1) * 8;
        int col = ks * 16 + (lane & 3) * 2 + (reg >> 1) * 8 + h;
        float w;
        if (row < 128)      w = Wd[row * 128 + col];
        else if (row < 144) w = Wb[(row - 128) * 128 + col];
        else                w = Wc[(row - 144) * 128 + col];
        dqkv[idx] = __float2half(w);
    } else if (gi < 36864) {
        int idx = gi - 20480;
        int j = idx & 7, lane = (idx >> 3) & 31, ks = (idx >> 8) & 15, mt = idx >> 12;
        int reg = j >> 1, h = j & 1;
        int row = mt * 16 + (lane >> 2) + (reg & 1) * 8;
        int col = ks * 16 + (lane & 3) * 2 + (reg >> 1) * 8 + h;
        float w = 0.0f;
        if (col < 128) {
            if (row < 19)      w = Wout[row * 128 + col];
            else if (row < 38) w = Wp3[(row - 19) * 128 + col];
        } else {
            int c = col - 128;
            if (row < 19)      w = Wout[row * 128 + c];
            else if (row >= 38 && row < 57) w = Wc3[(row - 38) * 128 + c];
        }
        dfin[idx] = __float2half(w);
    }
}

// ---------------------------------------------------------------------------
// conv3x3 implicit GEMM, fp16 m16n8k16, halo-reuse B staging, fused BN+ReLU.
// ---------------------------------------------------------------------------
#define CONV_SMEM 91392
#define BPX 80

template<int CIN_T>
__global__ void __launch_bounds__(256, 2) conv_mma_kernel(
        const __half* __restrict__ xpA, const __half* __restrict__ xpB,
        const __half* __restrict__ wfrag,
        const float* __restrict__ bn0, const float* __restrict__ bn1,
        __half* __restrict__ o16_0, __half* __restrict__ o16_1,
        __half* __restrict__ olo_0, __half* __restrict__ olo_1) {
    constexpr int CPC = CIN_T / 32;
    constexpr int NS = CPC * 3;
    extern __shared__ __align__(16) char smc[];
    const uint32_t smb = smem_u32(smc);
    const uint32_t Boff = smb;
    const uint32_t Aoff = smb + 2 * 21120;

    const int tid = threadIdx.x, lane = tid & 31, wid = tid >> 5;
    const int warp_m = wid >> 2, warp_n = wid & 3;
    const int b = blockIdx.y, z = blockIdx.z;
    const int pxbase = blockIdx.x * 128;
    const int h0 = pxbase >> 6;
    const __half* xp = z ? xpB : xpA;
    const __half* Wf = wfrag + (size_t)z * (9 * CPC) * 4096;
    const float* bn = z ? bn1 : bn0;
    __half* o16 = z ? o16_1 : o16_0;
    __half* olo = z ? olo_1 : olo_0;
    const int g = lane >> 3;

    float acc[4][4][4];
#pragma unroll
    for (int mt = 0; mt < 4; mt++)
#pragma unroll
        for (int nt = 0; nt < 4; nt++)
#pragma unroll
            for (int r = 0; r < 4; r++) acc[mt][nt][r] = 0.0f;

    auto stageA = [&](int s, int buf) {
        const int cb = s / 3, kh = s % 3;
        const uint32_t Ad = Aoff + buf * 24576;
#pragma unroll
        for (int kw = 0; kw < 3; kw++) {
            const __half* src = Wf + (size_t)((kh * 3 + kw) * CPC + cb) * 4096;
#pragma unroll
            for (int t = 0; t < 2; t++) {
                int idx = tid + t * 256;
                CP_ASYNC16(Ad + kw * 8192 + idx * 16, src + idx * 8);
            }
        }
    };
    auto stageB = [&](int cb, int buf) {
        const uint32_t Bd = Boff + buf * 21120;
        const __half* base = xp + ((size_t)(b * XP_H + h0) * XP_H) * CIN_T + cb * 32;
        for (int idx = tid; idx < 1056; idx += 256) {
            int r = idx / 264, rem = idx % 264;
            int c = rem >> 2, q = rem & 3;
            CP_ASYNC16(Bd + (r * 66 + c) * BPX + q * 16,
                       base + ((size_t)r * XP_H + c) * CIN_T + q * 8);
        }
    };

    stageB(0, 0);
    stageA(0, 0);
    CP_COMMIT();

    for (int s = 0; s < NS; s++) {
        const int cb = s / 3, kh = s % 3;
        if (s + 1 < NS) {
            stageA(s + 1, (s + 1) & 1);
            if ((s + 1) % 3 == 0) stageB((s + 1) / 3, ((s + 1) / 3) & 1);
            CP_COMMIT();
            CP_WAIT(1);
        } else {
            CP_WAIT(0);
        }
        __syncthreads();

        const uint32_t Bh = Boff + (cb & 1) * 21120;
        const char* Ap = smc + 2 * 21120 + (s & 1) * 24576;
#pragma unroll
        for (int ks = 0; ks < 2; ks++) {
#pragma unroll
            for (int kw = 0; kw < 3; kw++) {
                uint32_t afr[4][4];
#pragma unroll
                for (int mt = 0; mt < 4; mt++) {
                    uint4 v = *(const uint4*)(Ap + kw * 8192 +
                        ((((warp_m * 4 + mt) * 2 + ks) * 32 + lane) << 4));
                    afr[mt][0] = v.x; afr[mt][1] = v.y; afr[mt][2] = v.z; afr[mt][3] = v.w;
                }
                uint32_t bfr[2][4];
#pragma unroll
                for (int t16 = 0; t16 < 2; t16++) {
                    const int n_row = warp_n * 32 + t16 * 16 + (g >> 1) * 8 + (lane & 7);
                    const int r = n_row >> 6, w = n_row & 63;
                    ldsm4(bfr[t16], Bh + ((r + kh) * 66 + w + kw) * BPX
                                      + ks * 32 + (g & 1) * 16);
                }
#pragma unroll
                for (int mt = 0; mt < 4; mt++)
#pragma unroll
                    for (int t16 = 0; t16 < 2; t16++) {
                        mma_f16(acc[mt][2 * t16],     afr[mt], bfr[t16][0], bfr[t16][1]);
                        mma_f16(acc[mt][2 * t16 + 1], afr[mt], bfr[t16][2], bfr[t16][3]);
                    }
            }
        }
        __syncthreads();
    }

#pragma unroll
    for (int mt = 0; mt < 4; mt++) {
        const int co = warp_m * 64 + mt * 16 + (lane >> 2);
        const float sc0 = bn[co],     sh0 = bn[128 + co];
        const float sc8 = bn[co + 8], sh8 = bn[136 + co];
#pragma unroll
        for (int nt = 0; nt < 4; nt++) {
            const int px = pxbase + warp_n * 32 + nt * 8 + 2 * (lane & 3);
            float v0x = fmaxf(acc[mt][nt][0] * sc0 + sh0, 0.0f);
            float v0y = fmaxf(acc[mt][nt][1] * sc0 + sh0, 0.0f);
            float v1x = fmaxf(acc[mt][nt][2] * sc8 + sh8, 0.0f);
            float v1y = fmaxf(acc[mt][nt][3] * sc8 + sh8, 0.0f);
            *(uint32_t*)(o16 + ((size_t)b * 128 + co) * NPIX + px) = ph2(v0x, v0y);
            *(uint32_t*)(o16 + ((size_t)b * 128 + co + 8) * NPIX + px) = ph2(v1x, v1y);
            if (olo) {
                float r0x = v0x - __half2float(__float2half(v0x));
                float r0y = v0y - __half2float(__float2half(v0y));
                float r1x = v1x - __half2float(__float2half(v1x));
                float r1y = v1y - __half2float(__float2half(v1y));
                *(uint32_t*)(olo + ((size_t)b * 128 + co) * NPIX + px) = ph2(r0x, r0y);
                *(uint32_t*)(olo + ((size_t)b * 128 + co + 8) * NPIX + px) = ph2(r1x, r1y);
            }
        }
    }
}

// ---------------------------------------------------------------------------
// QKV GEMM: [Wd;Wb;Wc](160x128) @ y16(128x4096) + bias.
// Q output pre-scaled by log2(e) so attention softmax can use ex2 directly.
// ---------------------------------------------------------------------------
#define QKV_SMEM 18432

__global__ void __launch_bounds__(320, 2) qkv_kernel(
        const __half* __restrict__ wq, const __half* __restrict__ y16,
        const float* __restrict__ bd, const float* __restrict__ bb,
        const float* __restrict__ bc,
        __half* __restrict__ vh, __half* __restrict__ qh, __half* __restrict__ kh) {
    extern __shared__ __align__(16) char smc[];
    const uint32_t smb = smem_u32(smc);
    const int tid = threadIdx.x, lane = tid & 31, wid = tid >> 5;
    const int b = blockIdx.y;
    const int n0 = blockIdx.x * 64;
    const int g = lane >> 3;

    for (int idx = tid; idx < 1024; idx += 320) {
        int ch = idx >> 3, seg = idx & 7;
        CP_ASYNC16(smb + ch * 144 + seg * 16,
                   y16 + ((size_t)b * 128 + ch) * NPIX + n0 + seg * 8);
    }
    CP_COMMIT();

    const int mt = wid;
    uint32_t afr[8][4];
    const uint4* wq4 = (const uint4*)wq;
#pragma unroll
    for (int ks = 0; ks < 8; ks++) {
        uint4 v = __ldg(&wq4[(mt * 8 + ks) * 32 + lane]);
        afr[ks][0] = v.x; afr[ks][1] = v.y; afr[ks][2] = v.z; afr[ks][3] = v.w;
    }

    float acc[8][4];
#pragma unroll
    for (int nt = 0; nt < 8; nt++)
#pragma unroll
        for (int r = 0; r < 4; r++) acc[nt][r] = 0.0f;

    CP_WAIT(0);
    __syncthreads();

    const uint32_t Bsm = smb;
#pragma unroll
    for (int ks = 0; ks < 8; ks++) {
#pragma unroll
        for (int t16 = 0; t16 < 4; t16++) {
            uint32_t bfr[4];
            ldsm4t(bfr, Bsm + (ks * 16 + (g & 1) * 8 + (lane & 7)) * 144
                       + (t16 * 16 + (g >> 1) * 8) * 2);
            mma_f16(acc[2 * t16],     afr[ks], bfr[0], bfr[1]);
            mma_f16(acc[2 * t16 + 1], afr[ks], bfr[2], bfr[3]);
        }
    }

    const int r0 = mt * 16 + (lane >> 2);
    if (mt < 8) {
        const float b0 = bd[r0], b8 = bd[r0 + 8];
        __half* v0 = vh + ((size_t)b * 128 + r0) * NPIX;
        __half* v8 = vh + ((size_t)b * 128 + r0 + 8) * NPIX;
#pragma unroll
        for (int nt = 0; nt < 8; nt++) {
            const int n = n0 + nt * 8 + 2 * (lane & 3);
            *(uint32_t*)(v0 + n) = ph2(acc[nt][0] + b0, acc[nt][1] + b0);
            *(uint32_t*)(v8 + n) = ph2(acc[nt][2] + b8, acc[nt][3] + b8);
        }
    } else {
        const bool isq = (mt == 8);
        const float* bias = isq ? bb : bc;
        __half* dst = isq ? qh : kh;
        const float qs = isq ? LOG2E : 1.0f;   // pre-scale q by log2(e)
        const int d = lane >> 2;
        const float b0 = bias[d], b8 = bias[d + 8];
#pragma unroll
        for (int nt = 0; nt < 8; nt++) {
            const int n = n0 + nt * 8 + 2 * (lane & 3);
            __half* p0 = dst + ((size_t)b * NPIX + n) * 16;
            p0[d]      = __float2half((acc[nt][0] + b0) * qs);
            p0[16 + d] = __float2half((acc[nt][1] + b0) * qs);
            p0[d + 8]      = __float2half((acc[nt][2] + b8) * qs);
            p0[16 + d + 8] = __float2half((acc[nt][3] + b8) * qs);
        }
    }
}

// ---------------------------------------------------------------------------
// PAM flash attention: q-tile 64, 128-thread CTA, occ 3, double-buffered K/V.
// Softmax in log2 domain (Q pre-scaled by log2e): ex2.approx.f16x2 for p-pairs,
// HADD2 row sums, warp-voted skip of the O rescale when max is unchanged.
// ---------------------------------------------------------------------------
#define ATT_SMEM 46080

__global__ void __launch_bounds__(128, 3) pam_attn_mma(
        const __half* __restrict__ qh, const __half* __restrict__ kh,
        const __half* __restrict__ vd,
        const __half* __restrict__ yhi, const __half* __restrict__ ylo,
        const float* __restrict__ alpha, __half* __restrict__ xp2) {
    extern __shared__ __align__(16) char smc[];
    const uint32_t smb = smem_u32(smc);
    const uint32_t Qb  = smb;
    const uint32_t Kb0 = smb + 3072;
    const uint32_t Vb0 = smb + 9216;

    const int tid = threadIdx.x, lane = tid & 31, wid = tid >> 5;
    const int b = blockIdx.y;
    const int n0 = blockIdx.x * 64;
    const int qbase = wid * 16;

    const int g = lane >> 3, r8 = lane & 7;
    const uint32_t qoff = (uint32_t)(((g & 1) * 8 + r8) * 48 + (g >> 1) * 16);
    const uint32_t koff = (uint32_t)(((g >> 1) * 8 + r8) * 48 + (g & 1) * 16);
    const uint32_t voff = (uint32_t)(((g >> 1) * 8 + r8) * 144 + (g & 1) * 16);

    auto stageKV = [&](int t, int buf) {
        const int k0 = t * 64;
        {
            int row = tid >> 1, h = tid & 1;
            CP_ASYNC16(Kb0 + buf * 3072 + row * 48 + h * 16,
                       kh + ((size_t)b * NPIX + k0 + row) * 16 + h * 8);
        }
#pragma unroll
        for (int t4 = 0; t4 < 8; t4++) {
            int idx = tid + t4 * 128;
            int ch = idx >> 3, c = idx & 7;
            CP_ASYNC16(Vb0 + buf * 18432 + ch * 144 + c * 16,
                       vd + ((size_t)b * 128 + ch) * NPIX + k0 + c * 8);
        }
        CP_COMMIT();
    };

    {
        int row = tid >> 1, h = tid & 1;
        CP_ASYNC16(Qb + row * 48 + h * 16,
                   qh + ((size_t)b * NPIX + n0 + row) * 16 + h * 8);
    }
    stageKV(0, 0);

    uint32_t qfr[4];
    float O[16][4];
#pragma unroll
    for (int nc = 0; nc < 16; nc++)
#pragma unroll
        for (int r = 0; r < 4; r++) O[nc][r] = 0.0f;
    float mrun0 = -1e30f, mrun1 = -1e30f, lrun0 = 0.0f, lrun1 = 0.0f;

    for (int t = 0; t < 64; t++) {
        const int buf = t & 1;
        CP_WAIT(0);
        __syncthreads();
        if (t + 1 < 64) stageKV(t + 1, buf ^ 1);
        if (t == 0) ldsm4(qfr, Qb + qbase * 48 + qoff);

        const uint32_t Kb = Kb0 + buf * 3072;
        const uint32_t Vb = Vb0 + buf * 18432;

        float S[8][4];
#pragma unroll
        for (int ks = 0; ks < 4; ks++) {
            uint32_t kb[4];
            ldsm4(kb, Kb + ks * 768 + koff);
#pragma unroll
            for (int r = 0; r < 4; r++) { S[2 * ks][r] = 0.0f; S[2 * ks + 1][r] = 0.0f; }
            mma_f16(S[2 * ks],     qfr, kb[0], kb[1]);
            mma_f16(S[2 * ks + 1], qfr, kb[2], kb[3]);
        }

        float tm0 = -1e30f, tm1 = -1e30f;
#pragma unroll
        for (int nt = 0; nt < 8; nt++) {
            tm0 = fmaxf(tm0, fmaxf(S[nt][0], S[nt][1]));
            tm1 = fmaxf(tm1, fmaxf(S[nt][2], S[nt][3]));
        }
        tm0 = fmaxf(tm0, __shfl_xor_sync(0xffffffffu, tm0, 1));
        tm0 = fmaxf(tm0, __shfl_xor_sync(0xffffffffu, tm0, 2));
        tm1 = fmaxf(tm1, __shfl_xor_sync(0xffffffffu, tm1, 1));
        tm1 = fmaxf(tm1, __shfl_xor_sync(0xffffffffu, tm1, 2));
        const float mn0 = fmaxf(mrun0, tm0), mn1 = fmaxf(mrun1, tm1);
        const float f0 = exp2f(mrun0 - mn0), f1 = exp2f(mrun1 - mn1);
        mrun0 = mn0; mrun1 = mn1;

        // p-pairs via one f16x2 MUFU ex2 each; HADD2 row sums.
        uint32_t afr[4][4];
        __half2 hs0 = __floats2half2_rn(0.0f, 0.0f);
        __half2 hs1 = hs0;
#pragma unroll
        for (int j = 0; j < 4; j++) {
            afr[j][0] = h2e2(S[2 * j][0] - mn0,     S[2 * j][1] - mn0);
            afr[j][1] = h2e2(S[2 * j][2] - mn1,     S[2 * j][3] - mn1);
            afr[j][2] = h2e2(S[2 * j + 1][0] - mn0, S[2 * j + 1][1] - mn0);
            afr[j][3] = h2e2(S[2 * j + 1][2] - mn1, S[2 * j + 1][3] - mn1);
            hs0 = __hadd2(hs0, __hadd2(u2h2(afr[j][0]), u2h2(afr[j][2])));
            hs1 = __hadd2(hs1, __hadd2(u2h2(afr[j][1]), u2h2(afr[j][3])));
        }
        float2 s0f = __half22float2(hs0);
        float2 s1f = __half22float2(hs1);
        float ts0 = s0f.x + s0f.y;
        float ts1 = s1f.x + s1f.y;
        ts0 += __shfl_xor_sync(0xffffffffu, ts0, 1);
        ts0 += __shfl_xor_sync(0xffffffffu, ts0, 2);
        ts1 += __shfl_xor_sync(0xffffffffu, ts1, 1);
        ts1 += __shfl_xor_sync(0xffffffffu, ts1, 2);
        lrun0 = lrun0 * f0 + ts0;
        lrun1 = lrun1 * f1 + ts1;

        // Skip the O rescale when no row max changed anywhere in the warp.
        if (!__all_sync(0xffffffffu, (f0 == 1.0f) && (f1 == 1.0f))) {
#pragma unroll
            for (int nc = 0; nc < 16; nc++) {
                O[nc][0] *= f0; O[nc][1] *= f0;
                O[nc][2] *= f1; O[nc][3] *= f1;
            }
        }

#pragma unroll
        for (int j = 0; j < 4; j++) {
            const uint32_t vb_j = Vb + j * 32 + voff;
#pragma unroll
            for (int p = 0; p < 8; p++) {
                uint32_t vb[4];
                ldsm4(vb, vb_j + p * 2304);
                mma_f16(O[2 * p],     afr[j], vb[0], vb[1]);
                mma_f16(O[2 * p + 1], afr[j], vb[2], vb[3]);
            }
        }
    }

    const float linv0 = 1.0f / lrun0, linv1 = 1.0f / lrun1;
    const float a = alpha[0];
    const int px0 = n0 + qbase + (lane >> 2);
    const int px1 = px0 + 8;
    __half* dst0 = xp2 + (((size_t)b * XP_H + (px0 >> 6) + 1) * XP_H + (px0 & 63) + 1) * CI;
    __half* dst1 = xp2 + (((size_t)b * XP_H + (px1 >> 6) + 1) * XP_H + (px1 & 63) + 1) * CI;
#pragma unroll
    for (int nc = 0; nc < 16; nc++) {
        const int ch = nc * 8 + 2 * (lane & 3);
        const __half* hp = yhi + ((size_t)b * 128 + ch) * NPIX;
        const __half* lp = ylo + ((size_t)b * 128 + ch) * NPIX;
        float ya0 = __half2float(hp[px0]) + __half2float(lp[px0]);
        float yb0 = __half2float(hp[NPIX + px0]) + __half2float(lp[NPIX + px0]);
        float ya1 = __half2float(hp[px1]) + __half2float(lp[px1]);
        float yb1 = __half2float(hp[NPIX + px1]) + __half2float(lp[NPIX + px1]);
        *(uint32_t*)(dst0 + ch) = ph2(fmaf(a, O[nc][0] * linv0, ya0),
                                      fmaf(a, O[nc][1] * linv0, yb0));
        *(uint32_t*)(dst1 + ch) = ph2(fmaf(a, O[nc][2] * linv1, ya1),
                                      fmaf(a, O[nc][3] * linv1, yb1));
    }
}

// ---------------------------------------------------------------------------
// CAM gram matrix via fp16 hi/lo split MMA, split-K partials.
// ---------------------------------------------------------------------------
#define CAME_SMEM 36864

__global__ void __launch_bounds__(256, 2) cam_energy_mma(
        const __half* __restrict__ yhi, const __half* __restrict__ ylo,
        float* __restrict__ epart) {
    extern __shared__ __align__(16) char smc[];
    const uint32_t smb = smem_u32(smc);
    const int tid = threadIdx.x, lane = tid & 31, wid = tid >> 5;
    const int warp_m = wid >> 2, warp_n = wid & 3;
    const int b = blockIdx.y, ksid = blockIdx.x;
    const int g = lane >> 3, r8 = lane & 7;

    float acc[4][4][4];
#pragma unroll
    for (int mt = 0; mt < 4; mt++)
#pragma unroll
        for (int nt = 0; nt < 4; nt++)
#pragma unroll
            for (int r = 0; r < 4; r++) acc[mt][nt][r] = 0.0f;

    for (int chunk = 0; chunk < 4; chunk++) {
        const int k0 = ksid * 256 + chunk * 64;
        __syncthreads();
#pragma unroll
        for (int t = 0; t < 4; t++) {
            int idx = tid + t * 256;
            int ch = idx >> 3, seg = idx & 7;
            CP_ASYNC16(smb + ch * 144 + seg * 16,
                       yhi + ((size_t)b * 128 + ch) * NPIX + k0 + seg * 8);
            CP_ASYNC16(smb + 18432 + ch * 144 + seg * 16,
                       ylo + ((size_t)b * 128 + ch) * NPIX + k0 + seg * 8);
        }
        CP_COMMIT();
        CP_WAIT(0);
        __syncthreads();

#pragma unroll
        for (int ks = 0; ks < 4; ks++) {
            uint32_t ahi[4][4], alo[4][4];
#pragma unroll
            for (int mt = 0; mt < 4; mt++) {
                const uint32_t arow = (warp_m * 64 + mt * 16 + (g & 1) * 8 + r8) * 144
                                      + ks * 32 + (g >> 1) * 16;
                ldsm4(ahi[mt], smb + arow);
                ldsm4(alo[mt], smb + 18432 + arow);
            }
            uint32_t bhi[2][4], blo[2][4];
#pragma unroll
            for (int t16 = 0; t16 < 2; t16++) {
                const uint32_t brow = (warp_n * 32 + t16 * 16 + (g >> 1) * 8 + r8) * 144
                                      + ks * 32 + (g & 1) * 16;
                ldsm4(bhi[t16], smb + brow);
                ldsm4(blo[t16], smb + 18432 + brow);
            }
#pragma unroll
            for (int mt = 0; mt < 4; mt++)
#pragma unroll
                for (int t16 = 0; t16 < 2; t16++) {
                    mma_f16(acc[mt][2 * t16],     ahi[mt], bhi[t16][0], bhi[t16][1]);
                    mma_f16(acc[mt][2 * t16 + 1], ahi[mt], bhi[t16][2], bhi[t16][3]);
                    mma_f16(acc[mt][2 * t16],     ahi[mt], blo[t16][0], blo[t16][1]);
                    mma_f16(acc[mt][2 * t16 + 1], ahi[mt], blo[t16][2], blo[t16][3]);
                    mma_f16(acc[mt][2 * t16],     alo[mt], bhi[t16][0], bhi[t16][1]);
                    mma_f16(acc[mt][2 * t16 + 1], alo[mt], bhi[t16][2], bhi[t16][3]);
                }
        }
    }

    float* ep = epart + (((size_t)ksid * BATCH + b) * 128) * 128;
#pragma unroll
    for (int mt = 0; mt < 4; mt++) {
        const int c0 = warp_m * 64 + mt * 16 + (lane >> 2);
#pragma unroll
        for (int nt = 0; nt < 4; nt++) {
            const int d = warp_n * 32 + nt * 8 + 2 * (lane & 3);
            *(float2*)(ep + (size_t)c0 * 128 + d) = make_float2(acc[mt][nt][0], acc[mt][nt][1]);
            *(float2*)(ep + (size_t)(c0 + 8) * 128 + d) = make_float2(acc[mt][nt][2], acc[mt][nt][3]);
        }
    }
}

// ---------------------------------------------------------------------------
// CAM softmax of (rowmax - E), reducing the KSPLIT partials -> fp16 attn
// ---------------------------------------------------------------------------
__global__ void cam_softmax_kernel(const float* __restrict__ epart,
                                   __half* __restrict__ attn) {
    const int row = blockIdx.x;
    const int tid = threadIdx.x;
    __shared__ float red[4];

    float e = 0.0f;
#pragma unroll
    for (int s = 0; s < KSPLIT; s++)
        e += epart[((size_t)s * 1024 + row) * 128 + tid];

    float m = e;
#pragma unroll
    for (int off = 16; off; off >>= 1) m = fmaxf(m, __shfl_xor_sync(0xffffffff, m, off));
    if ((tid & 31) == 0) red[tid >> 5] = m;
    __syncthreads();
    float mx = fmaxf(fmaxf(red[0], red[1]), fmaxf(red[2], red[3]));
    float e2 = mx - e;
    __syncthreads();

    float m2 = e2;
#pragma unroll
    for (int off = 16; off; off >>= 1) m2 = fmaxf(m2, __shfl_xor_sync(0xffffffff, m2, off));
    if ((tid & 31) == 0) red[tid >> 5] = m2;
    __syncthreads();
    m2 = fmaxf(fmaxf(red[0], red[1]), fmaxf(red[2], red[3]));
    float p = __expf(e2 - m2);
    __syncthreads();

    float s = p;
#pragma unroll
    for (int off = 16; off; off >>= 1) s += __shfl_xor_sync(0xffffffff, s, off);
    if ((tid & 31) == 0) red[tid >> 5] = s;
    __syncthreads();
    s = red[0] + red[1] + red[2] + red[3];

    attn[(size_t)row * 128 + tid] = __float2half(p / s);
}

// ---------------------------------------------------------------------------
// CAM feature via fp16 MMA -> fp16 padded NHWC; residual from hi+lo.
// ---------------------------------------------------------------------------
#define CAMF_SMEM 53248

__global__ void __launch_bounds__(256, 1) cam_feat_mma(
        const __half* __restrict__ attn16,
        const __half* __restrict__ yhi, const __half* __restrict__ ylo,
        const float* __restrict__ beta, __half* __restrict__ xp2) {
    extern __shared__ __align__(16) char smc[];
    const uint32_t smb = smem_u32(smc);
    const int tid = threadIdx.x, lane = tid & 31, wid = tid >> 5;
    const int b = blockIdx.y;
    const int n0 = blockIdx.x * 64;
    const int g = lane >> 3;

#pragma unroll
    for (int t = 0; t < 8; t++) {
        int idx = tid + t * 256;
        int c = idx >> 4, seg = idx & 15;
        CP_ASYNC16(smb + c * 272 + seg * 16,
                   attn16 + ((size_t)b * 128 + c) * 128 + seg * 8);
    }
#pragma unroll
    for (int t = 0; t < 4; t++) {
        int idx = tid + t * 256;
        int ch = idx >> 3, seg = idx & 7;
        CP_ASYNC16(smb + 34816 + ch * 144 + seg * 16,
                   yhi + ((size_t)b * 128 + ch) * NPIX + n0 + seg * 8);
    }
    CP_COMMIT();
    CP_WAIT(0);
    __syncthreads();

    const int mt = wid;
    float acc[8][4];
#pragma unroll
    for (int nt = 0; nt < 8; nt++)
#pragma unroll
        for (int r = 0; r < 4; r++) acc[nt][r] = 0.0f;

    const uint32_t Bsm = smb + 34816;
#pragma unroll
    for (int ks = 0; ks < 8; ks++) {
        uint32_t afr[4];
        ldsm4(afr, smb + (mt * 16 + (g & 1) * 8 + (lane & 7)) * 272
                  + ks * 32 + (g >> 1) * 16);
#pragma unroll
        for (int t16 = 0; t16 < 4; t16++) {
            uint32_t bfr[4];
            ldsm4t(bfr, Bsm + (ks * 16 + (g & 1) * 8 + (lane & 7)) * 144
                       + (t16 * 16 + (g >> 1) * 8) * 2);
            mma_f16(acc[2 * t16],     afr, bfr[0], bfr[1]);
            mma_f16(acc[2 * t16 + 1], afr, bfr[2], bfr[3]);
        }
    }

    const float bet = beta[0];
    const int c0 = mt * 16 + (lane >> 2);
#pragma unroll
    for (int nt = 0; nt < 8; nt++) {
        const int n = n0 + nt * 8 + 2 * (lane & 3);
        const __half* h0p = yhi + ((size_t)b * 128 + c0) * NPIX;
        const __half* l0p = ylo + ((size_t)b * 128 + c0) * NPIX;
        float y00 = __half2float(h0p[n]) + __half2float(l0p[n]);
        float y01 = __half2float(h0p[n + 1]) + __half2float(l0p[n + 1]);
        float y80 = __half2float(h0p[8 * NPIX + n]) + __half2float(l0p[8 * NPIX + n]);
        float y81 = __half2float(h0p[8 * NPIX + n + 1]) + __half2float(l0p[8 * NPIX + n + 1]);
        __half* p0 = xp2 + (((size_t)b * XP_H + (n >> 6) + 1) * XP_H + (n & 63) + 1) * CI;
        __half* p1 = p0 + CI;
        p0[c0]     = __float2half(fmaf(bet, acc[nt][0], y00));
        p1[c0]     = __float2half(fmaf(bet, acc[nt][1], y01));
        p0[c0 + 8] = __float2half(fmaf(bet, acc[nt][2], y80));
        p1[c0 + 8] = __float2half(fmaf(bet, acc[nt][3], y81));
    }
}

// ---------------------------------------------------------------------------
// Final heads via one fused fp16 MMA:  A[64x256] @ [fp;fc](256 x 64px tile).
// ---------------------------------------------------------------------------
#define FIN_SMEM 36864

__global__ void __launch_bounds__(128, 3) final_mma(
        const __half* __restrict__ wfin,
        const __half* __restrict__ fp, const __half* __restrict__ fc,
        const float* __restrict__ bout, const float* __restrict__ bp3,
        const float* __restrict__ bc3, float* __restrict__ out) {
    extern __shared__ __align__(16) char smc[];
    const uint32_t smb = smem_u32(smc);
    const int tid = threadIdx.x, lane = tid & 31, wid = tid >> 5;
    const int b = blockIdx.y;
    const int n0 = blockIdx.x * 64;
    const int g = lane >> 3;

#pragma unroll
    for (int t = 0; t < 16; t++) {
        int idx = tid + t * 128;
        int ch = idx >> 3, seg = idx & 7;
        const __half* src = (ch < 128)
            ? fp + ((size_t)b * 128 + ch) * NPIX + n0 + seg * 8
            : fc + ((size_t)b * 128 + (ch - 128)) * NPIX + n0 + seg * 8;
        CP_ASYNC16(smb + ch * 144 + seg * 16, src);
    }
    CP_COMMIT();

    const int mt = wid;
    uint32_t afr[16][4];
    const uint4* wf4 = (const uint4*)wfin;
#pragma unroll
    for (int ks = 0; ks < 16; ks++) {
        uint4 v = __ldg(&wf4[(mt * 16 + ks) * 32 + lane]);
        afr[ks][0] = v.x; afr[ks][1] = v.y; afr[ks][2] = v.z; afr[ks][3] = v.w;
    }

    float acc[8][4];
#pragma unroll
    for (int nt = 0; nt < 8; nt++)
#pragma unroll
        for (int r = 0; r < 4; r++) acc[nt][r] = 0.0f;

    CP_WAIT(0);
    __syncthreads();

    const uint32_t Bsm = smb;
#pragma unroll
    for (int ks = 0; ks < 16; ks++) {
#pragma unroll
        for (int t16 = 0; t16 < 4; t16++) {
            uint32_t bfr[4];
            ldsm4t(bfr, Bsm + (ks * 16 + (g & 1) * 8 + (lane & 7)) * 144
                       + (t16 * 16 + (g >> 1) * 8) * 2);
            mma_f16(acc[2 * t16],     afr[ks], bfr[0], bfr[1]);
            mma_f16(acc[2 * t16 + 1], afr[ks], bfr[2], bfr[3]);
        }
    }

    const size_t SEG = (size_t)BATCH * NC * NPIX;
    auto emit = [&](int row, int px, float v) {
        if (row >= 57) return;
        float bias;
        size_t base;
        if (row < 19)      { bias = bout[row]; base = ((size_t)b * NC + row) * NPIX; }
        else if (row < 38) { bias = bp3[row - 19]; base = SEG + ((size_t)b * NC + row - 19) * NPIX; }
        else               { bias = bc3[row - 38]; base = 2 * SEG + ((size_t)b * NC + row - 38) * NPIX; }
        out[base + px] = sigmoidf_(v + bias);
    };

    const int r0 = mt * 16 + (lane >> 2);
#pragma unroll
    for (int nt = 0; nt < 8; nt++) {
        const int px = n0 + nt * 8 + 2 * (lane & 3);
        emit(r0,     px,     acc[nt][0]);
        emit(r0,     px + 1, acc[nt][1]);
        emit(r0 + 8, px,     acc[nt][2]);
        emit(r0 + 8, px + 1, acc[nt][3]);
    }
}

// ---------------------------------------------------------------------------
// Streams / events (created once at program load)
// ---------------------------------------------------------------------------
namespace {
struct StreamInit {
    cudaStream_t s1;
    cudaEvent_t e0, e1, e2, e3, e4, e5, e6;
    StreamInit() {
        cudaStreamCreateWithFlags(&s1, cudaStreamNonBlocking);
        cudaEventCreateWithFlags(&e0, cudaEventDisableTiming);
        cudaEventCreateWithFlags(&e1, cudaEventDisableTiming);
        cudaEventCreateWithFlags(&e2, cudaEventDisableTiming);
        cudaEventCreateWithFlags(&e3, cudaEventDisableTiming);
        cudaEventCreateWithFlags(&e4, cudaEventDisableTiming);
        cudaEventCreateWithFlags(&e5, cudaEventDisableTiming);
        cudaEventCreateWithFlags(&e6, cudaEventDisableTiming);
    }
};
StreamInit g_str;
}

// ---------------------------------------------------------------------------
// Launch
// ---------------------------------------------------------------------------
extern "C" void kernel_launch(void* const* d_in, const int* in_sizes, int n_in,
                              void* d_out, int out_size) {
    const float* x    = (const float*)d_in[0];
    const float* Wp1  = (const float*)d_in[1];
    const float* bnp1 = (const float*)d_in[2];
    const float* Wc1  = (const float*)d_in[3];
    const float* bnc1 = (const float*)d_in[4];
    const float* Wb   = (const float*)d_in[5];
    const float* bb   = (const float*)d_in[6];
    const float* Wc   = (const float*)d_in[7];
    const float* bc   = (const float*)d_in[8];
    const float* Wd   = (const float*)d_in[9];
    const float* bd   = (const float*)d_in[10];
    const float* alpha= (const float*)d_in[11];
    const float* beta = (const float*)d_in[12];
    const float* Wp2  = (const float*)d_in[13];
    const float* bnp2 = (const float*)d_in[14];
    const float* Wc2  = (const float*)d_in[15];
    const float* bnc2 = (const float*)d_in[16];
    const float* Wout = (const float*)d_in[17];
    const float* bout = (const float*)d_in[18];
    const float* Wp3  = (const float*)d_in[19];
    const float* bp3  = (const float*)d_in[20];
    const float* Wc3  = (const float*)d_in[21];
    const float* bc3  = (const float*)d_in[22];
    float* out = (float*)d_out;

    float* epart;
    __half *featp1h, *featp1lo, *featc1h, *featc1lo, *qh, *kh, *vd, *attn16;
    __half *xpad, *xp2a, *xp2b, *wf1, *wf2, *wqkv, *wfin;
    cudaGetSymbolAddress((void**)&featp1h,  g_featp1h);
    cudaGetSymbolAddress((void**)&featp1lo, g_featp1lo);
    cudaGetSymbolAddress((void**)&featc1h,  g_featc1h);
    cudaGetSymbolAddress((void**)&featc1lo, g_featc1lo);
    cudaGetSymbolAddress((void**)&qh,       g_qh);
    cudaGetSymbolAddress((void**)&kh,       g_kh);
    cudaGetSymbolAddress((void**)&vd,       g_vd);
    cudaGetSymbolAddress((void**)&epart,    g_epart);
    cudaGetSymbolAddress((void**)&attn16,   g_attn16);
    cudaGetSymbolAddress((void**)&xpad,     g_xpad);
    cudaGetSymbolAddress((void**)&xp2a,     g_xp2a);
    cudaGetSymbolAddress((void**)&xp2b,     g_xp2b);
    cudaGetSymbolAddress((void**)&wf1,      g_wf16_1);
    cudaGetSymbolAddress((void**)&wf2,      g_wf16_2);
    cudaGetSymbolAddress((void**)&wqkv,     g_wqkv);
    cudaGetSymbolAddress((void**)&wfin,     g_wfinal);

    cudaFuncSetAttribute(conv_mma_kernel<512>,
                         cudaFuncAttributeMaxDynamicSharedMemorySize, CONV_SMEM);
    cudaFuncSetAttribute(conv_mma_kernel<128>,
                         cudaFuncAttributeMaxDynamicSharedMemorySize, CONV_SMEM);
    cudaFuncSetAttribute(pam_attn_mma,
                         cudaFuncAttributeMaxDynamicSharedMemorySize, ATT_SMEM);
    cudaFuncSetAttribute(pam_attn_mma,
                         cudaFuncAttributePreferredSharedMemoryCarveout, 100);
    cudaFuncSetAttribute(qkv_kernel,
                         cudaFuncAttributeMaxDynamicSharedMemorySize, QKV_SMEM);
    cudaFuncSetAttribute(cam_energy_mma,
                         cudaFuncAttributeMaxDynamicSharedMemorySize, CAME_SMEM);
    cudaFuncSetAttribute(cam_feat_mma,
                         cudaFuncAttributeMaxDynamicSharedMemorySize, CAMF_SMEM);
    cudaFuncSetAttribute(final_mma,
                         cudaFuncAttributeMaxDynamicSharedMemorySize, FIN_SMEM);

    cudaStream_t s1 = g_str.s1;

    // Fork s1 off the main stream
    cudaEventRecord(g_str.e0, 0);
    cudaStreamWaitEvent(s1, g_str.e0, 0);

    // s0: interior packing
    pack_x_kernel<<<dim3(64, BATCH), 256>>>(x, xpad);
    cudaEventRecord(g_str.e5, 0);   // pack_x done

    // s1: consolidated borders + weight packing (parallel with pack_x)
    zero_borders_all<<<dim3(XP_H, BATCH, 3), 256, 0, s1>>>(xpad, xp2a, xp2b);
    pack_w16<<<dim3(144, 2), 256, 0, s1>>>(Wp1, Wc1, wf1, CIN);
    cudaEventRecord(g_str.e1, s1);  // borders + wf1 ready
    pack_small<<<144, 256, 0, s1>>>(Wd, Wb, Wc, wqkv, Wout, Wp3, Wc3, wfin);
    cudaEventRecord(g_str.e4, s1);  // wqkv + wfinal ready (for qkv)
    pack_w16<<<dim3(36, 2), 256, 0, s1>>>(Wp2, Wc2, wf2, CI);
    cudaEventRecord(g_str.e6, s1);  // wf2 ready (for conv2)

    // s0: conv1-PAM FIRST (alone at full chip rate)
    cudaStreamWaitEvent(0, g_str.e1, 0);
    conv_mma_kernel<512><<<dim3(32, BATCH, 1), 256, CONV_SMEM>>>(
        xpad, xpad, wf1, bnp1, bnp1, featp1h, featp1h, featp1lo, featp1lo);
    cudaEventRecord(g_str.e2, 0);   // conv1-PAM done

    // s1: conv1-CAM + entire CAM chain (concurrent with PAM chain on s0)
    cudaStreamWaitEvent(s1, g_str.e2, 0);
    cudaStreamWaitEvent(s1, g_str.e5, 0);
    conv_mma_kernel<512><<<dim3(32, BATCH, 1), 256, CONV_SMEM, s1>>>(
        xpad, xpad, wf1 + 144 * 4096, bnc1, bnc1, featc1h, featc1h, featc1lo, featc1lo);
    cam_energy_mma<<<dim3(KSPLIT, BATCH), 256, CAME_SMEM, s1>>>(featc1h, featc1lo, epart);
    cam_softmax_kernel<<<BATCH * 128, 128, 0, s1>>>(epart, attn16);
    cam_feat_mma<<<dim3(64, BATCH), 256, CAMF_SMEM, s1>>>(
        attn16, featc1h, featc1lo, beta, xp2b);
    conv_mma_kernel<128><<<dim3(32, BATCH, 1), 256, CONV_SMEM, s1>>>(
        xp2b, xp2b, wf2 + 36 * 4096, bnc2, bnc2, featc1h, featc1h, nullptr, nullptr);
    cudaEventRecord(g_str.e3, s1);  // CAM branch fully done

    // s0: PAM chain (qkv waits only on pack_small)
    cudaStreamWaitEvent(0, g_str.e4, 0);
    qkv_kernel<<<dim3(64, BATCH), 320, QKV_SMEM>>>(
        wqkv, featp1h, bd, bb, bc, vd, qh, kh);
    pam_attn_mma<<<dim3(64, BATCH), 128, ATT_SMEM>>>(
        qh, kh, vd, featp1h, featp1lo, alpha, xp2a);
    cudaStreamWaitEvent(0, g_str.e6, 0);
    conv_mma_kernel<128><<<dim3(32, BATCH, 1), 256, CONV_SMEM>>>(
        xp2a, xp2a, wf2, bnp2, bnp2, featp1h, featp1h, nullptr, nullptr);

    // Join, then fused final heads
    cudaStreamWaitEvent(0, g_str.e3, 0);
    final_mma<<<dim3(64, BATCH), 128, FIN_SMEM>>>(
        wfin, featp1h, featc1h, bout, bp3, bc3, out);
}

// round 17
// speedup vs baseline: 1.0618x; 1.0264x over previous
#include <cuda_runtime.h>
#include <cuda_bf16.h>
#include <cuda_fp16.h>
#include <math.h>
#include <cstdint>

// ---------------------------------------------------------------------------
// Problem constants
// ---------------------------------------------------------------------------
#define BATCH 8
#define CIN   512
#define CI    128
#define CK    16
#define NC    19
#define NPIX  4096
#define FEAT_ELEMS (BATCH * CI * NPIX)
#define XP_H 66
#define KSPLIT 16
#define LOG2E 1.4426950408889634f

// ---------------------------------------------------------------------------
// Scratch (device globals)
// ---------------------------------------------------------------------------
__device__ __half g_featp1h[FEAT_ELEMS];
__device__ __half g_featp1lo[FEAT_ELEMS];
__device__ __half g_featc1h[FEAT_ELEMS];
__device__ __half g_featc1lo[FEAT_ELEMS];
__device__ __half g_qh[BATCH * NPIX * CK];
__device__ __half g_kh[BATCH * NPIX * CK];
__device__ __half g_vd[FEAT_ELEMS];
__device__ float  g_epart[KSPLIT * BATCH * CI * CI];
__device__ __half g_attn16[BATCH * CI * CI];
__device__ __half g_xpad[BATCH * XP_H * XP_H * CIN];
__device__ __half g_xp2a[BATCH * XP_H * XP_H * CI];
__device__ __half g_xp2b[BATCH * XP_H * XP_H * CI];
__device__ __half g_wf16_1[2 * 144 * 4096];
__device__ __half g_wf16_2[2 * 36 * 4096];
__device__ __half g_wqkv[10 * 8 * 32 * 8];
__device__ __half g_wfinal[4 * 16 * 32 * 8];

__device__ __forceinline__ float sigmoidf_(float x) {
    return 1.0f / (1.0f + __expf(-x));
}
__device__ __forceinline__ uint32_t smem_u32(const void* p) {
    uint32_t a;
    asm("{ .reg .u64 t; cvta.to.shared.u64 t, %1; cvt.u32.u64 %0, t; }" : "=r"(a) : "l"(p));
    return a;
}
__device__ __forceinline__ void mma_f16(float c[4], const uint32_t a[4], const uint32_t b0, const uint32_t b1) {
    asm volatile(
        "mma.sync.aligned.m16n8k16.row.col.f32.f16.f16.f32 "
        "{%0,%1,%2,%3}, {%4,%5,%6,%7}, {%8,%9}, {%0,%1,%2,%3};"
        : "+f"(c[0]), "+f"(c[1]), "+f"(c[2]), "+f"(c[3])
        : "r"(a[0]), "r"(a[1]), "r"(a[2]), "r"(a[3]), "r"(b0), "r"(b1));
}
__device__ __forceinline__ void ldsm4(uint32_t r[4], uint32_t addr) {
    asm volatile("ldmatrix.sync.aligned.m8n8.x4.shared.b16 {%0,%1,%2,%3}, [%4];"
                 : "=r"(r[0]), "=r"(r[1]), "=r"(r[2]), "=r"(r[3]) : "r"(addr));
}
__device__ __forceinline__ void ldsm4t(uint32_t r[4], uint32_t addr) {
    asm volatile("ldmatrix.sync.aligned.m8n8.x4.trans.shared.b16 {%0,%1,%2,%3}, [%4];"
                 : "=r"(r[0]), "=r"(r[1]), "=r"(r[2]), "=r"(r[3]) : "r"(addr));
}
#define CP_ASYNC16(dst, src) \
    asm volatile("cp.async.ca.shared.global [%0], [%1], 16;" :: "r"(dst), "l"(src))
#define CP_COMMIT() asm volatile("cp.async.commit_group;")
#define CP_WAIT(N)  asm volatile("cp.async.wait_group %0;" :: "n"(N))

__device__ __forceinline__ uint32_t ph2(float x, float y) {
    __half2 h = __floats2half2_rn(x, y);
    return *(uint32_t*)&h;
}
// Pack (lo, hi) floats to f16x2 and take 2^x on both halves (one MUFU op).
__device__ __forceinline__ uint32_t h2e2(float lo, float hi) {
    uint32_t h, r;
    asm("cvt.rn.f16x2.f32 %0, %1, %2;" : "=r"(h) : "f"(hi), "f"(lo));
    asm("ex2.approx.f16x2 %0, %1;" : "=r"(r) : "r"(h));
    return r;
}
__device__ __forceinline__ __half2 u2h2(uint32_t u) { return *(__half2*)&u; }

// ---------------------------------------------------------------------------
// Pack x: f32 NCHW -> fp16 NHWC padded
// ---------------------------------------------------------------------------
__global__ void pack_x_kernel(const float* __restrict__ x, __half* __restrict__ xp) {
    const int h = blockIdx.x, b = blockIdx.y, tid = threadIdx.x;
    __shared__ float s[32][65];
    for (int ci0 = 0; ci0 < CIN; ci0 += 32) {
        for (int idx = tid; idx < 32 * 64; idx += 256) {
            int ci_l = idx >> 6, w = idx & 63;
            s[ci_l][w] = x[(((size_t)b * CIN + ci0 + ci_l) * 64 + h) * 64 + w];
        }
        __syncthreads();
        for (int idx = tid; idx < 64 * 32; idx += 256) {
            int w = idx >> 5, ci_l = idx & 31;
            xp[(((size_t)b * XP_H + h + 1) * XP_H + w + 1) * CIN + ci0 + ci_l] =
                __float2half(s[ci_l][w]);
        }
        __syncthreads();
    }
}

// One launch zeroes the borders of all three padded buffers (z selects).
__global__ void zero_borders_all(__half* __restrict__ xpad,
                                 __half* __restrict__ xp2a,
                                 __half* __restrict__ xp2b) {
    const int hp = blockIdx.x, b = blockIdx.y, z = blockIdx.z, tid = threadIdx.x;
    __half* base = (z == 0) ? xpad : (z == 1 ? xp2a : xp2b);
    const int C = (z == 0) ? CIN : CI;
    __half* row = base + ((size_t)b * XP_H + hp) * XP_H * C;
    const __half zz = __float2half(0.0f);
    if (hp == 0 || hp == XP_H - 1) {
        for (int idx = tid; idx < XP_H * C; idx += 256) row[idx] = zz;
    } else {
        for (int idx = tid; idx < C; idx += 256) {
            row[idx] = zz;
            row[(size_t)(XP_H - 1) * C + idx] = zz;
        }
    }
}

// ---------------------------------------------------------------------------
// Pack conv weights into m16n8k16 fp16 A-fragment order.
// ---------------------------------------------------------------------------
__global__ void pack_w16(const float* __restrict__ W0, const float* __restrict__ W1,
                         __half* __restrict__ wf, int CIN_T) {
    const int cpc = CIN_T / 32;
    const int chunk = blockIdx.x;
    const int kwh = chunk / cpc, cb = chunk % cpc;
    const float* W = blockIdx.y ? W1 : W0;
    __half* dst = wf + ((size_t)blockIdx.y * gridDim.x + chunk) * 4096;
    for (int t = 0; t < 16; t++) {
        int idx = threadIdx.x + t * 256;
        int j = idx & 7, lane = (idx >> 3) & 31, ks = (idx >> 8) & 1, mt = idx >> 9;
        int reg = j >> 1, h = j & 1;
        int co = mt * 16 + (lane >> 2) + (reg & 1) * 8;
        int ci = cb * 32 + ks * 16 + (lane & 3) * 2 + (reg >> 1) * 8 + h;
        dst[idx] = __float2half(W[((size_t)co * CIN_T + ci) * 9 + kwh]);
    }
}

// Parallel small-table pack: 144 CTAs x 256, 1 element/thread.
__global__ void pack_small(const float* __restrict__ Wd, const float* __restrict__ Wb,
                           const float* __restrict__ Wc, __half* __restrict__ dqkv,
                           const float* __restrict__ Wout, const float* __restrict__ Wp3,
                           const float* __restrict__ Wc3, __half* __restrict__ dfin) {
    int gi = blockIdx.x * 256 + threadIdx.x;
    if (gi < 20480) {
        int idx = gi;
        int j = idx & 7, lane = (idx >> 3) & 31, ks = (idx >> 8) & 7, mt = idx >> 11;
        int reg = j >> 1, h = j & 1;
        int row = mt * 16 + (lane >> 2) + (reg & 1) * 8;
        int col = ks * 16 + (lane & 3) * 2 + (reg >> 1) * 8 + h;
        float w;
        if (row < 128)      w = Wd[row * 128 + col];
        else if (row < 144) w = Wb[(row - 128) * 128 + col];
        else                w = Wc[(row - 144) * 128 + col];
        dqkv[idx] = __float2half(w);
    } else if (gi < 36864) {
        int idx = gi - 20480;
        int j = idx & 7, lane = (idx >> 3) & 31, ks = (idx >> 8) & 15, mt = idx >> 12;
        int reg = j >> 1, h = j & 1;
        int row = mt * 16 + (lane >> 2) + (reg & 1) * 8;
        int col = ks * 16 + (lane & 3) * 2 + (reg >> 1) * 8 + h;
        float w = 0.0f;
        if (col < 128) {
            if (row < 19)      w = Wout[row * 128 + col];
            else if (row < 38) w = Wp3[(row - 19) * 128 + col];
        } else {
            int c = col - 128;
            if (row < 19)      w = Wout[row * 128 + c];
            else if (row >= 38 && row < 57) w = Wc3[(row - 38) * 128 + c];
        }
        dfin[idx] = __float2half(w);
    }
}

// ---------------------------------------------------------------------------
// conv3x3 implicit GEMM, fp16 m16n8k16, halo-reuse B staging, fused BN+ReLU.
// ---------------------------------------------------------------------------
#define CONV_SMEM 91392
#define BPX 80

template<int CIN_T>
__global__ void __launch_bounds__(256, 2) conv_mma_kernel(
        const __half* __restrict__ xpA, const __half* __restrict__ xpB,
        const __half* __restrict__ wfrag,
        const float* __restrict__ bn0, const float* __restrict__ bn1,
        __half* __restrict__ o16_0, __half* __restrict__ o16_1,
        __half* __restrict__ olo_0, __half* __restrict__ olo_1) {
    constexpr int CPC = CIN_T / 32;
    constexpr int NS = CPC * 3;
    extern __shared__ __align__(16) char smc[];
    const uint32_t smb = smem_u32(smc);
    const uint32_t Boff = smb;
    const uint32_t Aoff = smb + 2 * 21120;

    const int tid = threadIdx.x, lane = tid & 31, wid = tid >> 5;
    const int warp_m = wid >> 2, warp_n = wid & 3;
    const int b = blockIdx.y, z = blockIdx.z;
    const int pxbase = blockIdx.x * 128;
    const int h0 = pxbase >> 6;
    const __half* xp = z ? xpB : xpA;
    const __half* Wf = wfrag + (size_t)z * (9 * CPC) * 4096;
    const float* bn = z ? bn1 : bn0;
    __half* o16 = z ? o16_1 : o16_0;
    __half* olo = z ? olo_1 : olo_0;
    const int g = lane >> 3;

    float acc[4][4][4];
#pragma unroll
    for (int mt = 0; mt < 4; mt++)
#pragma unroll
        for (int nt = 0; nt < 4; nt++)
#pragma unroll
            for (int r = 0; r < 4; r++) acc[mt][nt][r] = 0.0f;

    auto stageA = [&](int s, int buf) {
        const int cb = s / 3, kh = s % 3;
        const uint32_t Ad = Aoff + buf * 24576;
#pragma unroll
        for (int kw = 0; kw < 3; kw++) {
            const __half* src = Wf + (size_t)((kh * 3 + kw) * CPC + cb) * 4096;
#pragma unroll
            for (int t = 0; t < 2; t++) {
                int idx = tid + t * 256;
                CP_ASYNC16(Ad + kw * 8192 + idx * 16, src + idx * 8);
            }
        }
    };
    auto stageB = [&](int cb, int buf) {
        const uint32_t Bd = Boff + buf * 21120;
        const __half* base = xp + ((size_t)(b * XP_H + h0) * XP_H) * CIN_T + cb * 32;
        for (int idx = tid; idx < 1056; idx += 256) {
            int r = idx / 264, rem = idx % 264;
            int c = rem >> 2, q = rem & 3;
            CP_ASYNC16(Bd + (r * 66 + c) * BPX + q * 16,
                       base + ((size_t)r * XP_H + c) * CIN_T + q * 8);
        }
    };

    stageB(0, 0);
    stageA(0, 0);
    CP_COMMIT();

    for (int s = 0; s < NS; s++) {
        const int cb = s / 3, kh = s % 3;
        if (s + 1 < NS) {
            stageA(s + 1, (s + 1) & 1);
            if ((s + 1) % 3 == 0) stageB((s + 1) / 3, ((s + 1) / 3) & 1);
            CP_COMMIT();
            CP_WAIT(1);
        } else {
            CP_WAIT(0);
        }
        __syncthreads();

        const uint32_t Bh = Boff + (cb & 1) * 21120;
        const char* Ap = smc + 2 * 21120 + (s & 1) * 24576;
#pragma unroll
        for (int ks = 0; ks < 2; ks++) {
#pragma unroll
            for (int kw = 0; kw < 3; kw++) {
                uint32_t afr[4][4];
#pragma unroll
                for (int mt = 0; mt < 4; mt++) {
                    uint4 v = *(const uint4*)(Ap + kw * 8192 +
                        ((((warp_m * 4 + mt) * 2 + ks) * 32 + lane) << 4));
                    afr[mt][0] = v.x; afr[mt][1] = v.y; afr[mt][2] = v.z; afr[mt][3] = v.w;
                }
                uint32_t bfr[2][4];
#pragma unroll
                for (int t16 = 0; t16 < 2; t16++) {
                    const int n_row = warp_n * 32 + t16 * 16 + (g >> 1) * 8 + (lane & 7);
                    const int r = n_row >> 6, w = n_row & 63;
                    ldsm4(bfr[t16], Bh + ((r + kh) * 66 + w + kw) * BPX
                                      + ks * 32 + (g & 1) * 16);
                }
#pragma unroll
                for (int mt = 0; mt < 4; mt++)
#pragma unroll
                    for (int t16 = 0; t16 < 2; t16++) {
                        mma_f16(acc[mt][2 * t16],     afr[mt], bfr[t16][0], bfr[t16][1]);
                        mma_f16(acc[mt][2 * t16 + 1], afr[mt], bfr[t16][2], bfr[t16][3]);
                    }
            }
        }
        __syncthreads();
    }

#pragma unroll
    for (int mt = 0; mt < 4; mt++) {
        const int co = warp_m * 64 + mt * 16 + (lane >> 2);
        const float sc0 = bn[co],     sh0 = bn[128 + co];
        const float sc8 = bn[co + 8], sh8 = bn[136 + co];
#pragma unroll
        for (int nt = 0; nt < 4; nt++) {
            const int px = pxbase + warp_n * 32 + nt * 8 + 2 * (lane & 3);
            float v0x = fmaxf(acc[mt][nt][0] * sc0 + sh0, 0.0f);
            float v0y = fmaxf(acc[mt][nt][1] * sc0 + sh0, 0.0f);
            float v1x = fmaxf(acc[mt][nt][2] * sc8 + sh8, 0.0f);
            float v1y = fmaxf(acc[mt][nt][3] * sc8 + sh8, 0.0f);
            *(uint32_t*)(o16 + ((size_t)b * 128 + co) * NPIX + px) = ph2(v0x, v0y);
            *(uint32_t*)(o16 + ((size_t)b * 128 + co + 8) * NPIX + px) = ph2(v1x, v1y);
            if (olo) {
                float r0x = v0x - __half2float(__float2half(v0x));
                float r0y = v0y - __half2float(__float2half(v0y));
                float r1x = v1x - __half2float(__float2half(v1x));
                float r1y = v1y - __half2float(__float2half(v1y));
                *(uint32_t*)(olo + ((size_t)b * 128 + co) * NPIX + px) = ph2(r0x, r0y);
                *(uint32_t*)(olo + ((size_t)b * 128 + co + 8) * NPIX + px) = ph2(r1x, r1y);
            }
        }
    }
}

// ---------------------------------------------------------------------------
// QKV GEMM: [Wd;Wb;Wc](160x128) @ y16(128x4096) + bias.
// Q output pre-scaled by log2(e) so attention softmax can use ex2 directly.
// ---------------------------------------------------------------------------
#define QKV_SMEM 18432

__global__ void __launch_bounds__(320, 2) qkv_kernel(
        const __half* __restrict__ wq, const __half* __restrict__ y16,
        const float* __restrict__ bd, const float* __restrict__ bb,
        const float* __restrict__ bc,
        __half* __restrict__ vh, __half* __restrict__ qh, __half* __restrict__ kh) {
    extern __shared__ __align__(16) char smc[];
    const uint32_t smb = smem_u32(smc);
    const int tid = threadIdx.x, lane = tid & 31, wid = tid >> 5;
    const int b = blockIdx.y;
    const int n0 = blockIdx.x * 64;
    const int g = lane >> 3;

    for (int idx = tid; idx < 1024; idx += 320) {
        int ch = idx >> 3, seg = idx & 7;
        CP_ASYNC16(smb + ch * 144 + seg * 16,
                   y16 + ((size_t)b * 128 + ch) * NPIX + n0 + seg * 8);
    }
    CP_COMMIT();

    const int mt = wid;
    uint32_t afr[8][4];
    const uint4* wq4 = (const uint4*)wq;
#pragma unroll
    for (int ks = 0; ks < 8; ks++) {
        uint4 v = __ldg(&wq4[(mt * 8 + ks) * 32 + lane]);
        afr[ks][0] = v.x; afr[ks][1] = v.y; afr[ks][2] = v.z; afr[ks][3] = v.w;
    }

    float acc[8][4];
#pragma unroll
    for (int nt = 0; nt < 8; nt++)
#pragma unroll
        for (int r = 0; r < 4; r++) acc[nt][r] = 0.0f;

    CP_WAIT(0);
    __syncthreads();

    const uint32_t Bsm = smb;
#pragma unroll
    for (int ks = 0; ks < 8; ks++) {
#pragma unroll
        for (int t16 = 0; t16 < 4; t16++) {
            uint32_t bfr[4];
            ldsm4t(bfr, Bsm + (ks * 16 + (g & 1) * 8 + (lane & 7)) * 144
                       + (t16 * 16 + (g >> 1) * 8) * 2);
            mma_f16(acc[2 * t16],     afr[ks], bfr[0], bfr[1]);
            mma_f16(acc[2 * t16 + 1], afr[ks], bfr[2], bfr[3]);
        }
    }

    const int r0 = mt * 16 + (lane >> 2);
    if (mt < 8) {
        const float b0 = bd[r0], b8 = bd[r0 + 8];
        __half* v0 = vh + ((size_t)b * 128 + r0) * NPIX;
        __half* v8 = vh + ((size_t)b * 128 + r0 + 8) * NPIX;
#pragma unroll
        for (int nt = 0; nt < 8; nt++) {
            const int n = n0 + nt * 8 + 2 * (lane & 3);
            *(uint32_t*)(v0 + n) = ph2(acc[nt][0] + b0, acc[nt][1] + b0);
            *(uint32_t*)(v8 + n) = ph2(acc[nt][2] + b8, acc[nt][3] + b8);
        }
    } else {
        const bool isq = (mt == 8);
        const float* bias = isq ? bb : bc;
        __half* dst = isq ? qh : kh;
        const float qs = isq ? LOG2E : 1.0f;   // pre-scale q by log2(e)
        const int d = lane >> 2;
        const float b0 = bias[d], b8 = bias[d + 8];
#pragma unroll
        for (int nt = 0; nt < 8; nt++) {
            const int n = n0 + nt * 8 + 2 * (lane & 3);
            __half* p0 = dst + ((size_t)b * NPIX + n) * 16;
            p0[d]      = __float2half((acc[nt][0] + b0) * qs);
            p0[16 + d] = __float2half((acc[nt][1] + b0) * qs);
            p0[d + 8]      = __float2half((acc[nt][2] + b8) * qs);
            p0[16 + d + 8] = __float2half((acc[nt][3] + b8) * qs);
        }
    }
}

// ---------------------------------------------------------------------------
// PAM flash attention: q-tile 128 per CTA (4 warps x 32q x 128ch), occ 2,
// double-buffered K/V.  Halves V/K L2 traffic and V-ldsm issue vs 64q tiles:
// each staged K/V tile now serves 128 queries.  Log2-domain softmax (ex2.f16x2),
// warp-voted rescale skip, residual y from hi+lo.
// SMEM: Q [128][48] @0 (6144); K 2x3072 @6144; V 2x18432 @12288.  Total 49152.
// ---------------------------------------------------------------------------
#define ATT_SMEM 49152

__global__ void __launch_bounds__(128, 2) pam_attn_mma(
        const __half* __restrict__ qh, const __half* __restrict__ kh,
        const __half* __restrict__ vd,
        const __half* __restrict__ yhi, const __half* __restrict__ ylo,
        const float* __restrict__ alpha, __half* __restrict__ xp2) {
    extern __shared__ __align__(16) char smc[];
    const uint32_t smb = smem_u32(smc);
    const uint32_t Qb  = smb;
    const uint32_t Kb0 = smb + 6144;
    const uint32_t Vb0 = smb + 12288;

    const int tid = threadIdx.x, lane = tid & 31, wid = tid >> 5;
    const int b = blockIdx.y;
    const int n0 = blockIdx.x * 128;
    const int qbase = wid * 32;

    const int g = lane >> 3, r8 = lane & 7;
    const uint32_t qoff = (uint32_t)(((g & 1) * 8 + r8) * 48 + (g >> 1) * 16);
    const uint32_t koff = (uint32_t)(((g >> 1) * 8 + r8) * 48 + (g & 1) * 16);
    const uint32_t voff = (uint32_t)(((g >> 1) * 8 + r8) * 144 + (g & 1) * 16);

    auto stageKV = [&](int t, int buf) {
        const int k0 = t * 64;
        {
            int row = tid >> 1, h = tid & 1;
            CP_ASYNC16(Kb0 + buf * 3072 + row * 48 + h * 16,
                       kh + ((size_t)b * NPIX + k0 + row) * 16 + h * 8);
        }
#pragma unroll
        for (int t4 = 0; t4 < 8; t4++) {
            int idx = tid + t4 * 128;
            int ch = idx >> 3, c = idx & 7;
            CP_ASYNC16(Vb0 + buf * 18432 + ch * 144 + c * 16,
                       vd + ((size_t)b * 128 + ch) * NPIX + k0 + c * 8);
        }
        CP_COMMIT();
    };

    // Stage Q (128 rows x 32B, 256 x 16B copies over 128 threads)
#pragma unroll
    for (int t4 = 0; t4 < 2; t4++) {
        int idx = tid + t4 * 128;
        int row = idx >> 1, h = idx & 1;
        CP_ASYNC16(Qb + row * 48 + h * 16,
                   qh + ((size_t)b * NPIX + n0 + row) * 16 + h * 8);
    }
    stageKV(0, 0);

    uint32_t qfr[2][4];
    float O[2][16][4];
#pragma unroll
    for (int qs = 0; qs < 2; qs++)
#pragma unroll
        for (int nc = 0; nc < 16; nc++)
#pragma unroll
            for (int r = 0; r < 4; r++) O[qs][nc][r] = 0.0f;
    float mrun0[2] = {-1e30f, -1e30f}, mrun1[2] = {-1e30f, -1e30f};
    float lrun0[2] = {0.0f, 0.0f},     lrun1[2] = {0.0f, 0.0f};

    for (int t = 0; t < 64; t++) {
        const int buf = t & 1;
        CP_WAIT(0);
        __syncthreads();
        if (t + 1 < 64) stageKV(t + 1, buf ^ 1);
        if (t == 0) {
            ldsm4(qfr[0], Qb + qbase * 48 + qoff);
            ldsm4(qfr[1], Qb + (qbase + 16) * 48 + qoff);
        }

        const uint32_t Kb = Kb0 + buf * 3072;
        const uint32_t Vb = Vb0 + buf * 18432;

        uint32_t afr[2][4][4];
#pragma unroll
        for (int qs = 0; qs < 2; qs++) {
            float S[8][4];
#pragma unroll
            for (int ks = 0; ks < 4; ks++) {
                uint32_t kb[4];
                ldsm4(kb, Kb + ks * 768 + koff);
#pragma unroll
                for (int r = 0; r < 4; r++) { S[2 * ks][r] = 0.0f; S[2 * ks + 1][r] = 0.0f; }
                mma_f16(S[2 * ks],     qfr[qs], kb[0], kb[1]);
                mma_f16(S[2 * ks + 1], qfr[qs], kb[2], kb[3]);
            }

            float tm0 = -1e30f, tm1 = -1e30f;
#pragma unroll
            for (int nt = 0; nt < 8; nt++) {
                tm0 = fmaxf(tm0, fmaxf(S[nt][0], S[nt][1]));
                tm1 = fmaxf(tm1, fmaxf(S[nt][2], S[nt][3]));
            }
            tm0 = fmaxf(tm0, __shfl_xor_sync(0xffffffffu, tm0, 1));
            tm0 = fmaxf(tm0, __shfl_xor_sync(0xffffffffu, tm0, 2));
            tm1 = fmaxf(tm1, __shfl_xor_sync(0xffffffffu, tm1, 1));
            tm1 = fmaxf(tm1, __shfl_xor_sync(0xffffffffu, tm1, 2));
            const float mn0 = fmaxf(mrun0[qs], tm0), mn1 = fmaxf(mrun1[qs], tm1);
            const float f0 = exp2f(mrun0[qs] - mn0), f1 = exp2f(mrun1[qs] - mn1);
            mrun0[qs] = mn0; mrun1[qs] = mn1;

            __half2 hs0 = __floats2half2_rn(0.0f, 0.0f);
            __half2 hs1 = hs0;
#pragma unroll
            for (int j = 0; j < 4; j++) {
                afr[qs][j][0] = h2e2(S[2 * j][0] - mn0,     S[2 * j][1] - mn0);
                afr[qs][j][1] = h2e2(S[2 * j][2] - mn1,     S[2 * j][3] - mn1);
                afr[qs][j][2] = h2e2(S[2 * j + 1][0] - mn0, S[2 * j + 1][1] - mn0);
                afr[qs][j][3] = h2e2(S[2 * j + 1][2] - mn1, S[2 * j + 1][3] - mn1);
                hs0 = __hadd2(hs0, __hadd2(u2h2(afr[qs][j][0]), u2h2(afr[qs][j][2])));
                hs1 = __hadd2(hs1, __hadd2(u2h2(afr[qs][j][1]), u2h2(afr[qs][j][3])));
            }
            float2 s0f = __half22float2(hs0);
            float2 s1f = __half22float2(hs1);
            float ts0 = s0f.x + s0f.y;
            float ts1 = s1f.x + s1f.y;
            ts0 += __shfl_xor_sync(0xffffffffu, ts0, 1);
            ts0 += __shfl_xor_sync(0xffffffffu, ts0, 2);
            ts1 += __shfl_xor_sync(0xffffffffu, ts1, 1);
            ts1 += __shfl_xor_sync(0xffffffffu, ts1, 2);
            lrun0[qs] = lrun0[qs] * f0 + ts0;
            lrun1[qs] = lrun1[qs] * f1 + ts1;

            if (!__all_sync(0xffffffffu, (f0 == 1.0f) && (f1 == 1.0f))) {
#pragma unroll
                for (int nc = 0; nc < 16; nc++) {
                    O[qs][nc][0] *= f0; O[qs][nc][1] *= f0;
                    O[qs][nc][2] *= f1; O[qs][nc][3] *= f1;
                }
            }
        }

        // P·V: each V fragment feeds both q-subtiles (4 MMAs per ldsm).
#pragma unroll
        for (int j = 0; j < 4; j++) {
            const uint32_t vb_j = Vb + j * 32 + voff;
#pragma unroll
            for (int p = 0; p < 8; p++) {
                uint32_t vb[4];
                ldsm4(vb, vb_j + p * 2304);
                mma_f16(O[0][2 * p],     afr[0][j], vb[0], vb[1]);
                mma_f16(O[0][2 * p + 1], afr[0][j], vb[2], vb[3]);
                mma_f16(O[1][2 * p],     afr[1][j], vb[0], vb[1]);
                mma_f16(O[1][2 * p + 1], afr[1][j], vb[2], vb[3]);
            }
        }
    }

    const float a = alpha[0];
#pragma unroll
    for (int qs = 0; qs < 2; qs++) {
        const float linv0 = 1.0f / lrun0[qs], linv1 = 1.0f / lrun1[qs];
        const int px0 = n0 + qbase + qs * 16 + (lane >> 2);
        const int px1 = px0 + 8;
        __half* dst0 = xp2 + (((size_t)b * XP_H + (px0 >> 6) + 1) * XP_H + (px0 & 63) + 1) * CI;
        __half* dst1 = xp2 + (((size_t)b * XP_H + (px1 >> 6) + 1) * XP_H + (px1 & 63) + 1) * CI;
#pragma unroll
        for (int nc = 0; nc < 16; nc++) {
            const int ch = nc * 8 + 2 * (lane & 3);
            const __half* hp = yhi + ((size_t)b * 128 + ch) * NPIX;
            const __half* lp = ylo + ((size_t)b * 128 + ch) * NPIX;
            float ya0 = __half2float(hp[px0]) + __half2float(lp[px0]);
            float yb0 = __half2float(hp[NPIX + px0]) + __half2float(lp[NPIX + px0]);
            float ya1 = __half2float(hp[px1]) + __half2float(lp[px1]);
            float yb1 = __half2float(hp[NPIX + px1]) + __half2float(lp[NPIX + px1]);
            *(uint32_t*)(dst0 + ch) = ph2(fmaf(a, O[qs][nc][0] * linv0, ya0),
                                          fmaf(a, O[qs][nc][1] * linv0, yb0));
            *(uint32_t*)(dst1 + ch) = ph2(fmaf(a, O[qs][nc][2] * linv1, ya1),
                                          fmaf(a, O[qs][nc][3] * linv1, yb1));
        }
    }
}

// ---------------------------------------------------------------------------
// CAM gram matrix via fp16 hi/lo split MMA, split-K partials.
// ---------------------------------------------------------------------------
#define CAME_SMEM 36864

__global__ void __launch_bounds__(256, 2) cam_energy_mma(
        const __half* __restrict__ yhi, const __half* __restrict__ ylo,
        float* __restrict__ epart) {
    extern __shared__ __align__(16) char smc[];
    const uint32_t smb = smem_u32(smc);
    const int tid = threadIdx.x, lane = tid & 31, wid = tid >> 5;
    const int warp_m = wid >> 2, warp_n = wid & 3;
    const int b = blockIdx.y, ksid = blockIdx.x;
    const int g = lane >> 3, r8 = lane & 7;

    float acc[4][4][4];
#pragma unroll
    for (int mt = 0; mt < 4; mt++)
#pragma unroll
        for (int nt = 0; nt < 4; nt++)
#pragma unroll
            for (int r = 0; r < 4; r++) acc[mt][nt][r] = 0.0f;

    for (int chunk = 0; chunk < 4; chunk++) {
        const int k0 = ksid * 256 + chunk * 64;
        __syncthreads();
#pragma unroll
        for (int t = 0; t < 4; t++) {
            int idx = tid + t * 256;
            int ch = idx >> 3, seg = idx & 7;
            CP_ASYNC16(smb + ch * 144 + seg * 16,
                       yhi + ((size_t)b * 128 + ch) * NPIX + k0 + seg * 8);
            CP_ASYNC16(smb + 18432 + ch * 144 + seg * 16,
                       ylo + ((size_t)b * 128 + ch) * NPIX + k0 + seg * 8);
        }
        CP_COMMIT();
        CP_WAIT(0);
        __syncthreads();

#pragma unroll
        for (int ks = 0; ks < 4; ks++) {
            uint32_t ahi[4][4], alo[4][4];
#pragma unroll
            for (int mt = 0; mt < 4; mt++) {
                const uint32_t arow = (warp_m * 64 + mt * 16 + (g & 1) * 8 + r8) * 144
                                      + ks * 32 + (g >> 1) * 16;
                ldsm4(ahi[mt], smb + arow);
                ldsm4(alo[mt], smb + 18432 + arow);
            }
            uint32_t bhi[2][4], blo[2][4];
#pragma unroll
            for (int t16 = 0; t16 < 2; t16++) {
                const uint32_t brow = (warp_n * 32 + t16 * 16 + (g >> 1) * 8 + r8) * 144
                                      + ks * 32 + (g & 1) * 16;
                ldsm4(bhi[t16], smb + brow);
                ldsm4(blo[t16], smb + 18432 + brow);
            }
#pragma unroll
            for (int mt = 0; mt < 4; mt++)
#pragma unroll
                for (int t16 = 0; t16 < 2; t16++) {
                    mma_f16(acc[mt][2 * t16],     ahi[mt], bhi[t16][0], bhi[t16][1]);
                    mma_f16(acc[mt][2 * t16 + 1], ahi[mt], bhi[t16][2], bhi[t16][3]);
                    mma_f16(acc[mt][2 * t16],     ahi[mt], blo[t16][0], blo[t16][1]);
                    mma_f16(acc[mt][2 * t16 + 1], ahi[mt], blo[t16][2], blo[t16][3]);
                    mma_f16(acc[mt][2 * t16],     alo[mt], bhi[t16][0], bhi[t16][1]);
                    mma_f16(acc[mt][2 * t16 + 1], alo[mt], bhi[t16][2], bhi[t16][3]);
                }
        }
    }

    float* ep = epart + (((size_t)ksid * BATCH + b) * 128) * 128;
#pragma unroll
    for (int mt = 0; mt < 4; mt++) {
        const int c0 = warp_m * 64 + mt * 16 + (lane >> 2);
#pragma unroll
        for (int nt = 0; nt < 4; nt++) {
            const int d = warp_n * 32 + nt * 8 + 2 * (lane & 3);
            *(float2*)(ep + (size_t)c0 * 128 + d) = make_float2(acc[mt][nt][0], acc[mt][nt][1]);
            *(float2*)(ep + (size_t)(c0 + 8) * 128 + d) = make_float2(acc[mt][nt][2], acc[mt][nt][3]);
        }
    }
}

// ---------------------------------------------------------------------------
// CAM softmax of (rowmax - E), reducing the KSPLIT partials -> fp16 attn
// ---------------------------------------------------------------------------
__global__ void cam_softmax_kernel(const float* __restrict__ epart,
                                   __half* __restrict__ attn) {
    const int row = blockIdx.x;
    const int tid = threadIdx.x;
    __shared__ float red[4];

    float e = 0.0f;
#pragma unroll
    for (int s = 0; s < KSPLIT; s++)
        e += epart[((size_t)s * 1024 + row) * 128 + tid];

    float m = e;
#pragma unroll
    for (int off = 16; off; off >>= 1) m = fmaxf(m, __shfl_xor_sync(0xffffffff, m, off));
    if ((tid & 31) == 0) red[tid >> 5] = m;
    __syncthreads();
    float mx = fmaxf(fmaxf(red[0], red[1]), fmaxf(red[2], red[3]));
    float e2 = mx - e;
    __syncthreads();

    float m2 = e2;
#pragma unroll
    for (int off = 16; off; off >>= 1) m2 = fmaxf(m2, __shfl_xor_sync(0xffffffff, m2, off));
    if ((tid & 31) == 0) red[tid >> 5] = m2;
    __syncthreads();
    m2 = fmaxf(fmaxf(red[0], red[1]), fmaxf(red[2], red[3]));
    float p = __expf(e2 - m2);
    __syncthreads();

    float s = p;
#pragma unroll
    for (int off = 16; off; off >>= 1) s += __shfl_xor_sync(0xffffffff, s, off);
    if ((tid & 31) == 0) red[tid >> 5] = s;
    __syncthreads();
    s = red[0] + red[1] + red[2] + red[3];

    attn[(size_t)row * 128 + tid] = __float2half(p / s);
}

// ---------------------------------------------------------------------------
// CAM feature via fp16 MMA -> fp16 padded NHWC; residual from hi+lo.
// ---------------------------------------------------------------------------
#define CAMF_SMEM 53248

__global__ void __launch_bounds__(256, 1) cam_feat_mma(
        const __half* __restrict__ attn16,
        const __half* __restrict__ yhi, const __half* __restrict__ ylo,
        const float* __restrict__ beta, __half* __restrict__ xp2) {
    extern __shared__ __align__(16) char smc[];
    const uint32_t smb = smem_u32(smc);
    const int tid = threadIdx.x, lane = tid & 31, wid = tid >> 5;
    const int b = blockIdx.y;
    const int n0 = blockIdx.x * 64;
    const int g = lane >> 3;

#pragma unroll
    for (int t = 0; t < 8; t++) {
        int idx = tid + t * 256;
        int c = idx >> 4, seg = idx & 15;
        CP_ASYNC16(smb + c * 272 + seg * 16,
                   attn16 + ((size_t)b * 128 + c) * 128 + seg * 8);
    }
#pragma unroll
    for (int t = 0; t < 4; t++) {
        int idx = tid + t * 256;
        int ch = idx >> 3, seg = idx & 7;
        CP_ASYNC16(smb + 34816 + ch * 144 + seg * 16,
                   yhi + ((size_t)b * 128 + ch) * NPIX + n0 + seg * 8);
    }
    CP_COMMIT();
    CP_WAIT(0);
    __syncthreads();

    const int mt = wid;
    float acc[8][4];
#pragma unroll
    for (int nt = 0; nt < 8; nt++)
#pragma unroll
        for (int r = 0; r < 4; r++) acc[nt][r] = 0.0f;

    const uint32_t Bsm = smb + 34816;
#pragma unroll
    for (int ks = 0; ks < 8; ks++) {
        uint32_t afr[4];
        ldsm4(afr, smb + (mt * 16 + (g & 1) * 8 + (lane & 7)) * 272
                  + ks * 32 + (g >> 1) * 16);
#pragma unroll
        for (int t16 = 0; t16 < 4; t16++) {
            uint32_t bfr[4];
            ldsm4t(bfr, Bsm + (ks * 16 + (g & 1) * 8 + (lane & 7)) * 144
                       + (t16 * 16 + (g >> 1) * 8) * 2);
            mma_f16(acc[2 * t16],     afr, bfr[0], bfr[1]);
            mma_f16(acc[2 * t16 + 1], afr, bfr[2], bfr[3]);
        }
    }

    const float bet = beta[0];
    const int c0 = mt * 16 + (lane >> 2);
#pragma unroll
    for (int nt = 0; nt < 8; nt++) {
        const int n = n0 + nt * 8 + 2 * (lane & 3);
        const __half* h0p = yhi + ((size_t)b * 128 + c0) * NPIX;
        const __half* l0p = ylo + ((size_t)b * 128 + c0) * NPIX;
        float y00 = __half2float(h0p[n]) + __half2float(l0p[n]);
        float y01 = __half2float(h0p[n + 1]) + __half2float(l0p[n + 1]);
        float y80 = __half2float(h0p[8 * NPIX + n]) + __half2float(l0p[8 * NPIX + n]);
        float y81 = __half2float(h0p[8 * NPIX + n + 1]) + __half2float(l0p[8 * NPIX + n + 1]);
        __half* p0 = xp2 + (((size_t)b * XP_H + (n >> 6) + 1) * XP_H + (n & 63) + 1) * CI;
        __half* p1 = p0 + CI;
        p0[c0]     = __float2half(fmaf(bet, acc[nt][0], y00));
        p1[c0]     = __float2half(fmaf(bet, acc[nt][1], y01));
        p0[c0 + 8] = __float2half(fmaf(bet, acc[nt][2], y80));
        p1[c0 + 8] = __float2half(fmaf(bet, acc[nt][3], y81));
    }
}

// ---------------------------------------------------------------------------
// Final heads via one fused fp16 MMA:  A[64x256] @ [fp;fc](256 x 64px tile).
// ---------------------------------------------------------------------------
#define FIN_SMEM 36864

__global__ void __launch_bounds__(128, 3) final_mma(
        const __half* __restrict__ wfin,
        const __half* __restrict__ fp, const __half* __restrict__ fc,
        const float* __restrict__ bout, const float* __restrict__ bp3,
        const float* __restrict__ bc3, float* __restrict__ out) {
    extern __shared__ __align__(16) char smc[];
    const uint32_t smb = smem_u32(smc);
    const int tid = threadIdx.x, lane = tid & 31, wid = tid >> 5;
    const int b = blockIdx.y;
    const int n0 = blockIdx.x * 64;
    const int g = lane >> 3;

#pragma unroll
    for (int t = 0; t < 16; t++) {
        int idx = tid + t * 128;
        int ch = idx >> 3, seg = idx & 7;
        const __half* src = (ch < 128)
            ? fp + ((size_t)b * 128 + ch) * NPIX + n0 + seg * 8
            : fc + ((size_t)b * 128 + (ch - 128)) * NPIX + n0 + seg * 8;
        CP_ASYNC16(smb + ch * 144 + seg * 16, src);
    }
    CP_COMMIT();

    const int mt = wid;
    uint32_t afr[16][4];
    const uint4* wf4 = (const uint4*)wfin;
#pragma unroll
    for (int ks = 0; ks < 16; ks++) {
        uint4 v = __ldg(&wf4[(mt * 16 + ks) * 32 + lane]);
        afr[ks][0] = v.x; afr[ks][1] = v.y; afr[ks][2] = v.z; afr[ks][3] = v.w;
    }

    float acc[8][4];
#pragma unroll
    for (int nt = 0; nt < 8; nt++)
#pragma unroll
        for (int r = 0; r < 4; r++) acc[nt][r] = 0.0f;

    CP_WAIT(0);
    __syncthreads();

    const uint32_t Bsm = smb;
#pragma unroll
    for (int ks = 0; ks < 16; ks++) {
#pragma unroll
        for (int t16 = 0; t16 < 4; t16++) {
            uint32_t bfr[4];
            ldsm4t(bfr, Bsm + (ks * 16 + (g & 1) * 8 + (lane & 7)) * 144
                       + (t16 * 16 + (g >> 1) * 8) * 2);
            mma_f16(acc[2 * t16],     afr[ks], bfr[0], bfr[1]);
            mma_f16(acc[2 * t16 + 1], afr[ks], bfr[2], bfr[3]);
        }
    }

    const size_t SEG = (size_t)BATCH * NC * NPIX;
    auto emit = [&](int row, int px, float v) {
        if (row >= 57) return;
        float bias;
        size_t base;
        if (row < 19)      { bias = bout[row]; base = ((size_t)b * NC + row) * NPIX; }
        else if (row < 38) { bias = bp3[row - 19]; base = SEG + ((size_t)b * NC + row - 19) * NPIX; }
        else               { bias = bc3[row - 38]; base = 2 * SEG + ((size_t)b * NC + row - 38) * NPIX; }
        out[base + px] = sigmoidf_(v + bias);
    };

    const int r0 = mt * 16 + (lane >> 2);
#pragma unroll
    for (int nt = 0; nt < 8; nt++) {
        const int px = n0 + nt * 8 + 2 * (lane & 3);
        emit(r0,     px,     acc[nt][0]);
        emit(r0,     px + 1, acc[nt][1]);
        emit(r0 + 8, px,     acc[nt][2]);
        emit(r0 + 8, px + 1, acc[nt][3]);
    }
}

// ---------------------------------------------------------------------------
// Streams / events (created once at program load)
// ---------------------------------------------------------------------------
namespace {
struct StreamInit {
    cudaStream_t s1;
    cudaEvent_t e0, e1, e2, e3, e4, e5, e6;
    StreamInit() {
        cudaStreamCreateWithFlags(&s1, cudaStreamNonBlocking);
        cudaEventCreateWithFlags(&e0, cudaEventDisableTiming);
        cudaEventCreateWithFlags(&e1, cudaEventDisableTiming);
        cudaEventCreateWithFlags(&e2, cudaEventDisableTiming);
        cudaEventCreateWithFlags(&e3, cudaEventDisableTiming);
        cudaEventCreateWithFlags(&e4, cudaEventDisableTiming);
        cudaEventCreateWithFlags(&e5, cudaEventDisableTiming);
        cudaEventCreateWithFlags(&e6, cudaEventDisableTiming);
    }
};
StreamInit g_str;
}

// ---------------------------------------------------------------------------
// Launch
// ---------------------------------------------------------------------------
extern "C" void kernel_launch(void* const* d_in, const int* in_sizes, int n_in,
                              void* d_out, int out_size) {
    const float* x    = (const float*)d_in[0];
    const float* Wp1  = (const float*)d_in[1];
    const float* bnp1 = (const float*)d_in[2];
    const float* Wc1  = (const float*)d_in[3];
    const float* bnc1 = (const float*)d_in[4];
    const float* Wb   = (const float*)d_in[5];
    const float* bb   = (const float*)d_in[6];
    const float* Wc   = (const float*)d_in[7];
    const float* bc   = (const float*)d_in[8];
    const float* Wd   = (const float*)d_in[9];
    const float* bd   = (const float*)d_in[10];
    const float* alpha= (const float*)d_in[11];
    const float* beta = (const float*)d_in[12];
    const float* Wp2  = (const float*)d_in[13];
    const float* bnp2 = (const float*)d_in[14];
    const float* Wc2  = (const float*)d_in[15];
    const float* bnc2 = (const float*)d_in[16];
    const float* Wout = (const float*)d_in[17];
    const float* bout = (const float*)d_in[18];
    const float* Wp3  = (const float*)d_in[19];
    const float* bp3  = (const float*)d_in[20];
    const float* Wc3  = (const float*)d_in[21];
    const float* bc3  = (const float*)d_in[22];
    float* out = (float*)d_out;

    float* epart;
    __half *featp1h, *featp1lo, *featc1h, *featc1lo, *qh, *kh, *vd, *attn16;
    __half *xpad, *xp2a, *xp2b, *wf1, *wf2, *wqkv, *wfin;
    cudaGetSymbolAddress((void**)&featp1h,  g_featp1h);
    cudaGetSymbolAddress((void**)&featp1lo, g_featp1lo);
    cudaGetSymbolAddress((void**)&featc1h,  g_featc1h);
    cudaGetSymbolAddress((void**)&featc1lo, g_featc1lo);
    cudaGetSymbolAddress((void**)&qh,       g_qh);
    cudaGetSymbolAddress((void**)&kh,       g_kh);
    cudaGetSymbolAddress((void**)&vd,       g_vd);
    cudaGetSymbolAddress((void**)&epart,    g_epart);
    cudaGetSymbolAddress((void**)&attn16,   g_attn16);
    cudaGetSymbolAddress((void**)&xpad,     g_xpad);
    cudaGetSymbolAddress((void**)&xp2a,     g_xp2a);
    cudaGetSymbolAddress((void**)&xp2b,     g_xp2b);
    cudaGetSymbolAddress((void**)&wf1,      g_wf16_1);
    cudaGetSymbolAddress((void**)&wf2,      g_wf16_2);
    cudaGetSymbolAddress((void**)&wqkv,     g_wqkv);
    cudaGetSymbolAddress((void**)&wfin,     g_wfinal);

    cudaFuncSetAttribute(conv_mma_kernel<512>,
                         cudaFuncAttributeMaxDynamicSharedMemorySize, CONV_SMEM);
    cudaFuncSetAttribute(conv_mma_kernel<128>,
                         cudaFuncAttributeMaxDynamicSharedMemorySize, CONV_SMEM);
    cudaFuncSetAttribute(pam_attn_mma,
                         cudaFuncAttributeMaxDynamicSharedMemorySize, ATT_SMEM);
    cudaFuncSetAttribute(pam_attn_mma,
                         cudaFuncAttributePreferredSharedMemoryCarveout, 100);
    cudaFuncSetAttribute(qkv_kernel,
                         cudaFuncAttributeMaxDynamicSharedMemorySize, QKV_SMEM);
    cudaFuncSetAttribute(cam_energy_mma,
                         cudaFuncAttributeMaxDynamicSharedMemorySize, CAME_SMEM);
    cudaFuncSetAttribute(cam_feat_mma,
                         cudaFuncAttributeMaxDynamicSharedMemorySize, CAMF_SMEM);
    cudaFuncSetAttribute(final_mma,
                         cudaFuncAttributeMaxDynamicSharedMemorySize, FIN_SMEM);

    cudaStream_t s1 = g_str.s1;

    // Fork s1 off the main stream
    cudaEventRecord(g_str.e0, 0);
    cudaStreamWaitEvent(s1, g_str.e0, 0);

    // s0: interior packing
    pack_x_kernel<<<dim3(64, BATCH), 256>>>(x, xpad);
    cudaEventRecord(g_str.e5, 0);   // pack_x done

    // s1: consolidated borders + weight packing (parallel with pack_x)
    zero_borders_all<<<dim3(XP_H, BATCH, 3), 256, 0, s1>>>(xpad, xp2a, xp2b);
    pack_w16<<<dim3(144, 2), 256, 0, s1>>>(Wp1, Wc1, wf1, CIN);
    cudaEventRecord(g_str.e1, s1);  // borders + wf1 ready
    pack_small<<<144, 256, 0, s1>>>(Wd, Wb, Wc, wqkv, Wout, Wp3, Wc3, wfin);
    cudaEventRecord(g_str.e4, s1);  // wqkv + wfinal ready (for qkv)
    pack_w16<<<dim3(36, 2), 256, 0, s1>>>(Wp2, Wc2, wf2, CI);
    cudaEventRecord(g_str.e6, s1);  // wf2 ready (for conv2)

    // s0: conv1-PAM FIRST (alone at full chip rate)
    cudaStreamWaitEvent(0, g_str.e1, 0);
    conv_mma_kernel<512><<<dim3(32, BATCH, 1), 256, CONV_SMEM>>>(
        xpad, xpad, wf1, bnp1, bnp1, featp1h, featp1h, featp1lo, featp1lo);
    cudaEventRecord(g_str.e2, 0);   // conv1-PAM done

    // s1: conv1-CAM + entire CAM chain (concurrent with PAM chain on s0)
    cudaStreamWaitEvent(s1, g_str.e2, 0);
    cudaStreamWaitEvent(s1, g_str.e5, 0);
    conv_mma_kernel<512><<<dim3(32, BATCH, 1), 256, CONV_SMEM, s1>>>(
        xpad, xpad, wf1 + 144 * 4096, bnc1, bnc1, featc1h, featc1h, featc1lo, featc1lo);
    cam_energy_mma<<<dim3(KSPLIT, BATCH), 256, CAME_SMEM, s1>>>(featc1h, featc1lo, epart);
    cam_softmax_kernel<<<BATCH * 128, 128, 0, s1>>>(epart, attn16);
    cam_feat_mma<<<dim3(64, BATCH), 256, CAMF_SMEM, s1>>>(
        attn16, featc1h, featc1lo, beta, xp2b);
    conv_mma_kernel<128><<<dim3(32, BATCH, 1), 256, CONV_SMEM, s1>>>(
        xp2b, xp2b, wf2 + 36 * 4096, bnc2, bnc2, featc1h, featc1h, nullptr, nullptr);
    cudaEventRecord(g_str.e3, s1);  // CAM branch fully done

    // s0: PAM chain (qkv waits only on pack_small)
    cudaStreamWaitEvent(0, g_str.e4, 0);
    qkv_kernel<<<dim3(64, BATCH), 320, QKV_SMEM>>>(
        wqkv, featp1h, bd, bb, bc, vd, qh, kh);
    pam_attn_mma<<<dim3(32, BATCH), 128, ATT_SMEM>>>(
        qh, kh, vd, featp1h, featp1lo, alpha, xp2a);
    cudaStreamWaitEvent(0, g_str.e6, 0);
    conv_mma_kernel<128><<<dim3(32, BATCH, 1), 256, CONV_SMEM>>>(
        xp2a, xp2a, wf2, bnp2, bnp2, featp1h, featp1h, nullptr, nullptr);

    // Join, then fused final heads
    cudaStreamWaitEvent(0, g_str.e3, 0);
    final_mma<<<dim3(64, BATCH), 128, FIN_SMEM>>>(
        wfin, featp1h, featc1h, bout, bp3, bc3, out);
}